// round 1
// baseline (speedup 1.0000x reference)
#include <cuda_runtime.h>

// Problem constants: B=1, N=16, T=2048, E=64, H=4, D=16
#define NN   16
#define TT   2048
#define EE   64
#define HH   4
#define DD   16
#define NP   (NN*HH)          // 64 (n,h) pairs
#define QSCALE 0.125f         // 1/sqrt(E)

// Scratch (static device arrays; allocation-free per harness rules)
__device__ float g_Q[NP * TT * DD];   // projected q, pre-scaled by 1/8
__device__ float g_K[NP * TT * DD];   // projected k
__device__ float g_W[NP * TT * DD];   // projected v, later folded with 1/Z[k]
__device__ float g_O[NN * TT * EE];   // attention output pre-FC

// ---------------------------------------------------------------------------
// dot of two 16-float rows held as 4x float4
__device__ __forceinline__ float dot16(const float4 a0, const float4 a1,
                                       const float4 a2, const float4 a3,
                                       const float4 b0, const float4 b1,
                                       const float4 b2, const float4 b3)
{
    float s = a0.x * b0.x;
    s = fmaf(a0.y, b0.y, s); s = fmaf(a0.z, b0.z, s); s = fmaf(a0.w, b0.w, s);
    s = fmaf(a1.x, b1.x, s); s = fmaf(a1.y, b1.y, s); s = fmaf(a1.z, b1.z, s);
    s = fmaf(a1.w, b1.w, s);
    s = fmaf(a2.x, b2.x, s); s = fmaf(a2.y, b2.y, s); s = fmaf(a2.z, b2.z, s);
    s = fmaf(a2.w, b2.w, s);
    s = fmaf(a3.x, b3.x, s); s = fmaf(a3.y, b3.y, s); s = fmaf(a3.z, b3.z, s);
    s = fmaf(a3.w, b3.w, s);
    return s;
}

// ---------------------------------------------------------------------------
// K1: head projections. one thread per (n,h,t); computes q,k,v rows.
__global__ void k_proj(const float* __restrict__ value,
                       const float* __restrict__ key,
                       const float* __restrict__ query,
                       const float* __restrict__ Wq, const float* __restrict__ bq,
                       const float* __restrict__ Wk, const float* __restrict__ bk,
                       const float* __restrict__ Wv, const float* __restrict__ bv)
{
    __shared__ float sWq[256], sWk[256], sWv[256];
    __shared__ float sbq[16], sbk[16], sbv[16];
    int tid = threadIdx.x;
    if (tid < 256) { sWq[tid] = Wq[tid]; sWk[tid] = Wk[tid]; sWv[tid] = Wv[tid]; }
    if (tid < 16)  { sbq[tid] = bq[tid]; sbk[tid] = bk[tid]; sbv[tid] = bv[tid]; }
    __syncthreads();

    int id = blockIdx.x * blockDim.x + tid;     // 0 .. 131071
    int t  = id & (TT - 1);
    int p  = id >> 11;                          // n*4 + h
    int n  = p >> 2;
    int h  = p & 3;
    int in_base  = (n * TT + t) * EE + h * DD;
    int out_base = (p * TT + t) * DD;

    float x[16];
    // ---- q (scaled by 1/8) ----
    #pragma unroll
    for (int i = 0; i < 16; i++) x[i] = query[in_base + i];
    #pragma unroll
    for (int j = 0; j < 16; j++) {
        float acc = sbq[j];
        #pragma unroll
        for (int i = 0; i < 16; i++) acc = fmaf(x[i], sWq[i * 16 + j], acc);
        g_Q[out_base + j] = acc * QSCALE;
    }
    // ---- k ----
    #pragma unroll
    for (int i = 0; i < 16; i++) x[i] = key[in_base + i];
    #pragma unroll
    for (int j = 0; j < 16; j++) {
        float acc = sbk[j];
        #pragma unroll
        for (int i = 0; i < 16; i++) acc = fmaf(x[i], sWk[i * 16 + j], acc);
        g_K[out_base + j] = acc;
    }
    // ---- v ----
    #pragma unroll
    for (int i = 0; i < 16; i++) x[i] = value[in_base + i];
    #pragma unroll
    for (int j = 0; j < 16; j++) {
        float acc = sbv[j];
        #pragma unroll
        for (int i = 0; i < 16; i++) acc = fmaf(x[i], sWv[i * 16 + j], acc);
        g_W[out_base + j] = acc;
    }
}

// ---------------------------------------------------------------------------
// K2: column partition sums. softmax is over the QUERY axis, so each column k
// needs Z[k] = sum_q exp((q.k)/8). Scores are bounded (|s| < ~6), so no max
// subtraction needed (shift-invariant). Fold 1/Z into v: g_W[k,:] = v[k,:]/Z[k].
// grid = (T/128, NP), block = 128; thread owns one column k.
__global__ void k_colstats()
{
    __shared__ float Qs[128 * 16];
    int tid = threadIdx.x;
    int p   = blockIdx.y;
    int k   = blockIdx.x * 128 + tid;

    const float4* kr = reinterpret_cast<const float4*>(&g_K[(p * TT + k) * DD]);
    float4 k0 = kr[0], k1 = kr[1], k2 = kr[2], k3 = kr[3];

    float z = 0.0f;
    for (int qt = 0; qt < TT / 128; qt++) {
        __syncthreads();
        {
            const float4* src =
                reinterpret_cast<const float4*>(&g_Q[(p * TT + qt * 128 + tid) * DD]);
            float4* dst = reinterpret_cast<float4*>(&Qs[tid * 16]);
            dst[0] = src[0]; dst[1] = src[1]; dst[2] = src[2]; dst[3] = src[3];
        }
        __syncthreads();
        #pragma unroll 4
        for (int qq = 0; qq < 128; qq++) {
            const float4* q4 = reinterpret_cast<const float4*>(&Qs[qq * 16]);
            float4 a0 = q4[0], a1 = q4[1], a2 = q4[2], a3 = q4[3];
            float s = dot16(a0, a1, a2, a3, k0, k1, k2, k3);
            z += __expf(s);
        }
    }
    float inv = 1.0f / z;
    float4* wr = reinterpret_cast<float4*>(&g_W[(p * TT + k) * DD]);
    float4 w0 = wr[0], w1 = wr[1], w2 = wr[2], w3 = wr[3];
    w0.x *= inv; w0.y *= inv; w0.z *= inv; w0.w *= inv;
    w1.x *= inv; w1.y *= inv; w1.z *= inv; w1.w *= inv;
    w2.x *= inv; w2.y *= inv; w2.z *= inv; w2.w *= inv;
    w3.x *= inv; w3.y *= inv; w3.z *= inv; w3.w *= inv;
    wr[0] = w0; wr[1] = w1; wr[2] = w2; wr[3] = w3;
}

// ---------------------------------------------------------------------------
// K3: out[q,:] = sum_k exp(q.Ks[k]) * Ws[k,:]  (Ws already folded with 1/Z).
// grid = (T/128, NP), block = 128; thread owns one q row.
__global__ void k_attn_out()
{
    __shared__ float Ks[128 * 16];
    __shared__ float Ws[128 * 16];
    int tid = threadIdx.x;
    int p   = blockIdx.y;
    int n   = p >> 2;
    int h   = p & 3;
    int q   = blockIdx.x * 128 + tid;

    const float4* qr = reinterpret_cast<const float4*>(&g_Q[(p * TT + q) * DD]);
    float4 q0 = qr[0], q1 = qr[1], q2 = qr[2], q3 = qr[3];

    float acc[16];
    #pragma unroll
    for (int j = 0; j < 16; j++) acc[j] = 0.0f;

    for (int kt = 0; kt < TT / 128; kt++) {
        __syncthreads();
        {
            int r = kt * 128 + tid;
            const float4* ks = reinterpret_cast<const float4*>(&g_K[(p * TT + r) * DD]);
            const float4* ws = reinterpret_cast<const float4*>(&g_W[(p * TT + r) * DD]);
            float4* kd = reinterpret_cast<float4*>(&Ks[tid * 16]);
            float4* wd = reinterpret_cast<float4*>(&Ws[tid * 16]);
            kd[0] = ks[0]; kd[1] = ks[1]; kd[2] = ks[2]; kd[3] = ks[3];
            wd[0] = ws[0]; wd[1] = ws[1]; wd[2] = ws[2]; wd[3] = ws[3];
        }
        __syncthreads();
        #pragma unroll 4
        for (int kk = 0; kk < 128; kk++) {
            const float4* k4 = reinterpret_cast<const float4*>(&Ks[kk * 16]);
            float4 b0 = k4[0], b1 = k4[1], b2 = k4[2], b3 = k4[3];
            float s = dot16(q0, q1, q2, q3, b0, b1, b2, b3);
            float e = __expf(s);
            const float4* w4 = reinterpret_cast<const float4*>(&Ws[kk * 16]);
            float4 w0 = w4[0], w1 = w4[1], w2 = w4[2], w3 = w4[3];
            acc[0]  = fmaf(e, w0.x, acc[0]);  acc[1]  = fmaf(e, w0.y, acc[1]);
            acc[2]  = fmaf(e, w0.z, acc[2]);  acc[3]  = fmaf(e, w0.w, acc[3]);
            acc[4]  = fmaf(e, w1.x, acc[4]);  acc[5]  = fmaf(e, w1.y, acc[5]);
            acc[6]  = fmaf(e, w1.z, acc[6]);  acc[7]  = fmaf(e, w1.w, acc[7]);
            acc[8]  = fmaf(e, w2.x, acc[8]);  acc[9]  = fmaf(e, w2.y, acc[9]);
            acc[10] = fmaf(e, w2.z, acc[10]); acc[11] = fmaf(e, w2.w, acc[11]);
            acc[12] = fmaf(e, w3.x, acc[12]); acc[13] = fmaf(e, w3.y, acc[13]);
            acc[14] = fmaf(e, w3.z, acc[14]); acc[15] = fmaf(e, w3.w, acc[15]);
        }
    }
    float4* outr = reinterpret_cast<float4*>(&g_O[(n * TT + q) * EE + h * DD]);
    outr[0] = make_float4(acc[0],  acc[1],  acc[2],  acc[3]);
    outr[1] = make_float4(acc[4],  acc[5],  acc[6],  acc[7]);
    outr[2] = make_float4(acc[8],  acc[9],  acc[10], acc[11]);
    outr[3] = make_float4(acc[12], acc[13], acc[14], acc[15]);
}

// ---------------------------------------------------------------------------
// K4: final FC: y = g_O @ Wfc + bfc. block = 256 = 64 rows x 4 col-quarters.
__global__ void k_fc(const float* __restrict__ Wfc,
                     const float* __restrict__ bfc,
                     float* __restrict__ out)
{
    __shared__ float sW[64 * 64];
    __shared__ float sb[64];
    __shared__ float Xs[64 * 68];   // padded rows to kill bank conflicts
    int tid = threadIdx.x;
    for (int i = tid; i < 4096; i += 256) sW[i] = Wfc[i];
    if (tid < 64) sb[tid] = bfc[tid];
    for (int i = tid; i < 4096; i += 256)
        Xs[(i >> 6) * 68 + (i & 63)] = g_O[blockIdx.x * 4096 + i];
    __syncthreads();

    int r  = tid >> 2;            // row within tile (0..63)
    int jo = (tid & 3) * 16;      // output quarter

    float acc[16];
    #pragma unroll
    for (int j = 0; j < 16; j++) acc[j] = sb[jo + j];

    #pragma unroll 4
    for (int i = 0; i < 64; i++) {
        float xi = Xs[r * 68 + i];
        const float4* w4 = reinterpret_cast<const float4*>(&sW[i * 64 + jo]);
        float4 w0 = w4[0], w1 = w4[1], w2 = w4[2], w3 = w4[3];
        acc[0]  = fmaf(xi, w0.x, acc[0]);  acc[1]  = fmaf(xi, w0.y, acc[1]);
        acc[2]  = fmaf(xi, w0.z, acc[2]);  acc[3]  = fmaf(xi, w0.w, acc[3]);
        acc[4]  = fmaf(xi, w1.x, acc[4]);  acc[5]  = fmaf(xi, w1.y, acc[5]);
        acc[6]  = fmaf(xi, w1.z, acc[6]);  acc[7]  = fmaf(xi, w1.w, acc[7]);
        acc[8]  = fmaf(xi, w2.x, acc[8]);  acc[9]  = fmaf(xi, w2.y, acc[9]);
        acc[10] = fmaf(xi, w2.z, acc[10]); acc[11] = fmaf(xi, w2.w, acc[11]);
        acc[12] = fmaf(xi, w3.x, acc[12]); acc[13] = fmaf(xi, w3.y, acc[13]);
        acc[14] = fmaf(xi, w3.z, acc[14]); acc[15] = fmaf(xi, w3.w, acc[15]);
    }

    float4* o4 = reinterpret_cast<float4*>(&out[blockIdx.x * 4096 + r * 64 + jo]);
    o4[0] = make_float4(acc[0],  acc[1],  acc[2],  acc[3]);
    o4[1] = make_float4(acc[4],  acc[5],  acc[6],  acc[7]);
    o4[2] = make_float4(acc[8],  acc[9],  acc[10], acc[11]);
    o4[3] = make_float4(acc[12], acc[13], acc[14], acc[15]);
}

// ---------------------------------------------------------------------------
// Input order per setup_inputs dict:
// 0:value 1:key 2:query 3:Wq 4:bq 5:Wk 6:bk 7:Wv 8:bv 9:Wfc 10:bfc
extern "C" void kernel_launch(void* const* d_in, const int* in_sizes, int n_in,
                              void* d_out, int out_size)
{
    const float* value = (const float*)d_in[0];
    const float* key_  = (const float*)d_in[1];
    const float* query = (const float*)d_in[2];
    const float* Wq    = (const float*)d_in[3];
    const float* bq    = (const float*)d_in[4];
    const float* Wk    = (const float*)d_in[5];
    const float* bk    = (const float*)d_in[6];
    const float* Wv    = (const float*)d_in[7];
    const float* bv    = (const float*)d_in[8];
    const float* Wfc   = (const float*)d_in[9];
    const float* bfc   = (const float*)d_in[10];
    float* out = (float*)d_out;

    k_proj<<<(NP * TT) / 256, 256>>>(value, key_, query, Wq, bq, Wk, bk, Wv, bv);
    k_colstats<<<dim3(TT / 128, NP), 128>>>();
    k_attn_out<<<dim3(TT / 128, NP), 128>>>();
    k_fc<<<(NN * TT) / 64, 256>>>(Wfc, bfc, out);
}

// round 3
// speedup vs baseline: 2.7696x; 2.7696x over previous
#include <cuda_runtime.h>
#include <cuda_fp16.h>
#include <cstdint>

// Problem constants: B=1, N=16, T=2048, E=64, H=4, D=16
#define NN   16
#define TT   2048
#define EE   64
#define HH   4
#define DD   16
#define NP   (NN*HH)          // 64 (n,h) pairs
#define QSCALE 0.125f         // 1/sqrt(E)

// ---------------------------------------------------------------------------
// Scratch (static device arrays; allocation-free per harness rules)
__device__ __align__(16) __half g_Qh[NP * TT * DD];  // q*0.125 hi
__device__ __align__(16) __half g_Ql[NP * TT * DD];  // q*0.125 lo
__device__ __align__(16) __half g_Kh[NP * TT * DD];
__device__ __align__(16) __half g_Kl[NP * TT * DD];
__device__ __align__(16) float  g_V [NP * TT * DD];  // projected v (fp32)
__device__ __align__(16) __half g_Wh[NP * TT * DD];  // (v/Z) hi
__device__ __align__(16) __half g_Wl[NP * TT * DD];  // (v/Z) lo
__device__ float g_Z[NP * TT];                       // column partition sums
__device__ __align__(16) float g_O[NN * TT * EE];    // attention out pre-FC

// ---------------------------------------------------------------------------
__device__ __forceinline__ uint32_t smem_u32(const void* p) {
    return (uint32_t)__cvta_generic_to_shared(p);
}
__device__ __forceinline__ void cp16(uint32_t dst, const void* src) {
    asm volatile("cp.async.cg.shared.global [%0], [%1], 16;" :: "r"(dst), "l"(src));
}
#define CP_COMMIT() asm volatile("cp.async.commit_group;")
#define CP_WAIT(n)  asm volatile("cp.async.wait_group %0;" :: "n"(n))

#define LDSM_X4(r0,r1,r2,r3,addr) \
    asm volatile("ldmatrix.sync.aligned.m8n8.x4.shared.b16 {%0,%1,%2,%3}, [%4];" \
        : "=r"(r0),"=r"(r1),"=r"(r2),"=r"(r3) : "r"(addr))
#define LDSM_X2(r0,r1,addr) \
    asm volatile("ldmatrix.sync.aligned.m8n8.x2.shared.b16 {%0,%1}, [%2];" \
        : "=r"(r0),"=r"(r1) : "r"(addr))
#define LDSM_X4T(r0,r1,r2,r3,addr) \
    asm volatile("ldmatrix.sync.aligned.m8n8.x4.trans.shared.b16 {%0,%1,%2,%3}, [%4];" \
        : "=r"(r0),"=r"(r1),"=r"(r2),"=r"(r3) : "r"(addr))
#define MMA16816(c0,c1,c2,c3,a0,a1,a2,a3,b0,b1) \
    asm volatile("mma.sync.aligned.m16n8k16.row.col.f32.f16.f16.f32 " \
        "{%0,%1,%2,%3},{%4,%5,%6,%7},{%8,%9},{%0,%1,%2,%3};" \
        : "+f"(c0),"+f"(c1),"+f"(c2),"+f"(c3) \
        : "r"(a0),"r"(a1),"r"(a2),"r"(a3),"r"(b0),"r"(b1))

__device__ __forceinline__ uint32_t pack2(__half a, __half b) {
    __half2 t = __halves2half2(a, b);
    return reinterpret_cast<uint32_t&>(t);
}

// ---------------------------------------------------------------------------
// K1: head projections -> split fp16 Q (scaled), K, and fp32 V.
__global__ void k_proj(const float* __restrict__ value,
                       const float* __restrict__ key,
                       const float* __restrict__ query,
                       const float* __restrict__ Wq, const float* __restrict__ bq,
                       const float* __restrict__ Wk, const float* __restrict__ bk,
                       const float* __restrict__ Wv, const float* __restrict__ bv)
{
    __shared__ float sWq[256], sWk[256], sWv[256];
    __shared__ float sbq[16], sbk[16], sbv[16];
    int tid = threadIdx.x;
    if (tid < 256) { sWq[tid] = Wq[tid]; sWk[tid] = Wk[tid]; sWv[tid] = Wv[tid]; }
    if (tid < 16)  { sbq[tid] = bq[tid]; sbk[tid] = bk[tid]; sbv[tid] = bv[tid]; }
    __syncthreads();

    int id = blockIdx.x * blockDim.x + tid;
    int t  = id & (TT - 1);
    int p  = id >> 11;
    int n  = p >> 2;
    int h  = p & 3;
    int in_base  = (n * TT + t) * EE + h * DD;
    int out_base = (p * TT + t) * DD;

    float x[16];
    // ---- q (scaled), split hi/lo ----
    #pragma unroll
    for (int i = 0; i < 16; i++) x[i] = query[in_base + i];
    {
        __half hh[16], hl[16];
        #pragma unroll
        for (int j = 0; j < 16; j++) {
            float acc = sbq[j];
            #pragma unroll
            for (int i = 0; i < 16; i++) acc = fmaf(x[i], sWq[i * 16 + j], acc);
            acc *= QSCALE;
            __half hi = __float2half_rn(acc);
            hh[j] = hi;
            hl[j] = __float2half_rn(acc - __half2float(hi));
        }
        __half2* dh = reinterpret_cast<__half2*>(&g_Qh[out_base]);
        __half2* dl = reinterpret_cast<__half2*>(&g_Ql[out_base]);
        #pragma unroll
        for (int j = 0; j < 8; j++) {
            dh[j] = __halves2half2(hh[2 * j], hh[2 * j + 1]);
            dl[j] = __halves2half2(hl[2 * j], hl[2 * j + 1]);
        }
    }
    // ---- k, split hi/lo ----
    #pragma unroll
    for (int i = 0; i < 16; i++) x[i] = key[in_base + i];
    {
        __half hh[16], hl[16];
        #pragma unroll
        for (int j = 0; j < 16; j++) {
            float acc = sbk[j];
            #pragma unroll
            for (int i = 0; i < 16; i++) acc = fmaf(x[i], sWk[i * 16 + j], acc);
            __half hi = __float2half_rn(acc);
            hh[j] = hi;
            hl[j] = __float2half_rn(acc - __half2float(hi));
        }
        __half2* dh = reinterpret_cast<__half2*>(&g_Kh[out_base]);
        __half2* dl = reinterpret_cast<__half2*>(&g_Kl[out_base]);
        #pragma unroll
        for (int j = 0; j < 8; j++) {
            dh[j] = __halves2half2(hh[2 * j], hh[2 * j + 1]);
            dl[j] = __halves2half2(hl[2 * j], hl[2 * j + 1]);
        }
    }
    // ---- v (fp32) ----
    #pragma unroll
    for (int i = 0; i < 16; i++) x[i] = value[in_base + i];
    #pragma unroll
    for (int j = 0; j < 16; j++) {
        float acc = sbv[j];
        #pragma unroll
        for (int i = 0; i < 16; i++) acc = fmaf(x[i], sWv[i * 16 + j], acc);
        g_V[out_base + j] = acc;
    }
}

// ---------------------------------------------------------------------------
// K2 (pass A): Z[k] = sum_q exp(q.k/8) via mma.  Warp owns 16 k-rows (A frag),
// streams Q tiles (B frags) through a 3-deep cp.async pipeline.
// grid = (TT/64, NP), block = 128 (4 warps).
__global__ void __launch_bounds__(128) k_zsum()
{
    __shared__ __align__(16) __half sKh[64 * 16], sKl[64 * 16];
    __shared__ __align__(16) __half sQh[3][128 * 16];
    __shared__ __align__(16) __half sQl[3][128 * 16];

    int tid = threadIdx.x, lane = tid & 31, warp = tid >> 5;
    int p = blockIdx.y, kbase = blockIdx.x * 64;

    // stage this block's 64 K rows (hi+lo)
    {
        int arr = tid >> 6, row = tid & 63;
        const uint4* src = reinterpret_cast<const uint4*>(
            (arr ? g_Kl : g_Kh) + (p * TT + kbase + row) * DD);
        uint4* dst = reinterpret_cast<uint4*>((arr ? sKl : sKh) + row * 16);
        dst[0] = src[0]; dst[1] = src[1];
    }

    // prologue: stage Q tiles 0 and 1
    {
        const __half* qh = g_Qh + (p * TT + 0 * 128 + tid) * DD;
        const __half* ql = g_Ql + (p * TT + 0 * 128 + tid) * DD;
        uint32_t dh = smem_u32(&sQh[0][tid * 16]);
        uint32_t dl = smem_u32(&sQl[0][tid * 16]);
        cp16(dh, qh); cp16(dh + 16, qh + 8);
        cp16(dl, ql); cp16(dl + 16, ql + 8);
    }
    CP_COMMIT();
    {
        const __half* qh = g_Qh + (p * TT + 1 * 128 + tid) * DD;
        const __half* ql = g_Ql + (p * TT + 1 * 128 + tid) * DD;
        uint32_t dh = smem_u32(&sQh[1][tid * 16]);
        uint32_t dl = smem_u32(&sQl[1][tid * 16]);
        cp16(dh, qh); cp16(dh + 16, qh + 8);
        cp16(dl, ql); cp16(dl + 16, ql + 8);
    }
    CP_COMMIT();

    __syncthreads();   // K tiles visible

    // A frags: K rows (m16 x k16), hi and lo
    uint32_t akh0, akh1, akh2, akh3, akl0, akl1, akl2, akl3;
    {
        int g = lane >> 3;
        int row = warp * 16 + (g & 1) * 8 + (lane & 7);
        int col = (g >> 1) * 8;
        uint32_t ah = smem_u32(&sKh[row * 16 + col]);
        LDSM_X4(akh0, akh1, akh2, akh3, ah);
        uint32_t al = smem_u32(&sKl[row * 16 + col]);
        LDSM_X4(akl0, akl1, akl2, akl3, al);
    }

    float z0 = 0.0f, z1 = 0.0f;

    for (int qt = 0; qt < 16; qt++) {
        if (qt < 15) { CP_WAIT(1); } else { CP_WAIT(0); }
        __syncthreads();
        int buf = qt % 3;
        #pragma unroll
        for (int qc = 0; qc < 16; qc++) {
            int brow = (qc * 8 + (lane & 7)) * 16 + ((lane >> 3) & 1) * 8;
            uint32_t b0h, b1h, b0l, b1l;
            LDSM_X2(b0h, b1h, smem_u32(&sQh[buf][brow]));
            LDSM_X2(b0l, b1l, smem_u32(&sQl[buf][brow]));
            float c0 = 0.f, c1 = 0.f, c2 = 0.f, c3 = 0.f;
            MMA16816(c0, c1, c2, c3, akh0, akh1, akh2, akh3, b0h, b1h);
            MMA16816(c0, c1, c2, c3, akh0, akh1, akh2, akh3, b0l, b1l);
            MMA16816(c0, c1, c2, c3, akl0, akl1, akl2, akl3, b0h, b1h);
            z0 += __expf(c0) + __expf(c1);
            z1 += __expf(c2) + __expf(c3);
        }
        // stage tile qt+2
        if (qt + 2 < 16) {
            int nb = (qt + 2) % 3;
            const __half* qh = g_Qh + (p * TT + (qt + 2) * 128 + tid) * DD;
            const __half* ql = g_Ql + (p * TT + (qt + 2) * 128 + tid) * DD;
            uint32_t dh = smem_u32(&sQh[nb][tid * 16]);
            uint32_t dl = smem_u32(&sQl[nb][tid * 16]);
            cp16(dh, qh); cp16(dh + 16, qh + 8);
            cp16(dl, ql); cp16(dl + 16, ql + 8);
            CP_COMMIT();
        }
    }

    // quad reduce across the 4 threads sharing each row
    z0 += __shfl_xor_sync(0xffffffffu, z0, 1);
    z0 += __shfl_xor_sync(0xffffffffu, z0, 2);
    z1 += __shfl_xor_sync(0xffffffffu, z1, 1);
    z1 += __shfl_xor_sync(0xffffffffu, z1, 2);
    if ((lane & 3) == 0) {
        int r = lane >> 2;
        g_Z[p * TT + kbase + warp * 16 + r]     = z0;
        g_Z[p * TT + kbase + warp * 16 + r + 8] = z1;
    }
}

// ---------------------------------------------------------------------------
// K3: fold 1/Z into V, split to fp16 hi/lo.  one thread per (p,k).
__global__ void k_fold()
{
    int id = blockIdx.x * blockDim.x + threadIdx.x;   // 0 .. NP*TT-1
    float inv = 1.0f / g_Z[id];
    const float4* v4 = reinterpret_cast<const float4*>(&g_V[id * DD]);
    __half2* dh = reinterpret_cast<__half2*>(&g_Wh[id * DD]);
    __half2* dl = reinterpret_cast<__half2*>(&g_Wl[id * DD]);
    #pragma unroll
    for (int i = 0; i < 4; i++) {
        float4 x = v4[i];
        float w0 = x.x * inv, w1 = x.y * inv, w2 = x.z * inv, w3 = x.w * inv;
        __half h0 = __float2half_rn(w0), h1 = __float2half_rn(w1);
        __half h2 = __float2half_rn(w2), h3 = __float2half_rn(w3);
        dh[2 * i]     = __halves2half2(h0, h1);
        dh[2 * i + 1] = __halves2half2(h2, h3);
        dl[2 * i]     = __halves2half2(__float2half_rn(w0 - __half2float(h0)),
                                       __float2half_rn(w1 - __half2float(h1)));
        dl[2 * i + 1] = __halves2half2(__float2half_rn(w2 - __half2float(h2)),
                                       __float2half_rn(w3 - __half2float(h3)));
    }
}

// ---------------------------------------------------------------------------
// K4 (pass B): out[q,:] = sum_k exp(q.k/8) * W[k,:]  (W pre-folded with 1/Z).
// FA2-style register pipeline: S via 3 mmas, exp, repack C->A frag, PV via 3.
// grid = (TT/64, NP), block = 128 (4 warps, warp owns 16 q rows).
__global__ void __launch_bounds__(128) k_out()
{
    __shared__ __align__(16) __half sQh[64 * 16], sQl[64 * 16];
    __shared__ __align__(16) __half sB[3][4][16 * 16];   // [buf][Kh,Kl,Wh,Wl]

    int tid = threadIdx.x, lane = tid & 31, warp = tid >> 5;
    int p = blockIdx.y, qbase = blockIdx.x * 64;
    int n = p >> 2, h = p & 3;

    // stage this block's 64 Q rows (hi+lo)
    {
        int arr = tid >> 6, row = tid & 63;
        const uint4* src = reinterpret_cast<const uint4*>(
            (arr ? g_Ql : g_Qh) + (p * TT + qbase + row) * DD);
        uint4* dst = reinterpret_cast<uint4*>((arr ? sQl : sQh) + row * 16);
        dst[0] = src[0]; dst[1] = src[1];
    }

    // per-thread chunk-stage role: 4 arrays x 16 rows x 2 halves
    int sarr = tid >> 5;
    int srow = (tid & 31) >> 1;
    int shf  = tid & 1;
    const __half* gsrc = (sarr == 0) ? g_Kh : (sarr == 1) ? g_Kl
                        : (sarr == 2) ? g_Wh : g_Wl;

    // prologue: stage chunks 0, 1
    cp16(smem_u32(&sB[0][sarr][srow * 16 + shf * 8]),
         gsrc + (p * TT + 0 * 16 + srow) * DD + shf * 8);
    CP_COMMIT();
    cp16(smem_u32(&sB[1][sarr][srow * 16 + shf * 8]),
         gsrc + (p * TT + 1 * 16 + srow) * DD + shf * 8);
    CP_COMMIT();

    __syncthreads();   // Q tile visible

    // A frags: Q rows (m16 x k16), hi and lo
    uint32_t aqh0, aqh1, aqh2, aqh3, aql0, aql1, aql2, aql3;
    int g = lane >> 3;
    {
        int row = warp * 16 + (g & 1) * 8 + (lane & 7);
        int col = (g >> 1) * 8;
        LDSM_X4(aqh0, aqh1, aqh2, aqh3, smem_u32(&sQh[row * 16 + col]));
        LDSM_X4(aql0, aql1, aql2, aql3, smem_u32(&sQl[row * 16 + col]));
    }

    float oc0[4] = {0.f, 0.f, 0.f, 0.f};   // d 0-7
    float oc1[4] = {0.f, 0.f, 0.f, 0.f};   // d 8-15

    // W b-frag ldmatrix address (x4 trans): [k0-7,d0-7][k8-15,d0-7][k0-7,d8-15][k8-15,d8-15]
    int wrow = (g & 1) * 8 + (lane & 7);
    int wcol = (g >> 1) * 8;

    for (int kc = 0; kc < 128; kc++) {
        if (kc < 127) { CP_WAIT(1); } else { CP_WAIT(0); }
        __syncthreads();
        int buf = kc % 3;

        // --- S tiles + exp -> P frags ---
        uint32_t pah[4], pal[4];
        #pragma unroll
        for (int t2 = 0; t2 < 2; t2++) {
            int brow = (t2 * 8 + (lane & 7)) * 16 + ((lane >> 3) & 1) * 8;
            uint32_t b0h, b1h, b0l, b1l;
            LDSM_X2(b0h, b1h, smem_u32(&sB[buf][0][brow]));
            LDSM_X2(b0l, b1l, smem_u32(&sB[buf][1][brow]));
            float c0 = 0.f, c1 = 0.f, c2 = 0.f, c3 = 0.f;
            MMA16816(c0, c1, c2, c3, aqh0, aqh1, aqh2, aqh3, b0h, b1h);
            MMA16816(c0, c1, c2, c3, aqh0, aqh1, aqh2, aqh3, b0l, b1l);
            MMA16816(c0, c1, c2, c3, aql0, aql1, aql2, aql3, b0h, b1h);
            float e0 = __expf(c0), e1 = __expf(c1);
            float e2 = __expf(c2), e3 = __expf(c3);
            __half h0 = __float2half_rn(e0), h1 = __float2half_rn(e1);
            __half h2 = __float2half_rn(e2), h3 = __float2half_rn(e3);
            pah[2 * t2]     = pack2(h0, h1);
            pah[2 * t2 + 1] = pack2(h2, h3);
            pal[2 * t2]     = pack2(__float2half_rn(e0 - __half2float(h0)),
                                    __float2half_rn(e1 - __half2float(h1)));
            pal[2 * t2 + 1] = pack2(__float2half_rn(e2 - __half2float(h2)),
                                    __float2half_rn(e3 - __half2float(h3)));
        }

        // --- W b-frags (hi, lo) ---
        uint32_t wh0, wh1, wh2, wh3, wl0, wl1, wl2, wl3;
        LDSM_X4T(wh0, wh1, wh2, wh3, smem_u32(&sB[buf][2][wrow * 16 + wcol]));
        LDSM_X4T(wl0, wl1, wl2, wl3, smem_u32(&sB[buf][3][wrow * 16 + wcol]));

        // --- PV: out += P * W (3-term split) ---
        MMA16816(oc0[0], oc0[1], oc0[2], oc0[3], pah[0], pah[1], pah[2], pah[3], wh0, wh1);
        MMA16816(oc0[0], oc0[1], oc0[2], oc0[3], pah[0], pah[1], pah[2], pah[3], wl0, wl1);
        MMA16816(oc0[0], oc0[1], oc0[2], oc0[3], pal[0], pal[1], pal[2], pal[3], wh0, wh1);
        MMA16816(oc1[0], oc1[1], oc1[2], oc1[3], pah[0], pah[1], pah[2], pah[3], wh2, wh3);
        MMA16816(oc1[0], oc1[1], oc1[2], oc1[3], pah[0], pah[1], pah[2], pah[3], wl2, wl3);
        MMA16816(oc1[0], oc1[1], oc1[2], oc1[3], pal[0], pal[1], pal[2], pal[3], wh2, wh3);

        // stage chunk kc+2
        if (kc + 2 < 128) {
            int nb = (kc + 2) % 3;
            cp16(smem_u32(&sB[nb][sarr][srow * 16 + shf * 8]),
                 gsrc + (p * TT + (kc + 2) * 16 + srow) * DD + shf * 8);
            CP_COMMIT();
        }
    }

    // epilogue: write fragments to g_O
    {
        int r = lane >> 2, c = lane & 3;
        int q0 = qbase + warp * 16 + r;
        int base0 = (n * TT + q0) * EE + h * DD;
        int base8 = (n * TT + q0 + 8) * EE + h * DD;
        *reinterpret_cast<float2*>(&g_O[base0 + 2 * c])     = make_float2(oc0[0], oc0[1]);
        *reinterpret_cast<float2*>(&g_O[base8 + 2 * c])     = make_float2(oc0[2], oc0[3]);
        *reinterpret_cast<float2*>(&g_O[base0 + 8 + 2 * c]) = make_float2(oc1[0], oc1[1]);
        *reinterpret_cast<float2*>(&g_O[base8 + 8 + 2 * c]) = make_float2(oc1[2], oc1[3]);
    }
}

// ---------------------------------------------------------------------------
// K5: final FC: y = g_O @ Wfc + bfc. block = 256 = 64 rows x 4 col-quarters.
__global__ void k_fc(const float* __restrict__ Wfc,
                     const float* __restrict__ bfc,
                     float* __restrict__ out)
{
    __shared__ float sW[64 * 64];
    __shared__ float sb[64];
    __shared__ float Xs[64 * 68];
    int tid = threadIdx.x;
    for (int i = tid; i < 4096; i += 256) sW[i] = Wfc[i];
    if (tid < 64) sb[tid] = bfc[tid];
    for (int i = tid; i < 4096; i += 256)
        Xs[(i >> 6) * 68 + (i & 63)] = g_O[blockIdx.x * 4096 + i];
    __syncthreads();

    int r  = tid >> 2;
    int jo = (tid & 3) * 16;

    float acc[16];
    #pragma unroll
    for (int j = 0; j < 16; j++) acc[j] = sb[jo + j];

    #pragma unroll 4
    for (int i = 0; i < 64; i++) {
        float xi = Xs[r * 68 + i];
        const float4* w4 = reinterpret_cast<const float4*>(&sW[i * 64 + jo]);
        float4 w0 = w4[0], w1 = w4[1], w2 = w4[2], w3 = w4[3];
        acc[0]  = fmaf(xi, w0.x, acc[0]);  acc[1]  = fmaf(xi, w0.y, acc[1]);
        acc[2]  = fmaf(xi, w0.z, acc[2]);  acc[3]  = fmaf(xi, w0.w, acc[3]);
        acc[4]  = fmaf(xi, w1.x, acc[4]);  acc[5]  = fmaf(xi, w1.y, acc[5]);
        acc[6]  = fmaf(xi, w1.z, acc[6]);  acc[7]  = fmaf(xi, w1.w, acc[7]);
        acc[8]  = fmaf(xi, w2.x, acc[8]);  acc[9]  = fmaf(xi, w2.y, acc[9]);
        acc[10] = fmaf(xi, w2.z, acc[10]); acc[11] = fmaf(xi, w2.w, acc[11]);
        acc[12] = fmaf(xi, w3.x, acc[12]); acc[13] = fmaf(xi, w3.y, acc[13]);
        acc[14] = fmaf(xi, w3.z, acc[14]); acc[15] = fmaf(xi, w3.w, acc[15]);
    }

    float4* o4 = reinterpret_cast<float4*>(&out[blockIdx.x * 4096 + r * 64 + jo]);
    o4[0] = make_float4(acc[0],  acc[1],  acc[2],  acc[3]);
    o4[1] = make_float4(acc[4],  acc[5],  acc[6],  acc[7]);
    o4[2] = make_float4(acc[8],  acc[9],  acc[10], acc[11]);
    o4[3] = make_float4(acc[12], acc[13], acc[14], acc[15]);
}

// ---------------------------------------------------------------------------
// Input order: 0:value 1:key 2:query 3:Wq 4:bq 5:Wk 6:bk 7:Wv 8:bv 9:Wfc 10:bfc
extern "C" void kernel_launch(void* const* d_in, const int* in_sizes, int n_in,
                              void* d_out, int out_size)
{
    const float* value = (const float*)d_in[0];
    const float* key_  = (const float*)d_in[1];
    const float* query = (const float*)d_in[2];
    const float* Wq    = (const float*)d_in[3];
    const float* bq    = (const float*)d_in[4];
    const float* Wk    = (const float*)d_in[5];
    const float* bk    = (const float*)d_in[6];
    const float* Wv    = (const float*)d_in[7];
    const float* bv    = (const float*)d_in[8];
    const float* Wfc   = (const float*)d_in[9];
    const float* bfc   = (const float*)d_in[10];
    float* out = (float*)d_out;

    k_proj<<<(NP * TT) / 256, 256>>>(value, key_, query, Wq, bq, Wk, bk, Wv, bv);
    k_zsum<<<dim3(TT / 64, NP), 128>>>();
    k_fold<<<(NP * TT) / 256, 256>>>();
    k_out<<<dim3(TT / 64, NP), 128>>>();
    k_fc<<<(NN * TT) / 64, 256>>>(Wfc, bfc, out);
}

// round 5
// speedup vs baseline: 3.6237x; 1.3084x over previous
#include <cuda_runtime.h>
#include <cuda_fp16.h>
#include <cstdint>

// Problem constants: B=1, N=16, T=2048, E=64, H=4, D=16
#define NN   16
#define TT   2048
#define EE   64
#define HH   4
#define DD   16
#define NP   (NN*HH)          // 64 (n,h) pairs
// Q pre-scaled by log2(e)/8 so scores are in log2 domain -> ex2.approx (1 MUFU)
#define QSCALE2 0.180336880740290f

// ---------------------------------------------------------------------------
// Scratch (static device arrays; allocation-free per harness rules)
__device__ __align__(16) __half g_Qh[NP * TT * DD];  // q*log2e/8 hi
__device__ __align__(16) __half g_Ql[NP * TT * DD];  // q*log2e/8 lo
__device__ __align__(16) __half g_Kh[NP * TT * DD];
__device__ __align__(16) __half g_Kl[NP * TT * DD];
__device__ __align__(16) float  g_V [NP * TT * DD];  // projected v (fp32)
__device__ __align__(16) __half g_Wh[NP * TT * DD];  // (v/Z) hi
__device__ __align__(16) __half g_Wl[NP * TT * DD];  // (v/Z) lo
__device__ float g_Z[NP * TT];                       // column partition sums
__device__ __align__(16) __half g_Oh[NN * TT * EE];  // attention out hi
__device__ __align__(16) __half g_Ol[NN * TT * EE];  // attention out lo
__device__ __align__(16) __half g_Wfh[EE * EE];      // Wfc hi
__device__ __align__(16) __half g_Wfl[EE * EE];      // Wfc lo

// ---------------------------------------------------------------------------
__device__ __forceinline__ float EX2(float x) {
    float r;
    asm("ex2.approx.ftz.f32 %0, %1;" : "=f"(r) : "f"(x));
    return r;
}
__device__ __forceinline__ uint32_t smem_u32(const void* p) {
    return (uint32_t)__cvta_generic_to_shared(p);
}
__device__ __forceinline__ void cp16(uint32_t dst, const void* src) {
    asm volatile("cp.async.cg.shared.global [%0], [%1], 16;" :: "r"(dst), "l"(src));
}
#define CP_COMMIT() asm volatile("cp.async.commit_group;")
#define CP_WAIT(n)  asm volatile("cp.async.wait_group %0;" :: "n"(n))

#define LDSM_X4(r0,r1,r2,r3,addr) \
    asm volatile("ldmatrix.sync.aligned.m8n8.x4.shared.b16 {%0,%1,%2,%3}, [%4];" \
        : "=r"(r0),"=r"(r1),"=r"(r2),"=r"(r3) : "r"(addr))
#define LDSM_X4T(r0,r1,r2,r3,addr) \
    asm volatile("ldmatrix.sync.aligned.m8n8.x4.trans.shared.b16 {%0,%1,%2,%3}, [%4];" \
        : "=r"(r0),"=r"(r1),"=r"(r2),"=r"(r3) : "r"(addr))
#define MMA16816(c0,c1,c2,c3,a0,a1,a2,a3,b0,b1) \
    asm volatile("mma.sync.aligned.m16n8k16.row.col.f32.f16.f16.f32 " \
        "{%0,%1,%2,%3},{%4,%5,%6,%7},{%8,%9},{%0,%1,%2,%3};" \
        : "+f"(c0),"+f"(c1),"+f"(c2),"+f"(c3) \
        : "r"(a0),"r"(a1),"r"(a2),"r"(a3),"r"(b0),"r"(b1))

__device__ __forceinline__ uint32_t h2u(__half2 h) {
    return reinterpret_cast<uint32_t&>(h);
}

// ---------------------------------------------------------------------------
// K1: head projections -> split fp16 Q (log2e-scaled), K, and fp32 V.
__global__ void k_proj(const float* __restrict__ value,
                       const float* __restrict__ key,
                       const float* __restrict__ query,
                       const float* __restrict__ Wq, const float* __restrict__ bq,
                       const float* __restrict__ Wk, const float* __restrict__ bk,
                       const float* __restrict__ Wv, const float* __restrict__ bv)
{
    __shared__ float sWq[256], sWk[256], sWv[256];
    __shared__ float sbq[16], sbk[16], sbv[16];
    int tid = threadIdx.x;
    if (tid < 256) { sWq[tid] = Wq[tid]; sWk[tid] = Wk[tid]; sWv[tid] = Wv[tid]; }
    if (tid < 16)  { sbq[tid] = bq[tid]; sbk[tid] = bk[tid]; sbv[tid] = bv[tid]; }
    __syncthreads();

    int id = blockIdx.x * blockDim.x + tid;
    int t  = id & (TT - 1);
    int p  = id >> 11;
    int n  = p >> 2;
    int h  = p & 3;
    int in_base  = (n * TT + t) * EE + h * DD;
    int out_base = (p * TT + t) * DD;

    float x[16];
    // ---- q (scaled by log2e/8), split hi/lo ----
    #pragma unroll
    for (int i = 0; i < 16; i++) x[i] = query[in_base + i];
    {
        __half hh[16], hl[16];
        #pragma unroll
        for (int j = 0; j < 16; j++) {
            float acc = sbq[j];
            #pragma unroll
            for (int i = 0; i < 16; i++) acc = fmaf(x[i], sWq[i * 16 + j], acc);
            acc *= QSCALE2;
            __half hi = __float2half_rn(acc);
            hh[j] = hi;
            hl[j] = __float2half_rn(acc - __half2float(hi));
        }
        __half2* dh = reinterpret_cast<__half2*>(&g_Qh[out_base]);
        __half2* dl = reinterpret_cast<__half2*>(&g_Ql[out_base]);
        #pragma unroll
        for (int j = 0; j < 8; j++) {
            dh[j] = __halves2half2(hh[2 * j], hh[2 * j + 1]);
            dl[j] = __halves2half2(hl[2 * j], hl[2 * j + 1]);
        }
    }
    // ---- k, split hi/lo ----
    #pragma unroll
    for (int i = 0; i < 16; i++) x[i] = key[in_base + i];
    {
        __half hh[16], hl[16];
        #pragma unroll
        for (int j = 0; j < 16; j++) {
            float acc = sbk[j];
            #pragma unroll
            for (int i = 0; i < 16; i++) acc = fmaf(x[i], sWk[i * 16 + j], acc);
            __half hi = __float2half_rn(acc);
            hh[j] = hi;
            hl[j] = __float2half_rn(acc - __half2float(hi));
        }
        __half2* dh = reinterpret_cast<__half2*>(&g_Kh[out_base]);
        __half2* dl = reinterpret_cast<__half2*>(&g_Kl[out_base]);
        #pragma unroll
        for (int j = 0; j < 8; j++) {
            dh[j] = __halves2half2(hh[2 * j], hh[2 * j + 1]);
            dl[j] = __halves2half2(hl[2 * j], hl[2 * j + 1]);
        }
    }
    // ---- v (fp32) ----
    #pragma unroll
    for (int i = 0; i < 16; i++) x[i] = value[in_base + i];
    #pragma unroll
    for (int j = 0; j < 16; j++) {
        float acc = sbv[j];
        #pragma unroll
        for (int i = 0; i < 16; i++) acc = fmaf(x[i], sWv[i * 16 + j], acc);
        g_V[out_base + j] = acc;
    }
}

// ---------------------------------------------------------------------------
// K2 (pass A): Z[k] = sum_q exp2(q.k*log2e/8).  Warp owns 32 k-rows (2 A-frag
// sets), streams Q in 128-row tiles through a 3-deep cp.async pipeline.
// grid = (TT/128, NP), block = 128 (4 warps -> 128 k rows per block).
__global__ void __launch_bounds__(128) k_zsum()
{
    __shared__ __align__(16) __half sKh[128 * 16], sKl[128 * 16];
    __shared__ __align__(16) __half sQ[3][2][128 * 16];   // [buf][hi/lo]

    int tid = threadIdx.x, lane = tid & 31, warp = tid >> 5;
    int p = blockIdx.y, kbase = blockIdx.x * 128;

    // stage this block's 128 K rows (hi+lo): 256 uint4 per array, 64 thr each
    {
        int arr = tid >> 6;
        const uint4* src = reinterpret_cast<const uint4*>(
            (arr ? g_Kl : g_Kh) + (p * TT + kbase) * DD);
        uint4* dst = reinterpret_cast<uint4*>(arr ? sKl : sKh);
        #pragma unroll
        for (int j = 0; j < 4; j++) dst[(tid & 63) * 4 + j] = src[(tid & 63) * 4 + j];
    }

    int arrq = tid >> 6;
    const __half* gq = (arrq ? g_Ql : g_Qh) + p * TT * DD;
    // prologue: stage Q tiles 0, 1
    #pragma unroll
    for (int qt0 = 0; qt0 < 2; qt0++) {
        uint32_t d = smem_u32(&sQ[qt0][arrq][0]);
        #pragma unroll
        for (int j = 0; j < 4; j++) {
            int o = (tid & 63) * 4 + j;          // uint4 slot (256 per array)
            cp16(d + o * 16, gq + qt0 * 128 * DD + o * 8);
        }
        CP_COMMIT();
    }

    __syncthreads();   // K tiles visible

    // A frags: 2 sets of 16 K rows (hi and lo)
    int g = lane >> 3;
    uint32_t akh[2][4], akl[2][4];
    #pragma unroll
    for (int s = 0; s < 2; s++) {
        int row = warp * 32 + s * 16 + (g & 1) * 8 + (lane & 7);
        int col = (g >> 1) * 8;
        LDSM_X4(akh[s][0], akh[s][1], akh[s][2], akh[s][3], smem_u32(&sKh[row * 16 + col]));
        LDSM_X4(akl[s][0], akl[s][1], akl[s][2], akl[s][3], smem_u32(&sKl[row * 16 + col]));
    }

    float z[2][2] = {{0.f, 0.f}, {0.f, 0.f}};
    int browq = (g >> 1) * 8 + (lane & 7);   // b-frag q-row within 16-chunk
    int bcol  = (g & 1) * 8;

    for (int qt = 0; qt < 16; qt++) {
        if (qt < 15) { CP_WAIT(1); } else { CP_WAIT(0); }
        __syncthreads();
        int buf = qt % 3;
        uint32_t qbh = smem_u32(&sQ[buf][0][browq * 16 + bcol]);
        uint32_t qbl = smem_u32(&sQ[buf][1][browq * 16 + bcol]);
        #pragma unroll
        for (int sub = 0; sub < 8; sub++) {
            uint32_t bh0, bh1, bh2, bh3, bl0, bl1, bl2, bl3;
            LDSM_X4(bh0, bh1, bh2, bh3, qbh + sub * 512);
            LDSM_X4(bl0, bl1, bl2, bl3, qbl + sub * 512);
            #pragma unroll
            for (int s = 0; s < 2; s++) {
                {
                    float c0 = 0.f, c1 = 0.f, c2 = 0.f, c3 = 0.f;
                    MMA16816(c0, c1, c2, c3, akh[s][0], akh[s][1], akh[s][2], akh[s][3], bh0, bh1);
                    MMA16816(c0, c1, c2, c3, akh[s][0], akh[s][1], akh[s][2], akh[s][3], bl0, bl1);
                    MMA16816(c0, c1, c2, c3, akl[s][0], akl[s][1], akl[s][2], akl[s][3], bh0, bh1);
                    z[s][0] += EX2(c0) + EX2(c1);
                    z[s][1] += EX2(c2) + EX2(c3);
                }
                {
                    float c0 = 0.f, c1 = 0.f, c2 = 0.f, c3 = 0.f;
                    MMA16816(c0, c1, c2, c3, akh[s][0], akh[s][1], akh[s][2], akh[s][3], bh2, bh3);
                    MMA16816(c0, c1, c2, c3, akh[s][0], akh[s][1], akh[s][2], akh[s][3], bl2, bl3);
                    MMA16816(c0, c1, c2, c3, akl[s][0], akl[s][1], akl[s][2], akl[s][3], bh2, bh3);
                    z[s][0] += EX2(c0) + EX2(c1);
                    z[s][1] += EX2(c2) + EX2(c3);
                }
            }
        }
        // stage tile qt+2
        if (qt + 2 < 16) {
            int nb = (qt + 2) % 3;
            uint32_t d = smem_u32(&sQ[nb][arrq][0]);
            #pragma unroll
            for (int j = 0; j < 4; j++) {
                int o = (tid & 63) * 4 + j;
                cp16(d + o * 16, gq + (qt + 2) * 128 * DD + o * 8);
            }
            CP_COMMIT();
        }
    }

    // quad reduce across the 4 threads sharing each row
    #pragma unroll
    for (int s = 0; s < 2; s++)
        #pragma unroll
        for (int j = 0; j < 2; j++) {
            z[s][j] += __shfl_xor_sync(0xffffffffu, z[s][j], 1);
            z[s][j] += __shfl_xor_sync(0xffffffffu, z[s][j], 2);
        }
    if ((lane & 3) == 0) {
        int r = lane >> 2;
        #pragma unroll
        for (int s = 0; s < 2; s++) {
            g_Z[p * TT + kbase + warp * 32 + s * 16 + r]     = z[s][0];
            g_Z[p * TT + kbase + warp * 32 + s * 16 + r + 8] = z[s][1];
        }
    }
}

// ---------------------------------------------------------------------------
// K3: fold 1/Z into V, split to fp16 hi/lo.  one thread per (p,k).
__global__ void k_fold()
{
    int id = blockIdx.x * blockDim.x + threadIdx.x;   // 0 .. NP*TT-1
    float inv = 1.0f / g_Z[id];
    const float4* v4 = reinterpret_cast<const float4*>(&g_V[id * DD]);
    __half2* dh = reinterpret_cast<__half2*>(&g_Wh[id * DD]);
    __half2* dl = reinterpret_cast<__half2*>(&g_Wl[id * DD]);
    #pragma unroll
    for (int i = 0; i < 4; i++) {
        float4 x = v4[i];
        float w0 = x.x * inv, w1 = x.y * inv, w2 = x.z * inv, w3 = x.w * inv;
        __half2 h01 = __float22half2_rn(make_float2(w0, w1));
        __half2 h23 = __float22half2_rn(make_float2(w2, w3));
        float2 b01 = __half22float2(h01);
        float2 b23 = __half22float2(h23);
        dh[2 * i]     = h01;
        dh[2 * i + 1] = h23;
        dl[2 * i]     = __float22half2_rn(make_float2(w0 - b01.x, w1 - b01.y));
        dl[2 * i + 1] = __float22half2_rn(make_float2(w2 - b23.x, w3 - b23.y));
    }
}

// ---------------------------------------------------------------------------
// K4 (pass B): out[q,:] = sum_k exp2(s) * W[k,:]  (W pre-folded with 1/Z).
// 64-k chunks, 3-deep cp.async pipeline, one sync per 64 k.
// grid = (TT/64, NP), block = 128 (4 warps, warp owns 16 q rows).
__global__ void __launch_bounds__(128) k_out()
{
    __shared__ __align__(16) __half sQh[64 * 16], sQl[64 * 16];
    __shared__ __align__(16) __half sB[3][4][64 * 16];   // [buf][Kh,Kl,Wh,Wl]

    int tid = threadIdx.x, lane = tid & 31, warp = tid >> 5;
    int p = blockIdx.y, qbase = blockIdx.x * 64;
    int n = p >> 2, h = p & 3;

    // stage this block's 64 Q rows (hi+lo)
    {
        int arr = tid >> 6, row = tid & 63;
        const uint4* src = reinterpret_cast<const uint4*>(
            (arr ? g_Ql : g_Qh) + (p * TT + qbase + row) * DD);
        uint4* dst = reinterpret_cast<uint4*>((arr ? sQl : sQh) + row * 16);
        dst[0] = src[0]; dst[1] = src[1];
    }

    // B-chunk staging role: 4 arrays x (64 rows x 2 halves = 128 slots); 4/thread
    int sarr = tid >> 5;
    const __half* gsrc = (sarr == 0) ? g_Kh : (sarr == 1) ? g_Kl
                        : (sarr == 2) ? g_Wh : g_Wl;
    const __half* gsb = gsrc + p * TT * DD;
    uint32_t soff = smem_u32(&sB[0][sarr][0]) - smem_u32(&sB[0][0][0]);
    uint32_t sb_base = smem_u32(&sB[0][0][0]);
    const uint32_t BUFB = 4 * 64 * 16 * 2;   // bytes per buffer

    // prologue: stage chunks 0, 1
    #pragma unroll
    for (int c0 = 0; c0 < 2; c0++) {
        uint32_t d = sb_base + c0 * BUFB + soff;
        #pragma unroll
        for (int j = 0; j < 4; j++) {
            int o = (tid & 31) * 4 + j;          // 16B slot (128 per array)
            cp16(d + o * 16, gsb + c0 * 64 * DD + o * 8);
        }
        CP_COMMIT();
    }

    __syncthreads();   // Q tile visible

    // A frags: Q rows (m16 x k16), hi and lo
    int g = lane >> 3;
    uint32_t aqh0, aqh1, aqh2, aqh3, aql0, aql1, aql2, aql3;
    {
        int row = warp * 16 + (g & 1) * 8 + (lane & 7);
        int col = (g >> 1) * 8;
        LDSM_X4(aqh0, aqh1, aqh2, aqh3, smem_u32(&sQh[row * 16 + col]));
        LDSM_X4(aql0, aql1, aql2, aql3, smem_u32(&sQl[row * 16 + col]));
    }

    float oc0[4] = {0.f, 0.f, 0.f, 0.f};   // d 0-7
    float oc1[4] = {0.f, 0.f, 0.f, 0.f};   // d 8-15

    uint32_t koff = ((g >> 1) * 8 + (lane & 7)) * 32 + (g & 1) * 16;        // K b-frag byte off
    uint32_t woff = 2 * 64 * 16 * 2 + ((g & 1) * 8 + (lane & 7)) * 32 + (g >> 1) * 16; // Wh base

    for (int kc = 0; kc < 32; kc++) {
        if (kc < 31) { CP_WAIT(1); } else { CP_WAIT(0); }
        __syncthreads();
        uint32_t bufb = sb_base + (kc % 3) * BUFB;
        uint32_t kaddr = bufb + koff;
        uint32_t waddr = bufb + woff;
        #pragma unroll
        for (int sub = 0; sub < 4; sub++) {
            // --- S tiles + exp2 -> P frags ---
            uint32_t kh0, kh1, kh2, kh3, kl0, kl1, kl2, kl3;
            LDSM_X4(kh0, kh1, kh2, kh3, kaddr + sub * 512);
            LDSM_X4(kl0, kl1, kl2, kl3, kaddr + 2048 + sub * 512);
            uint32_t pah[4], pal[4];
            {
                float c0 = 0.f, c1 = 0.f, c2 = 0.f, c3 = 0.f;
                MMA16816(c0, c1, c2, c3, aqh0, aqh1, aqh2, aqh3, kh0, kh1);
                MMA16816(c0, c1, c2, c3, aqh0, aqh1, aqh2, aqh3, kl0, kl1);
                MMA16816(c0, c1, c2, c3, aql0, aql1, aql2, aql3, kh0, kh1);
                float e0 = EX2(c0), e1 = EX2(c1);
                float e2 = EX2(c2), e3 = EX2(c3);
                __half2 h01 = __float22half2_rn(make_float2(e0, e1));
                __half2 h23 = __float22half2_rn(make_float2(e2, e3));
                float2 b01 = __half22float2(h01), b23 = __half22float2(h23);
                pah[0] = h2u(h01); pah[1] = h2u(h23);
                pal[0] = h2u(__float22half2_rn(make_float2(e0 - b01.x, e1 - b01.y)));
                pal[1] = h2u(__float22half2_rn(make_float2(e2 - b23.x, e3 - b23.y)));
            }
            {
                float c0 = 0.f, c1 = 0.f, c2 = 0.f, c3 = 0.f;
                MMA16816(c0, c1, c2, c3, aqh0, aqh1, aqh2, aqh3, kh2, kh3);
                MMA16816(c0, c1, c2, c3, aqh0, aqh1, aqh2, aqh3, kl2, kl3);
                MMA16816(c0, c1, c2, c3, aql0, aql1, aql2, aql3, kh2, kh3);
                float e0 = EX2(c0), e1 = EX2(c1);
                float e2 = EX2(c2), e3 = EX2(c3);
                __half2 h01 = __float22half2_rn(make_float2(e0, e1));
                __half2 h23 = __float22half2_rn(make_float2(e2, e3));
                float2 b01 = __half22float2(h01), b23 = __half22float2(h23);
                pah[2] = h2u(h01); pah[3] = h2u(h23);
                pal[2] = h2u(__float22half2_rn(make_float2(e0 - b01.x, e1 - b01.y)));
                pal[3] = h2u(__float22half2_rn(make_float2(e2 - b23.x, e3 - b23.y)));
            }

            // --- W b-frags (hi, lo) ---
            uint32_t wh0, wh1, wh2, wh3, wl0, wl1, wl2, wl3;
            LDSM_X4T(wh0, wh1, wh2, wh3, waddr + sub * 512);
            LDSM_X4T(wl0, wl1, wl2, wl3, waddr + 2048 + sub * 512);

            // --- PV: out += P * W (3-term split) ---
            MMA16816(oc0[0], oc0[1], oc0[2], oc0[3], pah[0], pah[1], pah[2], pah[3], wh0, wh1);
            MMA16816(oc0[0], oc0[1], oc0[2], oc0[3], pah[0], pah[1], pah[2], pah[3], wl0, wl1);
            MMA16816(oc0[0], oc0[1], oc0[2], oc0[3], pal[0], pal[1], pal[2], pal[3], wh0, wh1);
            MMA16816(oc1[0], oc1[1], oc1[2], oc1[3], pah[0], pah[1], pah[2], pah[3], wh2, wh3);
            MMA16816(oc1[0], oc1[1], oc1[2], oc1[3], pah[0], pah[1], pah[2], pah[3], wl2, wl3);
            MMA16816(oc1[0], oc1[1], oc1[2], oc1[3], pal[0], pal[1], pal[2], pal[3], wh2, wh3);
        }
        // stage chunk kc+2
        if (kc + 2 < 32) {
            uint32_t d = sb_base + ((kc + 2) % 3) * BUFB + soff;
            #pragma unroll
            for (int j = 0; j < 4; j++) {
                int o = (tid & 31) * 4 + j;
                cp16(d + o * 16, gsb + (kc + 2) * 64 * DD + o * 8);
            }
            CP_COMMIT();
        }
    }

    // epilogue: write fp16 hi/lo fragments to g_Oh / g_Ol
    {
        int r = lane >> 2, c2 = lane & 3;
        int q0 = qbase + warp * 16 + r;
        int b0i = (n * TT + q0) * EE + h * DD;
        int b8i = (n * TT + q0 + 8) * EE + h * DD;
        int idxs[4] = { b0i + 2 * c2, b8i + 2 * c2, b0i + 8 + 2 * c2, b8i + 8 + 2 * c2 };
        float vals[4][2] = { {oc0[0], oc0[1]}, {oc0[2], oc0[3]},
                             {oc1[0], oc1[1]}, {oc1[2], oc1[3]} };
        #pragma unroll
        for (int i = 0; i < 4; i++) {
            __half2 hi = __float22half2_rn(make_float2(vals[i][0], vals[i][1]));
            float2 bb = __half22float2(hi);
            __half2 lo = __float22half2_rn(make_float2(vals[i][0] - bb.x, vals[i][1] - bb.y));
            *reinterpret_cast<__half2*>(&g_Oh[idxs[i]]) = hi;
            *reinterpret_cast<__half2*>(&g_Ol[idxs[i]]) = lo;
        }
    }
}

// ---------------------------------------------------------------------------
// K5a: split Wfc into fp16 hi/lo (one-time, tiny).
__global__ void k_wsplit(const float* __restrict__ Wfc)
{
    int i = blockIdx.x * blockDim.x + threadIdx.x;   // 0..4095
    float w = Wfc[i];
    __half hi = __float2half_rn(w);
    g_Wfh[i] = hi;
    g_Wfl[i] = __float2half_rn(w - __half2float(hi));
}

// ---------------------------------------------------------------------------
// K5b: final FC via fp16-split HMMA: y = O @ Wfc + bfc.
// grid = 256 blocks x 128 rows; block = 256 (8 warps, warp owns 16 rows).
__global__ void __launch_bounds__(256) k_fc_mma(const float* __restrict__ bfc,
                                               float* __restrict__ out)
{
    __shared__ __align__(16) __half sXh[128 * 64], sXl[128 * 64];
    __shared__ __align__(16) __half sWh[64 * 64],  sWl[64 * 64];
    __shared__ float sb[64];

    int tid = threadIdx.x, lane = tid & 31, warp = tid >> 5;
    int rowbase = blockIdx.x * 128;

    // stage X (128x64 hi/lo): 1024 uint4 per array, 4 per thread
    {
        const uint4* srch = reinterpret_cast<const uint4*>(g_Oh + rowbase * EE);
        const uint4* srcl = reinterpret_cast<const uint4*>(g_Ol + rowbase * EE);
        uint4* dh = reinterpret_cast<uint4*>(sXh);
        uint4* dl = reinterpret_cast<uint4*>(sXl);
        #pragma unroll
        for (int j = 0; j < 4; j++) {
            dh[tid + j * 256] = srch[tid + j * 256];
            dl[tid + j * 256] = srcl[tid + j * 256];
        }
    }
    // stage W (64x64 hi/lo): 512 uint4 per array, 2 per thread
    {
        const uint4* srch = reinterpret_cast<const uint4*>(g_Wfh);
        const uint4* srcl = reinterpret_cast<const uint4*>(g_Wfl);
        uint4* dh = reinterpret_cast<uint4*>(sWh);
        uint4* dl = reinterpret_cast<uint4*>(sWl);
        dh[tid] = srch[tid]; dh[tid + 256] = srch[tid + 256];
        dl[tid] = srcl[tid]; dl[tid + 256] = srcl[tid + 256];
    }
    if (tid < 64) sb[tid] = bfc[tid];
    __syncthreads();

    int g = lane >> 3;
    // A frags: warp's 16 rows x 4 k-tiles (hi, lo)
    uint32_t axh[4][4], axl[4][4];
    #pragma unroll
    for (int kt = 0; kt < 4; kt++) {
        int row = warp * 16 + (g & 1) * 8 + (lane & 7);
        int col = kt * 16 + (g >> 1) * 8;
        LDSM_X4(axh[kt][0], axh[kt][1], axh[kt][2], axh[kt][3], smem_u32(&sXh[row * 64 + col]));
        LDSM_X4(axl[kt][0], axl[kt][1], axl[kt][2], axl[kt][3], smem_u32(&sXl[row * 64 + col]));
    }

    float c[8][4];
    #pragma unroll
    for (int i = 0; i < 8; i++)
        #pragma unroll
        for (int j = 0; j < 4; j++) c[i][j] = 0.f;

    #pragma unroll
    for (int nt2 = 0; nt2 < 4; nt2++) {
        #pragma unroll
        for (int kt = 0; kt < 4; kt++) {
            int brow = kt * 16 + (g & 1) * 8 + (lane & 7);
            int bcol = nt2 * 16 + (g >> 1) * 8;
            uint32_t bh0, bh1, bh2, bh3, bl0, bl1, bl2, bl3;
            LDSM_X4T(bh0, bh1, bh2, bh3, smem_u32(&sWh[brow * 64 + bcol]));
            LDSM_X4T(bl0, bl1, bl2, bl3, smem_u32(&sWl[brow * 64 + bcol]));
            MMA16816(c[nt2*2][0], c[nt2*2][1], c[nt2*2][2], c[nt2*2][3],
                     axh[kt][0], axh[kt][1], axh[kt][2], axh[kt][3], bh0, bh1);
            MMA16816(c[nt2*2][0], c[nt2*2][1], c[nt2*2][2], c[nt2*2][3],
                     axh[kt][0], axh[kt][1], axh[kt][2], axh[kt][3], bl0, bl1);
            MMA16816(c[nt2*2][0], c[nt2*2][1], c[nt2*2][2], c[nt2*2][3],
                     axl[kt][0], axl[kt][1], axl[kt][2], axl[kt][3], bh0, bh1);
            MMA16816(c[nt2*2+1][0], c[nt2*2+1][1], c[nt2*2+1][2], c[nt2*2+1][3],
                     axh[kt][0], axh[kt][1], axh[kt][2], axh[kt][3], bh2, bh3);
            MMA16816(c[nt2*2+1][0], c[nt2*2+1][1], c[nt2*2+1][2], c[nt2*2+1][3],
                     axh[kt][0], axh[kt][1], axh[kt][2], axh[kt][3], bl2, bl3);
            MMA16816(c[nt2*2+1][0], c[nt2*2+1][1], c[nt2*2+1][2], c[nt2*2+1][3],
                     axl[kt][0], axl[kt][1], axl[kt][2], axl[kt][3], bh2, bh3);
        }
    }

    // epilogue: add bias, store fp32
    int r = lane >> 2, j = lane & 3;
    int row0 = rowbase + warp * 16 + r;
    #pragma unroll
    for (int nt = 0; nt < 8; nt++) {
        int ncol = nt * 8 + 2 * j;
        float b0 = sb[ncol], b1 = sb[ncol + 1];
        *reinterpret_cast<float2*>(&out[row0 * 64 + ncol]) =
            make_float2(c[nt][0] + b0, c[nt][1] + b1);
        *reinterpret_cast<float2*>(&out[(row0 + 8) * 64 + ncol]) =
            make_float2(c[nt][2] + b0, c[nt][3] + b1);
    }
}

// ---------------------------------------------------------------------------
// Input order: 0:value 1:key 2:query 3:Wq 4:bq 5:Wk 6:bk 7:Wv 8:bv 9:Wfc 10:bfc
extern "C" void kernel_launch(void* const* d_in, const int* in_sizes, int n_in,
                              void* d_out, int out_size)
{
    const float* value = (const float*)d_in[0];
    const float* key_  = (const float*)d_in[1];
    const float* query = (const float*)d_in[2];
    const float* Wq    = (const float*)d_in[3];
    const float* bq    = (const float*)d_in[4];
    const float* Wk    = (const float*)d_in[5];
    const float* bk    = (const float*)d_in[6];
    const float* Wv    = (const float*)d_in[7];
    const float* bv    = (const float*)d_in[8];
    const float* Wfc   = (const float*)d_in[9];
    const float* bfc   = (const float*)d_in[10];
    float* out = (float*)d_out;

    k_wsplit<<<16, 256>>>(Wfc);
    k_proj<<<(NP * TT) / 256, 256>>>(value, key_, query, Wq, bq, Wk, bk, Wv, bv);
    k_zsum<<<dim3(TT / 128, NP), 128>>>();
    k_fold<<<(NP * TT) / 256, 256>>>();
    k_out<<<dim3(TT / 64, NP), 128>>>();
    k_fc_mma<<<(NN * TT) / 128, 256>>>(bfc, out);
}

// round 7
// speedup vs baseline: 3.7431x; 1.0330x over previous
#include <cuda_runtime.h>
#include <cuda_fp16.h>
#include <cstdint>

// Problem constants: B=1, N=16, T=2048, E=64, H=4, D=16
#define NN   16
#define TT   2048
#define EE   64
#define HH   4
#define DD   16
#define NP   (NN*HH)          // 64 (n,h) pairs
// Q pre-scaled by log2(e)/8 so scores are in log2 domain -> ex2.approx (1 MUFU)
#define QSCALE2 0.180336880740290f

// ---------------------------------------------------------------------------
// Scratch (static device arrays; allocation-free per harness rules)
__device__ __align__(16) __half g_Qh[NP * TT * DD];  // q*log2e/8 hi
__device__ __align__(16) __half g_Ql[NP * TT * DD];  // q*log2e/8 lo
__device__ __align__(16) __half g_Kh[NP * TT * DD];
__device__ __align__(16) __half g_Kl[NP * TT * DD];
__device__ __align__(16) float  g_V [NP * TT * DD];  // projected v (fp32)
__device__ __align__(16) __half g_Wh[NP * TT * DD];  // (v/Z) hi
__device__ __align__(16) __half g_Wl[NP * TT * DD];  // (v/Z) lo
__device__ __align__(16) __half g_Oh[NN * TT * EE];  // attention out hi
__device__ __align__(16) __half g_Ol[NN * TT * EE];  // attention out lo
__device__ __align__(16) __half g_Wfh[EE * EE];      // Wfc hi
__device__ __align__(16) __half g_Wfl[EE * EE];      // Wfc lo

// ---------------------------------------------------------------------------
__device__ __forceinline__ float EX2(float x) {
    float r;
    asm("ex2.approx.ftz.f32 %0, %1;" : "=f"(r) : "f"(x));
    return r;
}
__device__ __forceinline__ uint32_t smem_u32(const void* p) {
    return (uint32_t)__cvta_generic_to_shared(p);
}
__device__ __forceinline__ void cp16(uint32_t dst, const void* src) {
    asm volatile("cp.async.cg.shared.global [%0], [%1], 16;" :: "r"(dst), "l"(src));
}
#define CP_COMMIT() asm volatile("cp.async.commit_group;")
#define CP_WAIT(n)  asm volatile("cp.async.wait_group %0;" :: "n"(n))

#define LDSM_X4(r0,r1,r2,r3,addr) \
    asm volatile("ldmatrix.sync.aligned.m8n8.x4.shared.b16 {%0,%1,%2,%3}, [%4];" \
        : "=r"(r0),"=r"(r1),"=r"(r2),"=r"(r3) : "r"(addr))
#define LDSM_X4T(r0,r1,r2,r3,addr) \
    asm volatile("ldmatrix.sync.aligned.m8n8.x4.trans.shared.b16 {%0,%1,%2,%3}, [%4];" \
        : "=r"(r0),"=r"(r1),"=r"(r2),"=r"(r3) : "r"(addr))
#define MMA16816(c0,c1,c2,c3,a0,a1,a2,a3,b0,b1) \
    asm volatile("mma.sync.aligned.m16n8k16.row.col.f32.f16.f16.f32 " \
        "{%0,%1,%2,%3},{%4,%5,%6,%7},{%8,%9},{%0,%1,%2,%3};" \
        : "+f"(c0),"+f"(c1),"+f"(c2),"+f"(c3) \
        : "r"(a0),"r"(a1),"r"(a2),"r"(a3),"r"(b0),"r"(b1))

__device__ __forceinline__ uint32_t h2u(__half2 h) {
    return reinterpret_cast<uint32_t&>(h);
}

// ---------------------------------------------------------------------------
// K1: head projections -> split fp16 Q (log2e-scaled), K, and fp32 V.
__global__ void k_proj(const float* __restrict__ value,
                       const float* __restrict__ key,
                       const float* __restrict__ query,
                       const float* __restrict__ Wq, const float* __restrict__ bq,
                       const float* __restrict__ Wk, const float* __restrict__ bk,
                       const float* __restrict__ Wv, const float* __restrict__ bv)
{
    __shared__ float sWq[256], sWk[256], sWv[256];
    __shared__ float sbq[16], sbk[16], sbv[16];
    int tid = threadIdx.x;
    if (tid < 256) { sWq[tid] = Wq[tid]; sWk[tid] = Wk[tid]; sWv[tid] = Wv[tid]; }
    if (tid < 16)  { sbq[tid] = bq[tid]; sbk[tid] = bk[tid]; sbv[tid] = bv[tid]; }
    __syncthreads();

    int id = blockIdx.x * blockDim.x + tid;
    int t  = id & (TT - 1);
    int p  = id >> 11;
    int n  = p >> 2;
    int h  = p & 3;
    int in_base  = (n * TT + t) * EE + h * DD;
    int out_base = (p * TT + t) * DD;

    float x[16];
    // ---- q (scaled by log2e/8), split hi/lo ----
    #pragma unroll
    for (int i = 0; i < 16; i++) x[i] = query[in_base + i];
    {
        __half hh[16], hl[16];
        #pragma unroll
        for (int j = 0; j < 16; j++) {
            float acc = sbq[j];
            #pragma unroll
            for (int i = 0; i < 16; i++) acc = fmaf(x[i], sWq[i * 16 + j], acc);
            acc *= QSCALE2;
            __half hi = __float2half_rn(acc);
            hh[j] = hi;
            hl[j] = __float2half_rn(acc - __half2float(hi));
        }
        __half2* dh = reinterpret_cast<__half2*>(&g_Qh[out_base]);
        __half2* dl = reinterpret_cast<__half2*>(&g_Ql[out_base]);
        #pragma unroll
        for (int j = 0; j < 8; j++) {
            dh[j] = __halves2half2(hh[2 * j], hh[2 * j + 1]);
            dl[j] = __halves2half2(hl[2 * j], hl[2 * j + 1]);
        }
    }
    // ---- k, split hi/lo ----
    #pragma unroll
    for (int i = 0; i < 16; i++) x[i] = key[in_base + i];
    {
        __half hh[16], hl[16];
        #pragma unroll
        for (int j = 0; j < 16; j++) {
            float acc = sbk[j];
            #pragma unroll
            for (int i = 0; i < 16; i++) acc = fmaf(x[i], sWk[i * 16 + j], acc);
            __half hi = __float2half_rn(acc);
            hh[j] = hi;
            hl[j] = __float2half_rn(acc - __half2float(hi));
        }
        __half2* dh = reinterpret_cast<__half2*>(&g_Kh[out_base]);
        __half2* dl = reinterpret_cast<__half2*>(&g_Kl[out_base]);
        #pragma unroll
        for (int j = 0; j < 8; j++) {
            dh[j] = __halves2half2(hh[2 * j], hh[2 * j + 1]);
            dl[j] = __halves2half2(hl[2 * j], hl[2 * j + 1]);
        }
    }
    // ---- v (fp32) ----
    #pragma unroll
    for (int i = 0; i < 16; i++) x[i] = value[in_base + i];
    #pragma unroll
    for (int j = 0; j < 16; j++) {
        float acc = sbv[j];
        #pragma unroll
        for (int i = 0; i < 16; i++) acc = fmaf(x[i], sWv[i * 16 + j], acc);
        g_V[out_base + j] = acc;
    }
}

// ---------------------------------------------------------------------------
// K2 (pass A): Z[k] = sum_q exp2(q.k*log2e/8), then fold 1/Z into V in-place
// (fused former k_fold).  Warp owns 32 k-rows (2 A-frag sets), streams Q in
// 128-row tiles through a 3-deep cp.async pipeline.
// grid = (TT/128, NP), block = 128 (4 warps -> 128 k rows per block).
__global__ void __launch_bounds__(128) k_zsum()
{
    __shared__ __align__(16) __half sKh[128 * 16], sKl[128 * 16];
    __shared__ __align__(16) __half sQ[3][2][128 * 16];   // [buf][hi/lo]
    __shared__ float sZ[128];

    int tid = threadIdx.x, lane = tid & 31, warp = tid >> 5;
    int p = blockIdx.y, kbase = blockIdx.x * 128;

    // stage this block's 128 K rows (hi+lo): 256 uint4 per array, 64 thr each
    {
        int arr = tid >> 6;
        const uint4* src = reinterpret_cast<const uint4*>(
            (arr ? g_Kl : g_Kh) + (p * TT + kbase) * DD);
        uint4* dst = reinterpret_cast<uint4*>(arr ? sKl : sKh);
        #pragma unroll
        for (int j = 0; j < 4; j++) dst[(tid & 63) * 4 + j] = src[(tid & 63) * 4 + j];
    }

    int arrq = tid >> 6;
    const __half* gq = (arrq ? g_Ql : g_Qh) + p * TT * DD;
    // prologue: stage Q tiles 0, 1
    #pragma unroll
    for (int qt0 = 0; qt0 < 2; qt0++) {
        uint32_t d = smem_u32(&sQ[qt0][arrq][0]);
        #pragma unroll
        for (int j = 0; j < 4; j++) {
            int o = (tid & 63) * 4 + j;          // uint4 slot (256 per array)
            cp16(d + o * 16, gq + qt0 * 128 * DD + o * 8);
        }
        CP_COMMIT();
    }

    __syncthreads();   // K tiles visible

    // A frags: 2 sets of 16 K rows (hi and lo)
    int g = lane >> 3;
    uint32_t akh[2][4], akl[2][4];
    #pragma unroll
    for (int s = 0; s < 2; s++) {
        int row = warp * 32 + s * 16 + (g & 1) * 8 + (lane & 7);
        int col = (g >> 1) * 8;
        LDSM_X4(akh[s][0], akh[s][1], akh[s][2], akh[s][3], smem_u32(&sKh[row * 16 + col]));
        LDSM_X4(akl[s][0], akl[s][1], akl[s][2], akl[s][3], smem_u32(&sKl[row * 16 + col]));
    }

    float z[2][2] = {{0.f, 0.f}, {0.f, 0.f}};
    int browq = (g >> 1) * 8 + (lane & 7);   // b-frag q-row within 16-chunk
    int bcol  = (g & 1) * 8;

    for (int qt = 0; qt < 16; qt++) {
        if (qt < 15) { CP_WAIT(1); } else { CP_WAIT(0); }
        __syncthreads();
        int buf = qt % 3;
        uint32_t qbh = smem_u32(&sQ[buf][0][browq * 16 + bcol]);
        uint32_t qbl = smem_u32(&sQ[buf][1][browq * 16 + bcol]);
        #pragma unroll
        for (int sub = 0; sub < 8; sub++) {
            uint32_t bh0, bh1, bh2, bh3, bl0, bl1, bl2, bl3;
            LDSM_X4(bh0, bh1, bh2, bh3, qbh + sub * 512);
            LDSM_X4(bl0, bl1, bl2, bl3, qbl + sub * 512);
            #pragma unroll
            for (int s = 0; s < 2; s++) {
                {
                    float c0 = 0.f, c1 = 0.f, c2 = 0.f, c3 = 0.f;
                    MMA16816(c0, c1, c2, c3, akh[s][0], akh[s][1], akh[s][2], akh[s][3], bh0, bh1);
                    MMA16816(c0, c1, c2, c3, akh[s][0], akh[s][1], akh[s][2], akh[s][3], bl0, bl1);
                    MMA16816(c0, c1, c2, c3, akl[s][0], akl[s][1], akl[s][2], akl[s][3], bh0, bh1);
                    z[s][0] += EX2(c0) + EX2(c1);
                    z[s][1] += EX2(c2) + EX2(c3);
                }
                {
                    float c0 = 0.f, c1 = 0.f, c2 = 0.f, c3 = 0.f;
                    MMA16816(c0, c1, c2, c3, akh[s][0], akh[s][1], akh[s][2], akh[s][3], bh2, bh3);
                    MMA16816(c0, c1, c2, c3, akh[s][0], akh[s][1], akh[s][2], akh[s][3], bl2, bl3);
                    MMA16816(c0, c1, c2, c3, akl[s][0], akl[s][1], akl[s][2], akl[s][3], bh2, bh3);
                    z[s][0] += EX2(c0) + EX2(c1);
                    z[s][1] += EX2(c2) + EX2(c3);
                }
            }
        }
        // stage tile qt+2
        if (qt + 2 < 16) {
            int nb = (qt + 2) % 3;
            uint32_t d = smem_u32(&sQ[nb][arrq][0]);
            #pragma unroll
            for (int j = 0; j < 4; j++) {
                int o = (tid & 63) * 4 + j;
                cp16(d + o * 16, gq + (qt + 2) * 128 * DD + o * 8);
            }
            CP_COMMIT();
        }
    }

    // quad reduce across the 4 threads sharing each row -> sZ
    #pragma unroll
    for (int s = 0; s < 2; s++)
        #pragma unroll
        for (int j = 0; j < 2; j++) {
            z[s][j] += __shfl_xor_sync(0xffffffffu, z[s][j], 1);
            z[s][j] += __shfl_xor_sync(0xffffffffu, z[s][j], 2);
        }
    if ((lane & 3) == 0) {
        int r = lane >> 2;
        #pragma unroll
        for (int s = 0; s < 2; s++) {
            sZ[warp * 32 + s * 16 + r]     = z[s][0];
            sZ[warp * 32 + s * 16 + r + 8] = z[s][1];
        }
    }
    __syncthreads();

    // fused fold: thread owns one k row; W[k,:] = V[k,:]/Z[k], split hi/lo
    {
        int id = p * TT + kbase + tid;
        float inv = 1.0f / sZ[tid];
        const float4* v4 = reinterpret_cast<const float4*>(&g_V[id * DD]);
        __half2* dh = reinterpret_cast<__half2*>(&g_Wh[id * DD]);
        __half2* dl = reinterpret_cast<__half2*>(&g_Wl[id * DD]);
        #pragma unroll
        for (int i = 0; i < 4; i++) {
            float4 x = v4[i];
            float w0 = x.x * inv, w1 = x.y * inv, w2 = x.z * inv, w3 = x.w * inv;
            __half2 h01 = __float22half2_rn(make_float2(w0, w1));
            __half2 h23 = __float22half2_rn(make_float2(w2, w3));
            float2 b01 = __half22float2(h01);
            float2 b23 = __half22float2(h23);
            dh[2 * i]     = h01;
            dh[2 * i + 1] = h23;
            dl[2 * i]     = __float22half2_rn(make_float2(w0 - b01.x, w1 - b01.y));
            dl[2 * i + 1] = __float22half2_rn(make_float2(w2 - b23.x, w3 - b23.y));
        }
    }
}

// ---------------------------------------------------------------------------
// K4 (pass B): out[q,:] = sum_k exp2(s) * W[k,:]  (W pre-folded with 1/Z).
// 64-k chunks, 3-deep cp.async pipeline, one sync per 64 k.
// P kept hi-only (error ~2^-12, random-walks out); W still split hi/lo.
// grid = (TT/64, NP), block = 128 (4 warps, warp owns 16 q rows).
__global__ void __launch_bounds__(128) k_out()
{
    __shared__ __align__(16) __half sQh[64 * 16], sQl[64 * 16];
    __shared__ __align__(16) __half sB[3][4][64 * 16];   // [buf][Kh,Kl,Wh,Wl]

    int tid = threadIdx.x, lane = tid & 31, warp = tid >> 5;
    int p = blockIdx.y, qbase = blockIdx.x * 64;
    int n = p >> 2, h = p & 3;

    // stage this block's 64 Q rows (hi+lo)
    {
        int arr = tid >> 6, row = tid & 63;
        const uint4* src = reinterpret_cast<const uint4*>(
            (arr ? g_Ql : g_Qh) + (p * TT + qbase + row) * DD);
        uint4* dst = reinterpret_cast<uint4*>((arr ? sQl : sQh) + row * 16);
        dst[0] = src[0]; dst[1] = src[1];
    }

    // B-chunk staging role: 4 arrays x (64 rows x 2 halves = 128 slots); 4/thread
    int sarr = tid >> 5;
    const __half* gsrc = (sarr == 0) ? g_Kh : (sarr == 1) ? g_Kl
                        : (sarr == 2) ? g_Wh : g_Wl;
    const __half* gsb = gsrc + p * TT * DD;
    uint32_t soff = smem_u32(&sB[0][sarr][0]) - smem_u32(&sB[0][0][0]);
    uint32_t sb_base = smem_u32(&sB[0][0][0]);
    const uint32_t BUFB = 4 * 64 * 16 * 2;   // bytes per buffer

    // prologue: stage chunks 0, 1
    #pragma unroll
    for (int c0 = 0; c0 < 2; c0++) {
        uint32_t d = sb_base + c0 * BUFB + soff;
        #pragma unroll
        for (int j = 0; j < 4; j++) {
            int o = (tid & 31) * 4 + j;          // 16B slot (128 per array)
            cp16(d + o * 16, gsb + c0 * 64 * DD + o * 8);
        }
        CP_COMMIT();
    }

    __syncthreads();   // Q tile visible

    // A frags: Q rows (m16 x k16), hi and lo
    int g = lane >> 3;
    uint32_t aqh0, aqh1, aqh2, aqh3, aql0, aql1, aql2, aql3;
    {
        int row = warp * 16 + (g & 1) * 8 + (lane & 7);
        int col = (g >> 1) * 8;
        LDSM_X4(aqh0, aqh1, aqh2, aqh3, smem_u32(&sQh[row * 16 + col]));
        LDSM_X4(aql0, aql1, aql2, aql3, smem_u32(&sQl[row * 16 + col]));
    }

    float oc0[4] = {0.f, 0.f, 0.f, 0.f};   // d 0-7
    float oc1[4] = {0.f, 0.f, 0.f, 0.f};   // d 8-15

    uint32_t koff = ((g >> 1) * 8 + (lane & 7)) * 32 + (g & 1) * 16;        // K b-frag byte off
    uint32_t woff = 2 * 64 * 16 * 2 + ((g & 1) * 8 + (lane & 7)) * 32 + (g >> 1) * 16; // Wh base

    for (int kc = 0; kc < 32; kc++) {
        if (kc < 31) { CP_WAIT(1); } else { CP_WAIT(0); }
        __syncthreads();
        uint32_t bufb = sb_base + (kc % 3) * BUFB;
        uint32_t kaddr = bufb + koff;
        uint32_t waddr = bufb + woff;
        #pragma unroll
        for (int sub = 0; sub < 4; sub++) {
            // --- S tiles + exp2 -> P frags (hi only) ---
            uint32_t kh0, kh1, kh2, kh3, kl0, kl1, kl2, kl3;
            LDSM_X4(kh0, kh1, kh2, kh3, kaddr + sub * 512);
            LDSM_X4(kl0, kl1, kl2, kl3, kaddr + 2048 + sub * 512);
            uint32_t pah[4];
            {
                float c0 = 0.f, c1 = 0.f, c2 = 0.f, c3 = 0.f;
                MMA16816(c0, c1, c2, c3, aqh0, aqh1, aqh2, aqh3, kh0, kh1);
                MMA16816(c0, c1, c2, c3, aqh0, aqh1, aqh2, aqh3, kl0, kl1);
                MMA16816(c0, c1, c2, c3, aql0, aql1, aql2, aql3, kh0, kh1);
                pah[0] = h2u(__float22half2_rn(make_float2(EX2(c0), EX2(c1))));
                pah[1] = h2u(__float22half2_rn(make_float2(EX2(c2), EX2(c3))));
            }
            {
                float c0 = 0.f, c1 = 0.f, c2 = 0.f, c3 = 0.f;
                MMA16816(c0, c1, c2, c3, aqh0, aqh1, aqh2, aqh3, kh2, kh3);
                MMA16816(c0, c1, c2, c3, aqh0, aqh1, aqh2, aqh3, kl2, kl3);
                MMA16816(c0, c1, c2, c3, aql0, aql1, aql2, aql3, kh2, kh3);
                pah[2] = h2u(__float22half2_rn(make_float2(EX2(c0), EX2(c1))));
                pah[3] = h2u(__float22half2_rn(make_float2(EX2(c2), EX2(c3))));
            }

            // --- W b-frags (hi, lo) ---
            uint32_t wh0, wh1, wh2, wh3, wl0, wl1, wl2, wl3;
            LDSM_X4T(wh0, wh1, wh2, wh3, waddr + sub * 512);
            LDSM_X4T(wl0, wl1, wl2, wl3, waddr + 2048 + sub * 512);

            // --- PV: out += P * (Wh + Wl) ---
            MMA16816(oc0[0], oc0[1], oc0[2], oc0[3], pah[0], pah[1], pah[2], pah[3], wh0, wh1);
            MMA16816(oc0[0], oc0[1], oc0[2], oc0[3], pah[0], pah[1], pah[2], pah[3], wl0, wl1);
            MMA16816(oc1[0], oc1[1], oc1[2], oc1[3], pah[0], pah[1], pah[2], pah[3], wh2, wh3);
            MMA16816(oc1[0], oc1[1], oc1[2], oc1[3], pah[0], pah[1], pah[2], pah[3], wl2, wl3);
        }
        // stage chunk kc+2
        if (kc + 2 < 32) {
            uint32_t d = sb_base + ((kc + 2) % 3) * BUFB + soff;
            #pragma unroll
            for (int j = 0; j < 4; j++) {
                int o = (tid & 31) * 4 + j;
                cp16(d + o * 16, gsb + (kc + 2) * 64 * DD + o * 8);
            }
            CP_COMMIT();
        }
    }

    // epilogue: write fp16 hi/lo fragments to g_Oh / g_Ol
    {
        int r = lane >> 2, c2 = lane & 3;
        int q0 = qbase + warp * 16 + r;
        int b0i = (n * TT + q0) * EE + h * DD;
        int b8i = (n * TT + q0 + 8) * EE + h * DD;
        int idxs[4] = { b0i + 2 * c2, b8i + 2 * c2, b0i + 8 + 2 * c2, b8i + 8 + 2 * c2 };
        float vals[4][2] = { {oc0[0], oc0[1]}, {oc0[2], oc0[3]},
                             {oc1[0], oc1[1]}, {oc1[2], oc1[3]} };
        #pragma unroll
        for (int i = 0; i < 4; i++) {
            __half2 hi = __float22half2_rn(make_float2(vals[i][0], vals[i][1]));
            float2 bb = __half22float2(hi);
            __half2 lo = __float22half2_rn(make_float2(vals[i][0] - bb.x, vals[i][1] - bb.y));
            *reinterpret_cast<__half2*>(&g_Oh[idxs[i]]) = hi;
            *reinterpret_cast<__half2*>(&g_Ol[idxs[i]]) = lo;
        }
    }
}

// ---------------------------------------------------------------------------
// K5a: split Wfc into fp16 hi/lo (one-time, tiny).
__global__ void k_wsplit(const float* __restrict__ Wfc)
{
    int i = blockIdx.x * blockDim.x + threadIdx.x;   // 0..4095
    float w = Wfc[i];
    __half hi = __float2half_rn(w);
    g_Wfh[i] = hi;
    g_Wfl[i] = __float2half_rn(w - __half2float(hi));
}

// ---------------------------------------------------------------------------
// K5b: final FC via fp16-split HMMA: y = O @ Wfc + bfc.
// grid = 256 blocks x 128 rows; block = 256 (8 warps, warp owns 16 rows).
__global__ void __launch_bounds__(256) k_fc_mma(const float* __restrict__ bfc,
                                               float* __restrict__ out)
{
    __shared__ __align__(16) __half sXh[128 * 64], sXl[128 * 64];
    __shared__ __align__(16) __half sWh[64 * 64],  sWl[64 * 64];
    __shared__ float sb[64];

    int tid = threadIdx.x, lane = tid & 31, warp = tid >> 5;
    int rowbase = blockIdx.x * 128;

    // stage X (128x64 hi/lo): 1024 uint4 per array, 4 per thread
    {
        const uint4* srch = reinterpret_cast<const uint4*>(g_Oh + rowbase * EE);
        const uint4* srcl = reinterpret_cast<const uint4*>(g_Ol + rowbase * EE);
        uint4* dh = reinterpret_cast<uint4*>(sXh);
        uint4* dl = reinterpret_cast<uint4*>(sXl);
        #pragma unroll
        for (int j = 0; j < 4; j++) {
            dh[tid + j * 256] = srch[tid + j * 256];
            dl[tid + j * 256] = srcl[tid + j * 256];
        }
    }
    // stage W (64x64 hi/lo): 512 uint4 per array, 2 per thread
    {
        const uint4* srch = reinterpret_cast<const uint4*>(g_Wfh);
        const uint4* srcl = reinterpret_cast<const uint4*>(g_Wfl);
        uint4* dh = reinterpret_cast<uint4*>(sWh);
        uint4* dl = reinterpret_cast<uint4*>(sWl);
        dh[tid] = srch[tid]; dh[tid + 256] = srch[tid + 256];
        dl[tid] = srcl[tid]; dl[tid + 256] = srcl[tid + 256];
    }
    if (tid < 64) sb[tid] = bfc[tid];
    __syncthreads();

    int g = lane >> 3;
    // A frags: warp's 16 rows x 4 k-tiles (hi, lo)
    uint32_t axh[4][4], axl[4][4];
    #pragma unroll
    for (int kt = 0; kt < 4; kt++) {
        int row = warp * 16 + (g & 1) * 8 + (lane & 7);
        int col = kt * 16 + (g >> 1) * 8;
        LDSM_X4(axh[kt][0], axh[kt][1], axh[kt][2], axh[kt][3], smem_u32(&sXh[row * 64 + col]));
        LDSM_X4(axl[kt][0], axl[kt][1], axl[kt][2], axl[kt][3], smem_u32(&sXl[row * 64 + col]));
    }

    float c[8][4];
    #pragma unroll
    for (int i = 0; i < 8; i++)
        #pragma unroll
        for (int j = 0; j < 4; j++) c[i][j] = 0.f;

    #pragma unroll
    for (int nt2 = 0; nt2 < 4; nt2++) {
        #pragma unroll
        for (int kt = 0; kt < 4; kt++) {
            int brow = kt * 16 + (g & 1) * 8 + (lane & 7);
            int bcol = nt2 * 16 + (g >> 1) * 8;
            uint32_t bh0, bh1, bh2, bh3, bl0, bl1, bl2, bl3;
            LDSM_X4T(bh0, bh1, bh2, bh3, smem_u32(&sWh[brow * 64 + bcol]));
            LDSM_X4T(bl0, bl1, bl2, bl3, smem_u32(&sWl[brow * 64 + bcol]));
            MMA16816(c[nt2*2][0], c[nt2*2][1], c[nt2*2][2], c[nt2*2][3],
                     axh[kt][0], axh[kt][1], axh[kt][2], axh[kt][3], bh0, bh1);
            MMA16816(c[nt2*2][0], c[nt2*2][1], c[nt2*2][2], c[nt2*2][3],
                     axh[kt][0], axh[kt][1], axh[kt][2], axh[kt][3], bl0, bl1);
            MMA16816(c[nt2*2][0], c[nt2*2][1], c[nt2*2][2], c[nt2*2][3],
                     axl[kt][0], axl[kt][1], axl[kt][2], axl[kt][3], bh0, bh1);
            MMA16816(c[nt2*2+1][0], c[nt2*2+1][1], c[nt2*2+1][2], c[nt2*2+1][3],
                     axh[kt][0], axh[kt][1], axh[kt][2], axh[kt][3], bh2, bh3);
            MMA16816(c[nt2*2+1][0], c[nt2*2+1][1], c[nt2*2+1][2], c[nt2*2+1][3],
                     axh[kt][0], axh[kt][1], axh[kt][2], axh[kt][3], bl2, bl3);
            MMA16816(c[nt2*2+1][0], c[nt2*2+1][1], c[nt2*2+1][2], c[nt2*2+1][3],
                     axl[kt][0], axl[kt][1], axl[kt][2], axl[kt][3], bh2, bh3);
        }
    }

    // epilogue: add bias, store fp32
    int r = lane >> 2, j = lane & 3;
    int row0 = rowbase + warp * 16 + r;
    #pragma unroll
    for (int nt = 0; nt < 8; nt++) {
        int ncol = nt * 8 + 2 * j;
        float b0 = sb[ncol], b1 = sb[ncol + 1];
        *reinterpret_cast<float2*>(&out[row0 * 64 + ncol]) =
            make_float2(c[nt][0] + b0, c[nt][1] + b1);
        *reinterpret_cast<float2*>(&out[(row0 + 8) * 64 + ncol]) =
            make_float2(c[nt][2] + b0, c[nt][3] + b1);
    }
}

// ---------------------------------------------------------------------------
// Input order: 0:value 1:key 2:query 3:Wq 4:bq 5:Wk 6:bk 7:Wv 8:bv 9:Wfc 10:bfc
extern "C" void kernel_launch(void* const* d_in, const int* in_sizes, int n_in,
                              void* d_out, int out_size)
{
    const float* value = (const float*)d_in[0];
    const float* key_  = (const float*)d_in[1];
    const float* query = (const float*)d_in[2];
    const float* Wq    = (const float*)d_in[3];
    const float* bq    = (const float*)d_in[4];
    const float* Wk    = (const float*)d_in[5];
    const float* bk    = (const float*)d_in[6];
    const float* Wv    = (const float*)d_in[7];
    const float* bv    = (const float*)d_in[8];
    const float* Wfc   = (const float*)d_in[9];
    const float* bfc   = (const float*)d_in[10];
    float* out = (float*)d_out;

    k_wsplit<<<16, 256>>>(Wfc);
    k_proj<<<(NP * TT) / 256, 256>>>(value, key_, query, Wq, bq, Wk, bk, Wv, bv);
    k_zsum<<<dim3(TT / 128, NP), 128>>>();
    k_out<<<dim3(TT / 64, NP), 128>>>();
    k_fc_mma<<<(NN * TT) / 128, 256>>>(bfc, out);
}

// round 9
// speedup vs baseline: 4.5111x; 1.2052x over previous
#include <cuda_runtime.h>
#include <cuda_fp16.h>
#include <cstdint>

// Problem constants: B=1, N=16, T=2048, E=64, H=4, D=16
#define NN   16
#define TT   2048
#define EE   64
#define HH   4
#define DD   16
#define NP   (NN*HH)          // 64 (n,h) pairs
// Q pre-scaled by log2(e)/8 so scores are in log2 domain -> ex2.approx (1 MUFU)
#define QSCALE2 0.180336880740290f

// ---------------------------------------------------------------------------
// Scratch (static device arrays; allocation-free per harness rules)
__device__ __align__(16) __half g_Qh[NP * TT * DD];  // q*log2e/8 hi
__device__ __align__(16) __half g_Ql[NP * TT * DD];  // q*log2e/8 lo
__device__ __align__(16) __half g_Kh[NP * TT * DD];
__device__ __align__(16) __half g_Kl[NP * TT * DD];
__device__ __align__(16) float  g_V [NP * TT * DD];  // projected v (fp32)
__device__ __align__(16) __half g_Wh[NP * TT * DD];  // (v/Z) hi
__device__ __align__(16) __half g_Wl[NP * TT * DD];  // (v/Z) lo
__device__ __align__(16) __half g_Oh[NN * TT * EE];  // attention out hi
__device__ __align__(16) __half g_Ol[NN * TT * EE];  // attention out lo
__device__ __align__(16) __half g_Wfh[EE * EE];      // Wfc hi
__device__ __align__(16) __half g_Wfl[EE * EE];      // Wfc lo

// ---------------------------------------------------------------------------
__device__ __forceinline__ float EX2(float x) {
    float r;
    asm("ex2.approx.ftz.f32 %0, %1;" : "=f"(r) : "f"(x));
    return r;
}
__device__ __forceinline__ uint32_t smem_u32(const void* p) {
    return (uint32_t)__cvta_generic_to_shared(p);
}
__device__ __forceinline__ void cp16(uint32_t dst, const void* src) {
    asm volatile("cp.async.cg.shared.global [%0], [%1], 16;" :: "r"(dst), "l"(src));
}
#define CP_COMMIT() asm volatile("cp.async.commit_group;")
#define CP_WAIT(n)  asm volatile("cp.async.wait_group %0;" :: "n"(n))

#define LDSM_X4(r0,r1,r2,r3,addr) \
    asm volatile("ldmatrix.sync.aligned.m8n8.x4.shared.b16 {%0,%1,%2,%3}, [%4];" \
        : "=r"(r0),"=r"(r1),"=r"(r2),"=r"(r3) : "r"(addr))
#define LDSM_X4T(r0,r1,r2,r3,addr) \
    asm volatile("ldmatrix.sync.aligned.m8n8.x4.trans.shared.b16 {%0,%1,%2,%3}, [%4];" \
        : "=r"(r0),"=r"(r1),"=r"(r2),"=r"(r3) : "r"(addr))
#define MMA16816(c0,c1,c2,c3,a0,a1,a2,a3,b0,b1) \
    asm volatile("mma.sync.aligned.m16n8k16.row.col.f32.f16.f16.f32 " \
        "{%0,%1,%2,%3},{%4,%5,%6,%7},{%8,%9},{%0,%1,%2,%3};" \
        : "+f"(c0),"+f"(c1),"+f"(c2),"+f"(c3) \
        : "r"(a0),"r"(a1),"r"(a2),"r"(a3),"r"(b0),"r"(b1))

__device__ __forceinline__ uint32_t h2u(__half2 h) {
    return reinterpret_cast<uint32_t&>(h);
}

// ---------------------------------------------------------------------------
// K1: head projections -> split fp16 Q (log2e-scaled), K, and fp32 V.
__global__ void k_proj(const float* __restrict__ value,
                       const float* __restrict__ key,
                       const float* __restrict__ query,
                       const float* __restrict__ Wq, const float* __restrict__ bq,
                       const float* __restrict__ Wk, const float* __restrict__ bk,
                       const float* __restrict__ Wv, const float* __restrict__ bv)
{
    __shared__ float sWq[256], sWk[256], sWv[256];
    __shared__ float sbq[16], sbk[16], sbv[16];
    int tid = threadIdx.x;
    if (tid < 256) { sWq[tid] = Wq[tid]; sWk[tid] = Wk[tid]; sWv[tid] = Wv[tid]; }
    if (tid < 16)  { sbq[tid] = bq[tid]; sbk[tid] = bk[tid]; sbv[tid] = bv[tid]; }
    __syncthreads();

    int id = blockIdx.x * blockDim.x + tid;
    int t  = id & (TT - 1);
    int p  = id >> 11;
    int n  = p >> 2;
    int h  = p & 3;
    int in_base  = (n * TT + t) * EE + h * DD;
    int out_base = (p * TT + t) * DD;

    float x[16];
    // ---- q (scaled by log2e/8), split hi/lo ----
    #pragma unroll
    for (int i = 0; i < 16; i++) x[i] = query[in_base + i];
    {
        __half hh[16], hl[16];
        #pragma unroll
        for (int j = 0; j < 16; j++) {
            float acc = sbq[j];
            #pragma unroll
            for (int i = 0; i < 16; i++) acc = fmaf(x[i], sWq[i * 16 + j], acc);
            acc *= QSCALE2;
            __half hi = __float2half_rn(acc);
            hh[j] = hi;
            hl[j] = __float2half_rn(acc - __half2float(hi));
        }
        __half2* dh = reinterpret_cast<__half2*>(&g_Qh[out_base]);
        __half2* dl = reinterpret_cast<__half2*>(&g_Ql[out_base]);
        #pragma unroll
        for (int j = 0; j < 8; j++) {
            dh[j] = __halves2half2(hh[2 * j], hh[2 * j + 1]);
            dl[j] = __halves2half2(hl[2 * j], hl[2 * j + 1]);
        }
    }
    // ---- k, split hi/lo ----
    #pragma unroll
    for (int i = 0; i < 16; i++) x[i] = key[in_base + i];
    {
        __half hh[16], hl[16];
        #pragma unroll
        for (int j = 0; j < 16; j++) {
            float acc = sbk[j];
            #pragma unroll
            for (int i = 0; i < 16; i++) acc = fmaf(x[i], sWk[i * 16 + j], acc);
            __half hi = __float2half_rn(acc);
            hh[j] = hi;
            hl[j] = __float2half_rn(acc - __half2float(hi));
        }
        __half2* dh = reinterpret_cast<__half2*>(&g_Kh[out_base]);
        __half2* dl = reinterpret_cast<__half2*>(&g_Kl[out_base]);
        #pragma unroll
        for (int j = 0; j < 8; j++) {
            dh[j] = __halves2half2(hh[2 * j], hh[2 * j + 1]);
            dl[j] = __halves2half2(hl[2 * j], hl[2 * j + 1]);
        }
    }
    // ---- v (fp32) ----
    #pragma unroll
    for (int i = 0; i < 16; i++) x[i] = value[in_base + i];
    #pragma unroll
    for (int j = 0; j < 16; j++) {
        float acc = sbv[j];
        #pragma unroll
        for (int i = 0; i < 16; i++) acc = fmaf(x[i], sWv[i * 16 + j], acc);
        g_V[out_base + j] = acc;
    }
}

// ---------------------------------------------------------------------------
// K2 (pass A): Z[k] = sum_q exp2(q.k*log2e/8), then fold 1/Z into V in-place.
// Warp owns 32 k-rows (2 A-frag sets), streams Q in 128-row tiles.
// grid = (TT/128, NP), block = 128.
__global__ void __launch_bounds__(128) k_zsum()
{
    __shared__ __align__(16) __half sKh[128 * 16], sKl[128 * 16];
    __shared__ __align__(16) __half sQ[3][2][128 * 16];   // [buf][hi/lo]
    __shared__ float sZ[128];

    int tid = threadIdx.x, lane = tid & 31, warp = tid >> 5;
    int p = blockIdx.y, kbase = blockIdx.x * 128;

    // stage this block's 128 K rows (hi+lo): 256 uint4 per array, 64 thr each
    {
        int arr = tid >> 6;
        const uint4* src = reinterpret_cast<const uint4*>(
            (arr ? g_Kl : g_Kh) + (p * TT + kbase) * DD);
        uint4* dst = reinterpret_cast<uint4*>(arr ? sKl : sKh);
        #pragma unroll
        for (int j = 0; j < 4; j++) dst[(tid & 63) * 4 + j] = src[(tid & 63) * 4 + j];
    }

    int arrq = tid >> 6;
    const __half* gq = (arrq ? g_Ql : g_Qh) + p * TT * DD;
    // prologue: stage Q tiles 0, 1
    #pragma unroll
    for (int qt0 = 0; qt0 < 2; qt0++) {
        uint32_t d = smem_u32(&sQ[qt0][arrq][0]);
        #pragma unroll
        for (int j = 0; j < 4; j++) {
            int o = (tid & 63) * 4 + j;          // uint4 slot (256 per array)
            cp16(d + o * 16, gq + qt0 * 128 * DD + o * 8);
        }
        CP_COMMIT();
    }

    __syncthreads();   // K tiles visible

    // A frags: 2 sets of 16 K rows (hi and lo)
    int g = lane >> 3;
    uint32_t akh[2][4], akl[2][4];
    #pragma unroll
    for (int s = 0; s < 2; s++) {
        int row = warp * 32 + s * 16 + (g & 1) * 8 + (lane & 7);
        int col = (g >> 1) * 8;
        LDSM_X4(akh[s][0], akh[s][1], akh[s][2], akh[s][3], smem_u32(&sKh[row * 16 + col]));
        LDSM_X4(akl[s][0], akl[s][1], akl[s][2], akl[s][3], smem_u32(&sKl[row * 16 + col]));
    }

    float z[2][2] = {{0.f, 0.f}, {0.f, 0.f}};
    int browq = (g >> 1) * 8 + (lane & 7);   // b-frag q-row within 16-chunk
    int bcol  = (g & 1) * 8;

    for (int qt = 0; qt < 16; qt++) {
        if (qt < 15) { CP_WAIT(1); } else { CP_WAIT(0); }
        __syncthreads();
        int buf = qt % 3;
        uint32_t qbh = smem_u32(&sQ[buf][0][browq * 16 + bcol]);
        uint32_t qbl = smem_u32(&sQ[buf][1][browq * 16 + bcol]);
        #pragma unroll
        for (int sub = 0; sub < 8; sub++) {
            uint32_t bh0, bh1, bh2, bh3, bl0, bl1, bl2, bl3;
            LDSM_X4(bh0, bh1, bh2, bh3, qbh + sub * 512);
            LDSM_X4(bl0, bl1, bl2, bl3, qbl + sub * 512);
            #pragma unroll
            for (int s = 0; s < 2; s++) {
                {
                    float c0 = 0.f, c1 = 0.f, c2 = 0.f, c3 = 0.f;
                    MMA16816(c0, c1, c2, c3, akh[s][0], akh[s][1], akh[s][2], akh[s][3], bh0, bh1);
                    MMA16816(c0, c1, c2, c3, akh[s][0], akh[s][1], akh[s][2], akh[s][3], bl0, bl1);
                    MMA16816(c0, c1, c2, c3, akl[s][0], akl[s][1], akl[s][2], akl[s][3], bh0, bh1);
                    z[s][0] += EX2(c0) + EX2(c1);
                    z[s][1] += EX2(c2) + EX2(c3);
                }
                {
                    float c0 = 0.f, c1 = 0.f, c2 = 0.f, c3 = 0.f;
                    MMA16816(c0, c1, c2, c3, akh[s][0], akh[s][1], akh[s][2], akh[s][3], bh2, bh3);
                    MMA16816(c0, c1, c2, c3, akh[s][0], akh[s][1], akh[s][2], akh[s][3], bl2, bl3);
                    MMA16816(c0, c1, c2, c3, akl[s][0], akl[s][1], akl[s][2], akl[s][3], bh2, bh3);
                    z[s][0] += EX2(c0) + EX2(c1);
                    z[s][1] += EX2(c2) + EX2(c3);
                }
            }
        }
        // stage tile qt+2
        if (qt + 2 < 16) {
            int nb = (qt + 2) % 3;
            uint32_t d = smem_u32(&sQ[nb][arrq][0]);
            #pragma unroll
            for (int j = 0; j < 4; j++) {
                int o = (tid & 63) * 4 + j;
                cp16(d + o * 16, gq + (qt + 2) * 128 * DD + o * 8);
            }
            CP_COMMIT();
        }
    }

    // quad reduce across the 4 threads sharing each row -> sZ
    #pragma unroll
    for (int s = 0; s < 2; s++)
        #pragma unroll
        for (int j = 0; j < 2; j++) {
            z[s][j] += __shfl_xor_sync(0xffffffffu, z[s][j], 1);
            z[s][j] += __shfl_xor_sync(0xffffffffu, z[s][j], 2);
        }
    if ((lane & 3) == 0) {
        int r = lane >> 2;
        #pragma unroll
        for (int s = 0; s < 2; s++) {
            sZ[warp * 32 + s * 16 + r]     = z[s][0];
            sZ[warp * 32 + s * 16 + r + 8] = z[s][1];
        }
    }
    __syncthreads();

    // fused fold: thread owns one k row; W[k,:] = V[k,:]/Z[k], split hi/lo
    {
        int id = p * TT + kbase + tid;
        float inv = 1.0f / sZ[tid];
        const float4* v4 = reinterpret_cast<const float4*>(&g_V[id * DD]);
        __half2* dh = reinterpret_cast<__half2*>(&g_Wh[id * DD]);
        __half2* dl = reinterpret_cast<__half2*>(&g_Wl[id * DD]);
        #pragma unroll
        for (int i = 0; i < 4; i++) {
            float4 x = v4[i];
            float w0 = x.x * inv, w1 = x.y * inv, w2 = x.z * inv, w3 = x.w * inv;
            __half2 h01 = __float22half2_rn(make_float2(w0, w1));
            __half2 h23 = __float22half2_rn(make_float2(w2, w3));
            float2 b01 = __half22float2(h01);
            float2 b23 = __half22float2(h23);
            dh[2 * i]     = h01;
            dh[2 * i + 1] = h23;
            dl[2 * i]     = __float22half2_rn(make_float2(w0 - b01.x, w1 - b01.y));
            dl[2 * i + 1] = __float22half2_rn(make_float2(w2 - b23.x, w3 - b23.y));
        }
    }
}

// ---------------------------------------------------------------------------
// K4 (pass B): out[q,:] = sum_k exp2(s) * W[k,:]  (W pre-folded with 1/Z).
// Warp owns 32 q rows (2 A-frag sets) -> each K/W b-frag LDSM feeds 2x MMAs,
// halving smem traffic (L1 was the binding pipe at 83.9%).
// 64-k chunks, 3-deep cp.async pipeline, one sync per 64 k.
// grid = (TT/128, NP), block = 128 (4 warps x 32 q rows = 128 q rows).
__global__ void __launch_bounds__(128) k_out()
{
    __shared__ __align__(16) __half sQh[128 * 16], sQl[128 * 16];
    __shared__ __align__(16) __half sB[3][4][64 * 16];   // [buf][Kh,Kl,Wh,Wl]

    int tid = threadIdx.x, lane = tid & 31, warp = tid >> 5;
    int p = blockIdx.y, qbase = blockIdx.x * 128;
    int n = p >> 2, h = p & 3;

    // stage this block's 128 Q rows (hi+lo): 256 uint4 per array, 64 thr each
    {
        int arr = tid >> 6;
        const uint4* src = reinterpret_cast<const uint4*>(
            (arr ? g_Ql : g_Qh) + (p * TT + qbase) * DD);
        uint4* dst = reinterpret_cast<uint4*>(arr ? sQl : sQh);
        #pragma unroll
        for (int j = 0; j < 4; j++) dst[(tid & 63) * 4 + j] = src[(tid & 63) * 4 + j];
    }

    // B-chunk staging role: 4 arrays x (64 rows x 2 halves = 128 slots); 4/thread
    int sarr = tid >> 5;
    const __half* gsrc = (sarr == 0) ? g_Kh : (sarr == 1) ? g_Kl
                        : (sarr == 2) ? g_Wh : g_Wl;
    const __half* gsb = gsrc + p * TT * DD;
    uint32_t soff = smem_u32(&sB[0][sarr][0]) - smem_u32(&sB[0][0][0]);
    uint32_t sb_base = smem_u32(&sB[0][0][0]);
    const uint32_t BUFB = 4 * 64 * 16 * 2;   // bytes per buffer

    // prologue: stage chunks 0, 1
    #pragma unroll
    for (int c0 = 0; c0 < 2; c0++) {
        uint32_t d = sb_base + c0 * BUFB + soff;
        #pragma unroll
        for (int j = 0; j < 4; j++) {
            int o = (tid & 31) * 4 + j;          // 16B slot (128 per array)
            cp16(d + o * 16, gsb + c0 * 64 * DD + o * 8);
        }
        CP_COMMIT();
    }

    __syncthreads();   // Q tile visible

    // A frags: 2 sets of 16 Q rows (hi and lo)
    int g = lane >> 3;
    uint32_t aqh[2][4], aql[2][4];
    #pragma unroll
    for (int s = 0; s < 2; s++) {
        int row = warp * 32 + s * 16 + (g & 1) * 8 + (lane & 7);
        int col = (g >> 1) * 8;
        LDSM_X4(aqh[s][0], aqh[s][1], aqh[s][2], aqh[s][3], smem_u32(&sQh[row * 16 + col]));
        LDSM_X4(aql[s][0], aql[s][1], aql[s][2], aql[s][3], smem_u32(&sQl[row * 16 + col]));
    }

    float oc[2][2][4];   // [set][d-half][frag]
    #pragma unroll
    for (int s = 0; s < 2; s++)
        #pragma unroll
        for (int dh2 = 0; dh2 < 2; dh2++)
            #pragma unroll
            for (int j = 0; j < 4; j++) oc[s][dh2][j] = 0.f;

    uint32_t koff = ((g >> 1) * 8 + (lane & 7)) * 32 + (g & 1) * 16;        // K b-frag byte off
    uint32_t woff = 2 * 64 * 16 * 2 + ((g & 1) * 8 + (lane & 7)) * 32 + (g >> 1) * 16; // Wh base

    for (int kc = 0; kc < 32; kc++) {
        if (kc < 31) { CP_WAIT(1); } else { CP_WAIT(0); }
        __syncthreads();
        uint32_t bufb = sb_base + (kc % 3) * BUFB;
        uint32_t kaddr = bufb + koff;
        uint32_t waddr = bufb + woff;
        #pragma unroll
        for (int sub = 0; sub < 4; sub++) {
            // --- K b-frags (hi, lo) and W b-frags (hi, lo) ---
            uint32_t kh0, kh1, kh2, kh3, kl0, kl1, kl2, kl3;
            LDSM_X4(kh0, kh1, kh2, kh3, kaddr + sub * 512);
            LDSM_X4(kl0, kl1, kl2, kl3, kaddr + 2048 + sub * 512);
            uint32_t wh0, wh1, wh2, wh3, wl0, wl1, wl2, wl3;
            LDSM_X4T(wh0, wh1, wh2, wh3, waddr + sub * 512);
            LDSM_X4T(wl0, wl1, wl2, wl3, waddr + 2048 + sub * 512);

            #pragma unroll
            for (int s = 0; s < 2; s++) {
                // --- S tiles + exp2 -> P frags (hi only) ---
                uint32_t pah[4];
                {
                    float c0 = 0.f, c1 = 0.f, c2 = 0.f, c3 = 0.f;
                    MMA16816(c0, c1, c2, c3, aqh[s][0], aqh[s][1], aqh[s][2], aqh[s][3], kh0, kh1);
                    MMA16816(c0, c1, c2, c3, aqh[s][0], aqh[s][1], aqh[s][2], aqh[s][3], kl0, kl1);
                    MMA16816(c0, c1, c2, c3, aql[s][0], aql[s][1], aql[s][2], aql[s][3], kh0, kh1);
                    pah[0] = h2u(__float22half2_rn(make_float2(EX2(c0), EX2(c1))));
                    pah[1] = h2u(__float22half2_rn(make_float2(EX2(c2), EX2(c3))));
                }
                {
                    float c0 = 0.f, c1 = 0.f, c2 = 0.f, c3 = 0.f;
                    MMA16816(c0, c1, c2, c3, aqh[s][0], aqh[s][1], aqh[s][2], aqh[s][3], kh2, kh3);
                    MMA16816(c0, c1, c2, c3, aqh[s][0], aqh[s][1], aqh[s][2], aqh[s][3], kl2, kl3);
                    MMA16816(c0, c1, c2, c3, aql[s][0], aql[s][1], aql[s][2], aql[s][3], kh2, kh3);
                    pah[2] = h2u(__float22half2_rn(make_float2(EX2(c0), EX2(c1))));
                    pah[3] = h2u(__float22half2_rn(make_float2(EX2(c2), EX2(c3))));
                }

                // --- PV: out += P * (Wh + Wl) ---
                MMA16816(oc[s][0][0], oc[s][0][1], oc[s][0][2], oc[s][0][3],
                         pah[0], pah[1], pah[2], pah[3], wh0, wh1);
                MMA16816(oc[s][0][0], oc[s][0][1], oc[s][0][2], oc[s][0][3],
                         pah[0], pah[1], pah[2], pah[3], wl0, wl1);
                MMA16816(oc[s][1][0], oc[s][1][1], oc[s][1][2], oc[s][1][3],
                         pah[0], pah[1], pah[2], pah[3], wh2, wh3);
                MMA16816(oc[s][1][0], oc[s][1][1], oc[s][1][2], oc[s][1][3],
                         pah[0], pah[1], pah[2], pah[3], wl2, wl3);
            }
        }
        // stage chunk kc+2
        if (kc + 2 < 32) {
            uint32_t d = sb_base + ((kc + 2) % 3) * BUFB + soff;
            #pragma unroll
            for (int j = 0; j < 4; j++) {
                int o = (tid & 31) * 4 + j;
                cp16(d + o * 16, gsb + (kc + 2) * 64 * DD + o * 8);
            }
            CP_COMMIT();
        }
    }

    // epilogue: write fp16 hi/lo fragments to g_Oh / g_Ol (both sets)
    {
        int r = lane >> 2, c2 = lane & 3;
        #pragma unroll
        for (int s = 0; s < 2; s++) {
            int q0 = qbase + warp * 32 + s * 16 + r;
            int b0i = (n * TT + q0) * EE + h * DD;
            int b8i = (n * TT + q0 + 8) * EE + h * DD;
            int idxs[4] = { b0i + 2 * c2, b8i + 2 * c2, b0i + 8 + 2 * c2, b8i + 8 + 2 * c2 };
            float vals[4][2] = { {oc[s][0][0], oc[s][0][1]}, {oc[s][0][2], oc[s][0][3]},
                                 {oc[s][1][0], oc[s][1][1]}, {oc[s][1][2], oc[s][1][3]} };
            #pragma unroll
            for (int i = 0; i < 4; i++) {
                __half2 hi = __float22half2_rn(make_float2(vals[i][0], vals[i][1]));
                float2 bb = __half22float2(hi);
                __half2 lo = __float22half2_rn(make_float2(vals[i][0] - bb.x, vals[i][1] - bb.y));
                *reinterpret_cast<__half2*>(&g_Oh[idxs[i]]) = hi;
                *reinterpret_cast<__half2*>(&g_Ol[idxs[i]]) = lo;
            }
        }
    }
}

// ---------------------------------------------------------------------------
// K5a: split Wfc into fp16 hi/lo (one-time, tiny).
__global__ void k_wsplit(const float* __restrict__ Wfc)
{
    int i = blockIdx.x * blockDim.x + threadIdx.x;   // 0..4095
    float w = Wfc[i];
    __half hi = __float2half_rn(w);
    g_Wfh[i] = hi;
    g_Wfl[i] = __float2half_rn(w - __half2float(hi));
}

// ---------------------------------------------------------------------------
// K5b: final FC via fp16-split HMMA: y = O @ Wfc + bfc.
// grid = 256 blocks x 128 rows; block = 256 (8 warps, warp owns 16 rows).
__global__ void __launch_bounds__(256) k_fc_mma(const float* __restrict__ bfc,
                                               float* __restrict__ out)
{
    __shared__ __align__(16) __half sXh[128 * 64], sXl[128 * 64];
    __shared__ __align__(16) __half sWh[64 * 64],  sWl[64 * 64];
    __shared__ float sb[64];

    int tid = threadIdx.x, lane = tid & 31, warp = tid >> 5;
    int rowbase = blockIdx.x * 128;

    // stage X (128x64 hi/lo): 1024 uint4 per array, 4 per thread
    {
        const uint4* srch = reinterpret_cast<const uint4*>(g_Oh + rowbase * EE);
        const uint4* srcl = reinterpret_cast<const uint4*>(g_Ol + rowbase * EE);
        uint4* dh = reinterpret_cast<uint4*>(sXh);
        uint4* dl = reinterpret_cast<uint4*>(sXl);
        #pragma unroll
        for (int j = 0; j < 4; j++) {
            dh[tid + j * 256] = srch[tid + j * 256];
            dl[tid + j * 256] = srcl[tid + j * 256];
        }
    }
    // stage W (64x64 hi/lo): 512 uint4 per array, 2 per thread
    {
        const uint4* srch = reinterpret_cast<const uint4*>(g_Wfh);
        const uint4* srcl = reinterpret_cast<const uint4*>(g_Wfl);
        uint4* dh = reinterpret_cast<uint4*>(sWh);
        uint4* dl = reinterpret_cast<uint4*>(sWl);
        dh[tid] = srch[tid]; dh[tid + 256] = srch[tid + 256];
        dl[tid] = srcl[tid]; dl[tid + 256] = srcl[tid + 256];
    }
    if (tid < 64) sb[tid] = bfc[tid];
    __syncthreads();

    int g = lane >> 3;
    // A frags: warp's 16 rows x 4 k-tiles (hi, lo)
    uint32_t axh[4][4], axl[4][4];
    #pragma unroll
    for (int kt = 0; kt < 4; kt++) {
        int row = warp * 16 + (g & 1) * 8 + (lane & 7);
        int col = kt * 16 + (g >> 1) * 8;
        LDSM_X4(axh[kt][0], axh[kt][1], axh[kt][2], axh[kt][3], smem_u32(&sXh[row * 64 + col]));
        LDSM_X4(axl[kt][0], axl[kt][1], axl[kt][2], axl[kt][3], smem_u32(&sXl[row * 64 + col]));
    }

    float c[8][4];
    #pragma unroll
    for (int i = 0; i < 8; i++)
        #pragma unroll
        for (int j = 0; j < 4; j++) c[i][j] = 0.f;

    #pragma unroll
    for (int nt2 = 0; nt2 < 4; nt2++) {
        #pragma unroll
        for (int kt = 0; kt < 4; kt++) {
            int brow = kt * 16 + (g & 1) * 8 + (lane & 7);
            int bcol = nt2 * 16 + (g >> 1) * 8;
            uint32_t bh0, bh1, bh2, bh3, bl0, bl1, bl2, bl3;
            LDSM_X4T(bh0, bh1, bh2, bh3, smem_u32(&sWh[brow * 64 + bcol]));
            LDSM_X4T(bl0, bl1, bl2, bl3, smem_u32(&sWl[brow * 64 + bcol]));
            MMA16816(c[nt2*2][0], c[nt2*2][1], c[nt2*2][2], c[nt2*2][3],
                     axh[kt][0], axh[kt][1], axh[kt][2], axh[kt][3], bh0, bh1);
            MMA16816(c[nt2*2][0], c[nt2*2][1], c[nt2*2][2], c[nt2*2][3],
                     axh[kt][0], axh[kt][1], axh[kt][2], axh[kt][3], bl0, bl1);
            MMA16816(c[nt2*2][0], c[nt2*2][1], c[nt2*2][2], c[nt2*2][3],
                     axl[kt][0], axl[kt][1], axl[kt][2], axl[kt][3], bh0, bh1);
            MMA16816(c[nt2*2+1][0], c[nt2*2+1][1], c[nt2*2+1][2], c[nt2*2+1][3],
                     axh[kt][0], axh[kt][1], axh[kt][2], axh[kt][3], bh2, bh3);
            MMA16816(c[nt2*2+1][0], c[nt2*2+1][1], c[nt2*2+1][2], c[nt2*2+1][3],
                     axh[kt][0], axh[kt][1], axh[kt][2], axh[kt][3], bl2, bl3);
            MMA16816(c[nt2*2+1][0], c[nt2*2+1][1], c[nt2*2+1][2], c[nt2*2+1][3],
                     axl[kt][0], axl[kt][1], axl[kt][2], axl[kt][3], bh2, bh3);
        }
    }

    // epilogue: add bias, store fp32
    int r = lane >> 2, j = lane & 3;
    int row0 = rowbase + warp * 16 + r;
    #pragma unroll
    for (int nt = 0; nt < 8; nt++) {
        int ncol = nt * 8 + 2 * j;
        float b0 = sb[ncol], b1 = sb[ncol + 1];
        *reinterpret_cast<float2*>(&out[row0 * 64 + ncol]) =
            make_float2(c[nt][0] + b0, c[nt][1] + b1);
        *reinterpret_cast<float2*>(&out[(row0 + 8) * 64 + ncol]) =
            make_float2(c[nt][2] + b0, c[nt][3] + b1);
    }
}

// ---------------------------------------------------------------------------
// Input order: 0:value 1:key 2:query 3:Wq 4:bq 5:Wk 6:bk 7:Wv 8:bv 9:Wfc 10:bfc
extern "C" void kernel_launch(void* const* d_in, const int* in_sizes, int n_in,
                              void* d_out, int out_size)
{
    const float* value = (const float*)d_in[0];
    const float* key_  = (const float*)d_in[1];
    const float* query = (const float*)d_in[2];
    const float* Wq    = (const float*)d_in[3];
    const float* bq    = (const float*)d_in[4];
    const float* Wk    = (const float*)d_in[5];
    const float* bk    = (const float*)d_in[6];
    const float* Wv    = (const float*)d_in[7];
    const float* bv    = (const float*)d_in[8];
    const float* Wfc   = (const float*)d_in[9];
    const float* bfc   = (const float*)d_in[10];
    float* out = (float*)d_out;

    k_wsplit<<<16, 256>>>(Wfc);
    k_proj<<<(NP * TT) / 256, 256>>>(value, key_, query, Wq, bq, Wk, bk, Wv, bv);
    k_zsum<<<dim3(TT / 128, NP), 128>>>();
    k_out<<<dim3(TT / 128, NP), 128>>>();
    k_fc_mma<<<(NN * TT) / 128, 256>>>(bfc, out);
}

// round 10
// speedup vs baseline: 6.0483x; 1.3408x over previous
#include <cuda_runtime.h>
#include <cuda_fp16.h>
#include <cstdint>

// Problem constants: B=1, N=16, T=2048, E=64, H=4, D=16
#define NN   16
#define TT   2048
#define EE   64
#define HH   4
#define DD   16
#define NP   (NN*HH)          // 64 (n,h) pairs
// Q pre-scaled by log2(e)/8 so scores are in log2 domain -> ex2.approx (1 MUFU)
#define QSCALE2 0.180336880740290f

// ---------------------------------------------------------------------------
// Scratch (static device arrays; allocation-free per harness rules)
__device__ __align__(16) __half g_Qh[NP * TT * DD];  // q*log2e/8 (fp16)
__device__ __align__(16) __half g_Kh[NP * TT * DD];  // k (fp16)
__device__ __align__(16) float  g_V [NP * TT * DD];  // projected v (fp32)
__device__ __align__(16) __half g_Wh[NP * TT * DD];  // (v/Z) hi
__device__ __align__(16) __half g_Wl[NP * TT * DD];  // (v/Z) lo
__device__ __align__(16) __half g_Oh[NN * TT * EE];  // attention out hi
__device__ __align__(16) __half g_Ol[NN * TT * EE];  // attention out lo
__device__ __align__(16) __half g_Wfh[EE * EE];      // Wfc hi
__device__ __align__(16) __half g_Wfl[EE * EE];      // Wfc lo

// ---------------------------------------------------------------------------
__device__ __forceinline__ float EX2(float x) {
    float r;
    asm("ex2.approx.ftz.f32 %0, %1;" : "=f"(r) : "f"(x));
    return r;
}
__device__ __forceinline__ uint32_t smem_u32(const void* p) {
    return (uint32_t)__cvta_generic_to_shared(p);
}
__device__ __forceinline__ void cp16(uint32_t dst, const void* src) {
    asm volatile("cp.async.cg.shared.global [%0], [%1], 16;" :: "r"(dst), "l"(src));
}
#define CP_COMMIT() asm volatile("cp.async.commit_group;")
#define CP_WAIT(n)  asm volatile("cp.async.wait_group %0;" :: "n"(n))

#define LDSM_X4(r0,r1,r2,r3,addr) \
    asm volatile("ldmatrix.sync.aligned.m8n8.x4.shared.b16 {%0,%1,%2,%3}, [%4];" \
        : "=r"(r0),"=r"(r1),"=r"(r2),"=r"(r3) : "r"(addr))
#define LDSM_X4T(r0,r1,r2,r3,addr) \
    asm volatile("ldmatrix.sync.aligned.m8n8.x4.trans.shared.b16 {%0,%1,%2,%3}, [%4];" \
        : "=r"(r0),"=r"(r1),"=r"(r2),"=r"(r3) : "r"(addr))
#define MMA16816(c0,c1,c2,c3,a0,a1,a2,a3,b0,b1) \
    asm volatile("mma.sync.aligned.m16n8k16.row.col.f32.f16.f16.f32 " \
        "{%0,%1,%2,%3},{%4,%5,%6,%7},{%8,%9},{%0,%1,%2,%3};" \
        : "+f"(c0),"+f"(c1),"+f"(c2),"+f"(c3) \
        : "r"(a0),"r"(a1),"r"(a2),"r"(a3),"r"(b0),"r"(b1))

__device__ __forceinline__ uint32_t h2u(__half2 h) {
    return reinterpret_cast<uint32_t&>(h);
}
__device__ __forceinline__ __half2 u2h(uint32_t u) {
    return reinterpret_cast<__half2&>(u);
}

// ---------------------------------------------------------------------------
// K1: head projections -> fp16 Q (log2e-scaled), fp16 K, fp32 V.
__global__ void k_proj(const float* __restrict__ value,
                       const float* __restrict__ key,
                       const float* __restrict__ query,
                       const float* __restrict__ Wq, const float* __restrict__ bq,
                       const float* __restrict__ Wk, const float* __restrict__ bk,
                       const float* __restrict__ Wv, const float* __restrict__ bv)
{
    __shared__ float sWq[256], sWk[256], sWv[256];
    __shared__ float sbq[16], sbk[16], sbv[16];
    int tid = threadIdx.x;
    if (tid < 256) { sWq[tid] = Wq[tid]; sWk[tid] = Wk[tid]; sWv[tid] = Wv[tid]; }
    if (tid < 16)  { sbq[tid] = bq[tid]; sbk[tid] = bk[tid]; sbv[tid] = bv[tid]; }
    __syncthreads();

    int id = blockIdx.x * blockDim.x + tid;
    int t  = id & (TT - 1);
    int p  = id >> 11;
    int n  = p >> 2;
    int h  = p & 3;
    int in_base  = (n * TT + t) * EE + h * DD;
    int out_base = (p * TT + t) * DD;

    float x[16];
    // ---- q (scaled by log2e/8) ----
    #pragma unroll
    for (int i = 0; i < 16; i++) x[i] = query[in_base + i];
    {
        float a[16];
        #pragma unroll
        for (int j = 0; j < 16; j++) {
            float acc = sbq[j];
            #pragma unroll
            for (int i = 0; i < 16; i++) acc = fmaf(x[i], sWq[i * 16 + j], acc);
            a[j] = acc * QSCALE2;
        }
        __half2* dh = reinterpret_cast<__half2*>(&g_Qh[out_base]);
        #pragma unroll
        for (int j = 0; j < 8; j++)
            dh[j] = __float22half2_rn(make_float2(a[2 * j], a[2 * j + 1]));
    }
    // ---- k ----
    #pragma unroll
    for (int i = 0; i < 16; i++) x[i] = key[in_base + i];
    {
        float a[16];
        #pragma unroll
        for (int j = 0; j < 16; j++) {
            float acc = sbk[j];
            #pragma unroll
            for (int i = 0; i < 16; i++) acc = fmaf(x[i], sWk[i * 16 + j], acc);
            a[j] = acc;
        }
        __half2* dh = reinterpret_cast<__half2*>(&g_Kh[out_base]);
        #pragma unroll
        for (int j = 0; j < 8; j++)
            dh[j] = __float22half2_rn(make_float2(a[2 * j], a[2 * j + 1]));
    }
    // ---- v (fp32) ----
    #pragma unroll
    for (int i = 0; i < 16; i++) x[i] = value[in_base + i];
    #pragma unroll
    for (int j = 0; j < 16; j++) {
        float acc = sbv[j];
        #pragma unroll
        for (int i = 0; i < 16; i++) acc = fmaf(x[i], sWv[i * 16 + j], acc);
        g_V[out_base + j] = acc;
    }
}

// ---------------------------------------------------------------------------
// K2 (pass A): Z[k] = sum_q exp2(qh.kh), then fold 1/Z into V in-place.
// S hi-only (1 MMA per n8 tile); exp via ex2.approx.f16x2 (2 exps / MUFU op;
// per-term fp16 error averages out over 2048 positive summands -> Z rel err
// ~2e-5).  Warp owns 32 k rows; Q streamed in 128-row tiles (hi only).
// grid = (TT/128, NP), block = 128.
__global__ void __launch_bounds__(128) k_zsum()
{
    __shared__ __align__(16) __half sK[128 * 16];
    __shared__ __align__(16) __half sQ[3][128 * 16];
    __shared__ float sZ[128];

    int tid = threadIdx.x, lane = tid & 31, warp = tid >> 5;
    int p = blockIdx.y, kbase = blockIdx.x * 128;

    // stage this block's 128 K rows: 256 uint4, 2 per thread
    {
        const uint4* src = reinterpret_cast<const uint4*>(g_Kh + (p * TT + kbase) * DD);
        uint4* dst = reinterpret_cast<uint4*>(sK);
        dst[tid * 2] = src[tid * 2];
        dst[tid * 2 + 1] = src[tid * 2 + 1];
    }

    const __half* gq = g_Qh + p * TT * DD;
    // prologue: stage Q tiles 0, 1 (256 uint4 each, 2 per thread)
    #pragma unroll
    for (int qt0 = 0; qt0 < 2; qt0++) {
        uint32_t d = smem_u32(&sQ[qt0][0]);
        cp16(d + (tid * 2) * 16,     gq + qt0 * 128 * DD + (tid * 2) * 8);
        cp16(d + (tid * 2 + 1) * 16, gq + qt0 * 128 * DD + (tid * 2 + 1) * 8);
        CP_COMMIT();
    }

    __syncthreads();   // K tile visible

    // A frags: 2 sets of 16 K rows
    int g = lane >> 3;
    uint32_t akh[2][4];
    #pragma unroll
    for (int s = 0; s < 2; s++) {
        int row = warp * 32 + s * 16 + (g & 1) * 8 + (lane & 7);
        int col = (g >> 1) * 8;
        LDSM_X4(akh[s][0], akh[s][1], akh[s][2], akh[s][3], smem_u32(&sK[row * 16 + col]));
    }

    float z[2][2] = {{0.f, 0.f}, {0.f, 0.f}};
    int browq = (g >> 1) * 8 + (lane & 7);
    int bcol  = (g & 1) * 8;

    for (int qt = 0; qt < 16; qt++) {
        if (qt < 15) { CP_WAIT(1); } else { CP_WAIT(0); }
        __syncthreads();
        int buf = qt % 3;
        uint32_t qb = smem_u32(&sQ[buf][browq * 16 + bcol]);
        #pragma unroll
        for (int sub = 0; sub < 8; sub++) {
            uint32_t bh0, bh1, bh2, bh3;
            LDSM_X4(bh0, bh1, bh2, bh3, qb + sub * 512);
            #pragma unroll
            for (int s = 0; s < 2; s++) {
                #pragma unroll
                for (int nh = 0; nh < 2; nh++) {
                    float c0 = 0.f, c1 = 0.f, c2 = 0.f, c3 = 0.f;
                    if (nh == 0) {
                        MMA16816(c0, c1, c2, c3, akh[s][0], akh[s][1], akh[s][2], akh[s][3], bh0, bh1);
                    } else {
                        MMA16816(c0, c1, c2, c3, akh[s][0], akh[s][1], akh[s][2], akh[s][3], bh2, bh3);
                    }
                    uint32_t e01, e23;
                    uint32_t h01 = h2u(__float22half2_rn(make_float2(c0, c1)));
                    uint32_t h23 = h2u(__float22half2_rn(make_float2(c2, c3)));
                    asm("ex2.approx.f16x2 %0, %1;" : "=r"(e01) : "r"(h01));
                    asm("ex2.approx.f16x2 %0, %1;" : "=r"(e23) : "r"(h23));
                    float2 f01 = __half22float2(u2h(e01));
                    float2 f23 = __half22float2(u2h(e23));
                    z[s][0] += f01.x + f01.y;
                    z[s][1] += f23.x + f23.y;
                }
            }
        }
        // stage tile qt+2
        if (qt + 2 < 16) {
            uint32_t d = smem_u32(&sQ[(qt + 2) % 3][0]);
            cp16(d + (tid * 2) * 16,     gq + (qt + 2) * 128 * DD + (tid * 2) * 8);
            cp16(d + (tid * 2 + 1) * 16, gq + (qt + 2) * 128 * DD + (tid * 2 + 1) * 8);
            CP_COMMIT();
        }
    }

    // quad reduce across the 4 threads sharing each row -> sZ
    #pragma unroll
    for (int s = 0; s < 2; s++)
        #pragma unroll
        for (int j = 0; j < 2; j++) {
            z[s][j] += __shfl_xor_sync(0xffffffffu, z[s][j], 1);
            z[s][j] += __shfl_xor_sync(0xffffffffu, z[s][j], 2);
        }
    if ((lane & 3) == 0) {
        int r = lane >> 2;
        #pragma unroll
        for (int s = 0; s < 2; s++) {
            sZ[warp * 32 + s * 16 + r]     = z[s][0];
            sZ[warp * 32 + s * 16 + r + 8] = z[s][1];
        }
    }
    __syncthreads();

    // fused fold: thread owns one k row; W[k,:] = V[k,:]/Z[k], split hi/lo
    {
        int id = p * TT + kbase + tid;
        float inv = 1.0f / sZ[tid];
        const float4* v4 = reinterpret_cast<const float4*>(&g_V[id * DD]);
        __half2* dh = reinterpret_cast<__half2*>(&g_Wh[id * DD]);
        __half2* dl = reinterpret_cast<__half2*>(&g_Wl[id * DD]);
        #pragma unroll
        for (int i = 0; i < 4; i++) {
            float4 x = v4[i];
            float w0 = x.x * inv, w1 = x.y * inv, w2 = x.z * inv, w3 = x.w * inv;
            __half2 h01 = __float22half2_rn(make_float2(w0, w1));
            __half2 h23 = __float22half2_rn(make_float2(w2, w3));
            float2 b01 = __half22float2(h01);
            float2 b23 = __half22float2(h23);
            dh[2 * i]     = h01;
            dh[2 * i + 1] = h23;
            dl[2 * i]     = __float22half2_rn(make_float2(w0 - b01.x, w1 - b01.y));
            dl[2 * i + 1] = __float22half2_rn(make_float2(w2 - b23.x, w3 - b23.y));
        }
    }
}

// ---------------------------------------------------------------------------
// K4 (pass B): out[q,:] = sum_k exp2(qh.kh) * W[k,:]  (W pre-folded, hi/lo).
// S hi-only (1 MMA/n8); P hi-only; PV keeps Wh+Wl.  6 MMAs per 16x16 per set.
// exp stays f32 EX2 (P feeds the weighted sum directly - no averaging).
// Warp owns 32 q rows; 64-k chunks, 3-deep cp.async, 1 sync per chunk.
// grid = (TT/128, NP), block = 128.
__global__ void __launch_bounds__(128) k_out()
{
    __shared__ __align__(16) __half sQh[128 * 16];
    __shared__ __align__(16) __half sB[3][3][64 * 16];   // [buf][Kh,Wh,Wl]

    int tid = threadIdx.x, lane = tid & 31, warp = tid >> 5;
    int p = blockIdx.y, qbase = blockIdx.x * 128;
    int n = p >> 2, h = p & 3;

    // stage this block's 128 Q rows: 256 uint4, 2 per thread
    {
        const uint4* src = reinterpret_cast<const uint4*>(g_Qh + (p * TT + qbase) * DD);
        uint4* dst = reinterpret_cast<uint4*>(sQh);
        dst[tid * 2] = src[tid * 2];
        dst[tid * 2 + 1] = src[tid * 2 + 1];
    }

    const __half* gk = g_Kh + p * TT * DD;
    const __half* gwh = g_Wh + p * TT * DD;
    const __half* gwl = g_Wl + p * TT * DD;
    uint32_t sb_base = smem_u32(&sB[0][0][0]);
    const uint32_t BUFB = 3 * 64 * 16 * 2;   // 6144 bytes per buffer

    // prologue: stage chunks 0, 1 (each: 3 arrays x 128 slots; 1 slot per thread per array)
    #pragma unroll
    for (int c0 = 0; c0 < 2; c0++) {
        uint32_t d = sb_base + c0 * BUFB;
        cp16(d + tid * 16,        gk  + c0 * 64 * DD + tid * 8);
        cp16(d + 2048 + tid * 16, gwh + c0 * 64 * DD + tid * 8);
        cp16(d + 4096 + tid * 16, gwl + c0 * 64 * DD + tid * 8);
        CP_COMMIT();
    }

    __syncthreads();   // Q tile visible

    // A frags: 2 sets of 16 Q rows
    int g = lane >> 3;
    uint32_t aqh[2][4];
    #pragma unroll
    for (int s = 0; s < 2; s++) {
        int row = warp * 32 + s * 16 + (g & 1) * 8 + (lane & 7);
        int col = (g >> 1) * 8;
        LDSM_X4(aqh[s][0], aqh[s][1], aqh[s][2], aqh[s][3], smem_u32(&sQh[row * 16 + col]));
    }

    float oc[2][2][4];   // [set][d-half][frag]
    #pragma unroll
    for (int s = 0; s < 2; s++)
        #pragma unroll
        for (int dh2 = 0; dh2 < 2; dh2++)
            #pragma unroll
            for (int j = 0; j < 4; j++) oc[s][dh2][j] = 0.f;

    uint32_t koff = ((g >> 1) * 8 + (lane & 7)) * 32 + (g & 1) * 16;
    uint32_t woff = 2048 + ((g & 1) * 8 + (lane & 7)) * 32 + (g >> 1) * 16;

    for (int kc = 0; kc < 32; kc++) {
        if (kc < 31) { CP_WAIT(1); } else { CP_WAIT(0); }
        __syncthreads();
        uint32_t bufb = sb_base + (kc % 3) * BUFB;
        uint32_t kaddr = bufb + koff;
        uint32_t waddr = bufb + woff;
        #pragma unroll
        for (int sub = 0; sub < 4; sub++) {
            uint32_t kh0, kh1, kh2, kh3;
            LDSM_X4(kh0, kh1, kh2, kh3, kaddr + sub * 512);
            uint32_t wh0, wh1, wh2, wh3, wl0, wl1, wl2, wl3;
            LDSM_X4T(wh0, wh1, wh2, wh3, waddr + sub * 512);
            LDSM_X4T(wl0, wl1, wl2, wl3, waddr + 2048 + sub * 512);

            #pragma unroll
            for (int s = 0; s < 2; s++) {
                uint32_t pah[4];
                {
                    float c0 = 0.f, c1 = 0.f, c2 = 0.f, c3 = 0.f;
                    MMA16816(c0, c1, c2, c3, aqh[s][0], aqh[s][1], aqh[s][2], aqh[s][3], kh0, kh1);
                    pah[0] = h2u(__float22half2_rn(make_float2(EX2(c0), EX2(c1))));
                    pah[1] = h2u(__float22half2_rn(make_float2(EX2(c2), EX2(c3))));
                }
                {
                    float c0 = 0.f, c1 = 0.f, c2 = 0.f, c3 = 0.f;
                    MMA16816(c0, c1, c2, c3, aqh[s][0], aqh[s][1], aqh[s][2], aqh[s][3], kh2, kh3);
                    pah[2] = h2u(__float22half2_rn(make_float2(EX2(c0), EX2(c1))));
                    pah[3] = h2u(__float22half2_rn(make_float2(EX2(c2), EX2(c3))));
                }

                MMA16816(oc[s][0][0], oc[s][0][1], oc[s][0][2], oc[s][0][3],
                         pah[0], pah[1], pah[2], pah[3], wh0, wh1);
                MMA16816(oc[s][0][0], oc[s][0][1], oc[s][0][2], oc[s][0][3],
                         pah[0], pah[1], pah[2], pah[3], wl0, wl1);
                MMA16816(oc[s][1][0], oc[s][1][1], oc[s][1][2], oc[s][1][3],
                         pah[0], pah[1], pah[2], pah[3], wh2, wh3);
                MMA16816(oc[s][1][0], oc[s][1][1], oc[s][1][2], oc[s][1][3],
                         pah[0], pah[1], pah[2], pah[3], wl2, wl3);
            }
        }
        // stage chunk kc+2
        if (kc + 2 < 32) {
            uint32_t d = sb_base + ((kc + 2) % 3) * BUFB;
            cp16(d + tid * 16,        gk  + (kc + 2) * 64 * DD + tid * 8);
            cp16(d + 2048 + tid * 16, gwh + (kc + 2) * 64 * DD + tid * 8);
            cp16(d + 4096 + tid * 16, gwl + (kc + 2) * 64 * DD + tid * 8);
            CP_COMMIT();
        }
    }

    // epilogue: write fp16 hi/lo fragments to g_Oh / g_Ol (both sets)
    {
        int r = lane >> 2, c2 = lane & 3;
        #pragma unroll
        for (int s = 0; s < 2; s++) {
            int q0 = qbase + warp * 32 + s * 16 + r;
            int b0i = (n * TT + q0) * EE + h * DD;
            int b8i = (n * TT + q0 + 8) * EE + h * DD;
            int idxs[4] = { b0i + 2 * c2, b8i + 2 * c2, b0i + 8 + 2 * c2, b8i + 8 + 2 * c2 };
            float vals[4][2] = { {oc[s][0][0], oc[s][0][1]}, {oc[s][0][2], oc[s][0][3]},
                                 {oc[s][1][0], oc[s][1][1]}, {oc[s][1][2], oc[s][1][3]} };
            #pragma unroll
            for (int i = 0; i < 4; i++) {
                __half2 hi = __float22half2_rn(make_float2(vals[i][0], vals[i][1]));
                float2 bb = __half22float2(hi);
                __half2 lo = __float22half2_rn(make_float2(vals[i][0] - bb.x, vals[i][1] - bb.y));
                *reinterpret_cast<__half2*>(&g_Oh[idxs[i]]) = hi;
                *reinterpret_cast<__half2*>(&g_Ol[idxs[i]]) = lo;
            }
        }
    }
}

// ---------------------------------------------------------------------------
// K5a: split Wfc into fp16 hi/lo (one-time, tiny).
__global__ void k_wsplit(const float* __restrict__ Wfc)
{
    int i = blockIdx.x * blockDim.x + threadIdx.x;   // 0..4095
    float w = Wfc[i];
    __half hi = __float2half_rn(w);
    g_Wfh[i] = hi;
    g_Wfl[i] = __float2half_rn(w - __half2float(hi));
}

// ---------------------------------------------------------------------------
// K5b: final FC via fp16-split HMMA: y = O @ Wfc + bfc.
// grid = 256 blocks x 128 rows; block = 256 (8 warps, warp owns 16 rows).
__global__ void __launch_bounds__(256) k_fc_mma(const float* __restrict__ bfc,
                                               float* __restrict__ out)
{
    __shared__ __align__(16) __half sXh[128 * 64], sXl[128 * 64];
    __shared__ __align__(16) __half sWh[64 * 64],  sWl[64 * 64];
    __shared__ float sb[64];

    int tid = threadIdx.x, lane = tid & 31, warp = tid >> 5;
    int rowbase = blockIdx.x * 128;

    {
        const uint4* srch = reinterpret_cast<const uint4*>(g_Oh + rowbase * EE);
        const uint4* srcl = reinterpret_cast<const uint4*>(g_Ol + rowbase * EE);
        uint4* dh = reinterpret_cast<uint4*>(sXh);
        uint4* dl = reinterpret_cast<uint4*>(sXl);
        #pragma unroll
        for (int j = 0; j < 4; j++) {
            dh[tid + j * 256] = srch[tid + j * 256];
            dl[tid + j * 256] = srcl[tid + j * 256];
        }
    }
    {
        const uint4* srch = reinterpret_cast<const uint4*>(g_Wfh);
        const uint4* srcl = reinterpret_cast<const uint4*>(g_Wfl);
        uint4* dh = reinterpret_cast<uint4*>(sWh);
        uint4* dl = reinterpret_cast<uint4*>(sWl);
        dh[tid] = srch[tid]; dh[tid + 256] = srch[tid + 256];
        dl[tid] = srcl[tid]; dl[tid + 256] = srcl[tid + 256];
    }
    if (tid < 64) sb[tid] = bfc[tid];
    __syncthreads();

    int g = lane >> 3;
    uint32_t axh[4][4], axl[4][4];
    #pragma unroll
    for (int kt = 0; kt < 4; kt++) {
        int row = warp * 16 + (g & 1) * 8 + (lane & 7);
        int col = kt * 16 + (g >> 1) * 8;
        LDSM_X4(axh[kt][0], axh[kt][1], axh[kt][2], axh[kt][3], smem_u32(&sXh[row * 64 + col]));
        LDSM_X4(axl[kt][0], axl[kt][1], axl[kt][2], axl[kt][3], smem_u32(&sXl[row * 64 + col]));
    }

    float c[8][4];
    #pragma unroll
    for (int i = 0; i < 8; i++)
        #pragma unroll
        for (int j = 0; j < 4; j++) c[i][j] = 0.f;

    #pragma unroll
    for (int nt2 = 0; nt2 < 4; nt2++) {
        #pragma unroll
        for (int kt = 0; kt < 4; kt++) {
            int brow = kt * 16 + (g & 1) * 8 + (lane & 7);
            int bcol = nt2 * 16 + (g >> 1) * 8;
            uint32_t bh0, bh1, bh2, bh3, bl0, bl1, bl2, bl3;
            LDSM_X4T(bh0, bh1, bh2, bh3, smem_u32(&sWh[brow * 64 + bcol]));
            LDSM_X4T(bl0, bl1, bl2, bl3, smem_u32(&sWl[brow * 64 + bcol]));
            MMA16816(c[nt2*2][0], c[nt2*2][1], c[nt2*2][2], c[nt2*2][3],
                     axh[kt][0], axh[kt][1], axh[kt][2], axh[kt][3], bh0, bh1);
            MMA16816(c[nt2*2][0], c[nt2*2][1], c[nt2*2][2], c[nt2*2][3],
                     axh[kt][0], axh[kt][1], axh[kt][2], axh[kt][3], bl0, bl1);
            MMA16816(c[nt2*2][0], c[nt2*2][1], c[nt2*2][2], c[nt2*2][3],
                     axl[kt][0], axl[kt][1], axl[kt][2], axl[kt][3], bh0, bh1);
            MMA16816(c[nt2*2+1][0], c[nt2*2+1][1], c[nt2*2+1][2], c[nt2*2+1][3],
                     axh[kt][0], axh[kt][1], axh[kt][2], axh[kt][3], bh2, bh3);
            MMA16816(c[nt2*2+1][0], c[nt2*2+1][1], c[nt2*2+1][2], c[nt2*2+1][3],
                     axh[kt][0], axh[kt][1], axh[kt][2], axh[kt][3], bl2, bl3);
            MMA16816(c[nt2*2+1][0], c[nt2*2+1][1], c[nt2*2+1][2], c[nt2*2+1][3],
                     axl[kt][0], axl[kt][1], axl[kt][2], axl[kt][3], bh2, bh3);
        }
    }

    int r = lane >> 2, j = lane & 3;
    int row0 = rowbase + warp * 16 + r;
    #pragma unroll
    for (int nt = 0; nt < 8; nt++) {
        int ncol = nt * 8 + 2 * j;
        float b0 = sb[ncol], b1 = sb[ncol + 1];
        *reinterpret_cast<float2*>(&out[row0 * 64 + ncol]) =
            make_float2(c[nt][0] + b0, c[nt][1] + b1);
        *reinterpret_cast<float2*>(&out[(row0 + 8) * 64 + ncol]) =
            make_float2(c[nt][2] + b0, c[nt][3] + b1);
    }
}

// ---------------------------------------------------------------------------
// Input order: 0:value 1:key 2:query 3:Wq 4:bq 5:Wk 6:bk 7:Wv 8:bv 9:Wfc 10:bfc
extern "C" void kernel_launch(void* const* d_in, const int* in_sizes, int n_in,
                              void* d_out, int out_size)
{
    const float* value = (const float*)d_in[0];
    const float* key_  = (const float*)d_in[1];
    const float* query = (const float*)d_in[2];
    const float* Wq    = (const float*)d_in[3];
    const float* bq    = (const float*)d_in[4];
    const float* Wk    = (const float*)d_in[5];
    const float* bk    = (const float*)d_in[6];
    const float* Wv    = (const float*)d_in[7];
    const float* bv    = (const float*)d_in[8];
    const float* Wfc   = (const float*)d_in[9];
    const float* bfc   = (const float*)d_in[10];
    float* out = (float*)d_out;

    k_wsplit<<<16, 256>>>(Wfc);
    k_proj<<<(NP * TT) / 256, 256>>>(value, key_, query, Wq, bq, Wk, bk, Wv, bv);
    k_zsum<<<dim3(TT / 128, NP), 128>>>();
    k_out<<<dim3(TT / 128, NP), 128>>>();
    k_fc_mma<<<(NN * TT) / 128, 256>>>(bfc, out);
}

// round 12
// speedup vs baseline: 6.1244x; 1.0126x over previous
#include <cuda_runtime.h>
#include <cuda_fp16.h>
#include <cstdint>

// Problem constants: B=1, N=16, T=2048, E=64, H=4, D=16
#define NN   16
#define TT   2048
#define EE   64
#define HH   4
#define DD   16
#define NP   (NN*HH)          // 64 (n,h) pairs
// Q pre-scaled by log2(e)/8 so scores are in log2 domain -> ex2.approx (1 MUFU)
#define QSCALE2 0.180336880740290f

// ---------------------------------------------------------------------------
// Scratch (static device arrays; allocation-free per harness rules)
__device__ __align__(16) __half g_Qh[NP * TT * DD];  // q*log2e/8 (fp16)
__device__ __align__(16) __half g_Kh[NP * TT * DD];  // k (fp16)
__device__ __align__(16) float  g_V [NP * TT * DD];  // projected v (fp32)
__device__ __align__(16) __half g_Wh[NP * TT * DD];  // (v/Z) hi
__device__ __align__(16) __half g_Wl[NP * TT * DD];  // (v/Z) lo
__device__ __align__(16) __half g_Oh[NN * TT * EE];  // attention out hi
__device__ __align__(16) __half g_Ol[NN * TT * EE];  // attention out lo
__device__ __align__(16) __half g_Wfh[EE * EE];      // Wfc hi
__device__ __align__(16) __half g_Wfl[EE * EE];      // Wfc lo

// ---------------------------------------------------------------------------
__device__ __forceinline__ uint32_t smem_u32(const void* p) {
    return (uint32_t)__cvta_generic_to_shared(p);
}
__device__ __forceinline__ void cp16(uint32_t dst, const void* src) {
    asm volatile("cp.async.cg.shared.global [%0], [%1], 16;" :: "r"(dst), "l"(src));
}
#define CP_COMMIT() asm volatile("cp.async.commit_group;")
#define CP_WAIT(n)  asm volatile("cp.async.wait_group %0;" :: "n"(n))

#define LDSM_X4(r0,r1,r2,r3,addr) \
    asm volatile("ldmatrix.sync.aligned.m8n8.x4.shared.b16 {%0,%1,%2,%3}, [%4];" \
        : "=r"(r0),"=r"(r1),"=r"(r2),"=r"(r3) : "r"(addr))
#define LDSM_X4T(r0,r1,r2,r3,addr) \
    asm volatile("ldmatrix.sync.aligned.m8n8.x4.trans.shared.b16 {%0,%1,%2,%3}, [%4];" \
        : "=r"(r0),"=r"(r1),"=r"(r2),"=r"(r3) : "r"(addr))
#define MMA16816(c0,c1,c2,c3,a0,a1,a2,a3,b0,b1) \
    asm volatile("mma.sync.aligned.m16n8k16.row.col.f32.f16.f16.f32 " \
        "{%0,%1,%2,%3},{%4,%5,%6,%7},{%8,%9},{%0,%1,%2,%3};" \
        : "+f"(c0),"+f"(c1),"+f"(c2),"+f"(c3) \
        : "r"(a0),"r"(a1),"r"(a2),"r"(a3),"r"(b0),"r"(b1))

__device__ __forceinline__ uint32_t h2u(__half2 h) {
    return reinterpret_cast<uint32_t&>(h);
}
__device__ __forceinline__ __half2 u2h(uint32_t u) {
    return reinterpret_cast<__half2&>(u);
}
// packed fp16x2 exp2 (1 MUFU op for 2 exps)
__device__ __forceinline__ uint32_t EX2H2(float a, float b) {
    uint32_t hin = h2u(__float22half2_rn(make_float2(a, b)));
    uint32_t r;
    asm("ex2.approx.f16x2 %0, %1;" : "=r"(r) : "r"(hin));
    return r;
}

// ---------------------------------------------------------------------------
// K1: head projections -> fp16 Q (log2e-scaled), fp16 K, fp32 V.
__global__ void k_proj(const float* __restrict__ value,
                       const float* __restrict__ key,
                       const float* __restrict__ query,
                       const float* __restrict__ Wq, const float* __restrict__ bq,
                       const float* __restrict__ Wk, const float* __restrict__ bk,
                       const float* __restrict__ Wv, const float* __restrict__ bv)
{
    __shared__ float sWq[256], sWk[256], sWv[256];
    __shared__ float sbq[16], sbk[16], sbv[16];
    int tid = threadIdx.x;
    if (tid < 256) { sWq[tid] = Wq[tid]; sWk[tid] = Wk[tid]; sWv[tid] = Wv[tid]; }
    if (tid < 16)  { sbq[tid] = bq[tid]; sbk[tid] = bk[tid]; sbv[tid] = bv[tid]; }
    __syncthreads();

    int id = blockIdx.x * blockDim.x + tid;
    int t  = id & (TT - 1);
    int p  = id >> 11;
    int n  = p >> 2;
    int h  = p & 3;
    int in_base  = (n * TT + t) * EE + h * DD;
    int out_base = (p * TT + t) * DD;

    float x[16];
    // ---- q (scaled by log2e/8) ----
    #pragma unroll
    for (int i = 0; i < 16; i++) x[i] = query[in_base + i];
    {
        float a[16];
        #pragma unroll
        for (int j = 0; j < 16; j++) {
            float acc = sbq[j];
            #pragma unroll
            for (int i = 0; i < 16; i++) acc = fmaf(x[i], sWq[i * 16 + j], acc);
            a[j] = acc * QSCALE2;
        }
        __half2* dh = reinterpret_cast<__half2*>(&g_Qh[out_base]);
        #pragma unroll
        for (int j = 0; j < 8; j++)
            dh[j] = __float22half2_rn(make_float2(a[2 * j], a[2 * j + 1]));
    }
    // ---- k ----
    #pragma unroll
    for (int i = 0; i < 16; i++) x[i] = key[in_base + i];
    {
        float a[16];
        #pragma unroll
        for (int j = 0; j < 16; j++) {
            float acc = sbk[j];
            #pragma unroll
            for (int i = 0; i < 16; i++) acc = fmaf(x[i], sWk[i * 16 + j], acc);
            a[j] = acc;
        }
        __half2* dh = reinterpret_cast<__half2*>(&g_Kh[out_base]);
        #pragma unroll
        for (int j = 0; j < 8; j++)
            dh[j] = __float22half2_rn(make_float2(a[2 * j], a[2 * j + 1]));
    }
    // ---- v (fp32) ----
    #pragma unroll
    for (int i = 0; i < 16; i++) x[i] = value[in_base + i];
    #pragma unroll
    for (int j = 0; j < 16; j++) {
        float acc = sbv[j];
        #pragma unroll
        for (int i = 0; i < 16; i++) acc = fmaf(x[i], sWv[i * 16 + j], acc);
        g_V[out_base + j] = acc;
    }
}

// ---------------------------------------------------------------------------
// K2 (pass A): Z[k] = sum_q exp2(qh.kh), then fold 1/Z into V in-place.
// S hi-only (1 MMA per n8 tile); exp via ex2.approx.f16x2 — crucially the
// SAME fp16 rounding + ex2 path k_out uses, so numerator/denominator of the
// softmax are exactly consistent.
// grid = (TT/128, NP), block = 128.
__global__ void __launch_bounds__(128) k_zsum()
{
    __shared__ __align__(16) __half sK[128 * 16];
    __shared__ __align__(16) __half sQ[3][128 * 16];
    __shared__ float sZ[128];

    int tid = threadIdx.x, lane = tid & 31, warp = tid >> 5;
    int p = blockIdx.y, kbase = blockIdx.x * 128;

    // stage this block's 128 K rows: 256 uint4, 2 per thread
    {
        const uint4* src = reinterpret_cast<const uint4*>(g_Kh + (p * TT + kbase) * DD);
        uint4* dst = reinterpret_cast<uint4*>(sK);
        dst[tid * 2] = src[tid * 2];
        dst[tid * 2 + 1] = src[tid * 2 + 1];
    }

    const __half* gq = g_Qh + p * TT * DD;
    // prologue: stage Q tiles 0, 1 (256 uint4 each, 2 per thread)
    #pragma unroll
    for (int qt0 = 0; qt0 < 2; qt0++) {
        uint32_t d = smem_u32(&sQ[qt0][0]);
        cp16(d + (tid * 2) * 16,     gq + qt0 * 128 * DD + (tid * 2) * 8);
        cp16(d + (tid * 2 + 1) * 16, gq + qt0 * 128 * DD + (tid * 2 + 1) * 8);
        CP_COMMIT();
    }

    __syncthreads();   // K tile visible

    // A frags: 2 sets of 16 K rows
    int g = lane >> 3;
    uint32_t akh[2][4];
    #pragma unroll
    for (int s = 0; s < 2; s++) {
        int row = warp * 32 + s * 16 + (g & 1) * 8 + (lane & 7);
        int col = (g >> 1) * 8;
        LDSM_X4(akh[s][0], akh[s][1], akh[s][2], akh[s][3], smem_u32(&sK[row * 16 + col]));
    }

    float z[2][2] = {{0.f, 0.f}, {0.f, 0.f}};
    int browq = (g >> 1) * 8 + (lane & 7);
    int bcol  = (g & 1) * 8;

    for (int qt = 0; qt < 16; qt++) {
        if (qt < 15) { CP_WAIT(1); } else { CP_WAIT(0); }
        __syncthreads();
        int buf = qt % 3;
        uint32_t qb = smem_u32(&sQ[buf][browq * 16 + bcol]);
        #pragma unroll
        for (int sub = 0; sub < 8; sub++) {
            uint32_t bh0, bh1, bh2, bh3;
            LDSM_X4(bh0, bh1, bh2, bh3, qb + sub * 512);
            #pragma unroll
            for (int s = 0; s < 2; s++) {
                #pragma unroll
                for (int nh = 0; nh < 2; nh++) {
                    float c0 = 0.f, c1 = 0.f, c2 = 0.f, c3 = 0.f;
                    if (nh == 0) {
                        MMA16816(c0, c1, c2, c3, akh[s][0], akh[s][1], akh[s][2], akh[s][3], bh0, bh1);
                    } else {
                        MMA16816(c0, c1, c2, c3, akh[s][0], akh[s][1], akh[s][2], akh[s][3], bh2, bh3);
                    }
                    uint32_t e01 = EX2H2(c0, c1);
                    uint32_t e23 = EX2H2(c2, c3);
                    float2 f01 = __half22float2(u2h(e01));
                    float2 f23 = __half22float2(u2h(e23));
                    z[s][0] += f01.x + f01.y;
                    z[s][1] += f23.x + f23.y;
                }
            }
        }
        // stage tile qt+2
        if (qt + 2 < 16) {
            uint32_t d = smem_u32(&sQ[(qt + 2) % 3][0]);
            cp16(d + (tid * 2) * 16,     gq + (qt + 2) * 128 * DD + (tid * 2) * 8);
            cp16(d + (tid * 2 + 1) * 16, gq + (qt + 2) * 128 * DD + (tid * 2 + 1) * 8);
            CP_COMMIT();
        }
    }

    // quad reduce across the 4 threads sharing each row -> sZ
    #pragma unroll
    for (int s = 0; s < 2; s++)
        #pragma unroll
        for (int j = 0; j < 2; j++) {
            z[s][j] += __shfl_xor_sync(0xffffffffu, z[s][j], 1);
            z[s][j] += __shfl_xor_sync(0xffffffffu, z[s][j], 2);
        }
    if ((lane & 3) == 0) {
        int r = lane >> 2;
        #pragma unroll
        for (int s = 0; s < 2; s++) {
            sZ[warp * 32 + s * 16 + r]     = z[s][0];
            sZ[warp * 32 + s * 16 + r + 8] = z[s][1];
        }
    }
    __syncthreads();

    // fused fold: thread owns one k row; W[k,:] = V[k,:]/Z[k], split hi/lo
    {
        int id = p * TT + kbase + tid;
        float inv = 1.0f / sZ[tid];
        const float4* v4 = reinterpret_cast<const float4*>(&g_V[id * DD]);
        __half2* dh = reinterpret_cast<__half2*>(&g_Wh[id * DD]);
        __half2* dl = reinterpret_cast<__half2*>(&g_Wl[id * DD]);
        #pragma unroll
        for (int i = 0; i < 4; i++) {
            float4 x = v4[i];
            float w0 = x.x * inv, w1 = x.y * inv, w2 = x.z * inv, w3 = x.w * inv;
            __half2 h01 = __float22half2_rn(make_float2(w0, w1));
            __half2 h23 = __float22half2_rn(make_float2(w2, w3));
            float2 b01 = __half22float2(h01);
            float2 b23 = __half22float2(h23);
            dh[2 * i]     = h01;
            dh[2 * i + 1] = h23;
            dl[2 * i]     = __float22half2_rn(make_float2(w0 - b01.x, w1 - b01.y));
            dl[2 * i + 1] = __float22half2_rn(make_float2(w2 - b23.x, w3 - b23.y));
        }
    }
}

// ---------------------------------------------------------------------------
// K4 (pass B): out[q,:] = sum_k exp2(qh.kh) * W[k,:]  (W pre-folded, hi/lo).
// S hi-only; P via ex2.approx.f16x2 (matches k_zsum bit-for-bit -> exactly
// consistent softmax; also ex2 output IS the P fragment - no repack, MUFU
// floor halved 63->32us).  PV keeps Wh+Wl.  Warp owns 32 q rows.
// grid = (TT/128, NP), block = 128.
__global__ void __launch_bounds__(128) k_out()
{
    __shared__ __align__(16) __half sQh[128 * 16];
    __shared__ __align__(16) __half sB[3][3][64 * 16];   // [buf][Kh,Wh,Wl]

    int tid = threadIdx.x, lane = tid & 31, warp = tid >> 5;
    int p = blockIdx.y, qbase = blockIdx.x * 128;
    int n = p >> 2, h = p & 3;

    // stage this block's 128 Q rows: 256 uint4, 2 per thread
    {
        const uint4* src = reinterpret_cast<const uint4*>(g_Qh + (p * TT + qbase) * DD);
        uint4* dst = reinterpret_cast<uint4*>(sQh);
        dst[tid * 2] = src[tid * 2];
        dst[tid * 2 + 1] = src[tid * 2 + 1];
    }

    const __half* gk = g_Kh + p * TT * DD;
    const __half* gwh = g_Wh + p * TT * DD;
    const __half* gwl = g_Wl + p * TT * DD;
    uint32_t sb_base = smem_u32(&sB[0][0][0]);
    const uint32_t BUFB = 3 * 64 * 16 * 2;   // 6144 bytes per buffer

    // prologue: stage chunks 0, 1
    #pragma unroll
    for (int c0 = 0; c0 < 2; c0++) {
        uint32_t d = sb_base + c0 * BUFB;
        cp16(d + tid * 16,        gk  + c0 * 64 * DD + tid * 8);
        cp16(d + 2048 + tid * 16, gwh + c0 * 64 * DD + tid * 8);
        cp16(d + 4096 + tid * 16, gwl + c0 * 64 * DD + tid * 8);
        CP_COMMIT();
    }

    __syncthreads();   // Q tile visible

    // A frags: 2 sets of 16 Q rows
    int g = lane >> 3;
    uint32_t aqh[2][4];
    #pragma unroll
    for (int s = 0; s < 2; s++) {
        int row = warp * 32 + s * 16 + (g & 1) * 8 + (lane & 7);
        int col = (g >> 1) * 8;
        LDSM_X4(aqh[s][0], aqh[s][1], aqh[s][2], aqh[s][3], smem_u32(&sQh[row * 16 + col]));
    }

    float oc[2][2][4];   // [set][d-half][frag]
    #pragma unroll
    for (int s = 0; s < 2; s++)
        #pragma unroll
        for (int dh2 = 0; dh2 < 2; dh2++)
            #pragma unroll
            for (int j = 0; j < 4; j++) oc[s][dh2][j] = 0.f;

    uint32_t koff = ((g >> 1) * 8 + (lane & 7)) * 32 + (g & 1) * 16;
    uint32_t woff = 2048 + ((g & 1) * 8 + (lane & 7)) * 32 + (g >> 1) * 16;

    for (int kc = 0; kc < 32; kc++) {
        if (kc < 31) { CP_WAIT(1); } else { CP_WAIT(0); }
        __syncthreads();
        uint32_t bufb = sb_base + (kc % 3) * BUFB;
        uint32_t kaddr = bufb + koff;
        uint32_t waddr = bufb + woff;
        #pragma unroll
        for (int sub = 0; sub < 4; sub++) {
            uint32_t kh0, kh1, kh2, kh3;
            LDSM_X4(kh0, kh1, kh2, kh3, kaddr + sub * 512);
            uint32_t wh0, wh1, wh2, wh3, wl0, wl1, wl2, wl3;
            LDSM_X4T(wh0, wh1, wh2, wh3, waddr + sub * 512);
            LDSM_X4T(wl0, wl1, wl2, wl3, waddr + 2048 + sub * 512);

            #pragma unroll
            for (int s = 0; s < 2; s++) {
                uint32_t pah[4];
                {
                    float c0 = 0.f, c1 = 0.f, c2 = 0.f, c3 = 0.f;
                    MMA16816(c0, c1, c2, c3, aqh[s][0], aqh[s][1], aqh[s][2], aqh[s][3], kh0, kh1);
                    pah[0] = EX2H2(c0, c1);
                    pah[1] = EX2H2(c2, c3);
                }
                {
                    float c0 = 0.f, c1 = 0.f, c2 = 0.f, c3 = 0.f;
                    MMA16816(c0, c1, c2, c3, aqh[s][0], aqh[s][1], aqh[s][2], aqh[s][3], kh2, kh3);
                    pah[2] = EX2H2(c0, c1);
                    pah[3] = EX2H2(c2, c3);
                }

                MMA16816(oc[s][0][0], oc[s][0][1], oc[s][0][2], oc[s][0][3],
                         pah[0], pah[1], pah[2], pah[3], wh0, wh1);
                MMA16816(oc[s][0][0], oc[s][0][1], oc[s][0][2], oc[s][0][3],
                         pah[0], pah[1], pah[2], pah[3], wl0, wl1);
                MMA16816(oc[s][1][0], oc[s][1][1], oc[s][1][2], oc[s][1][3],
                         pah[0], pah[1], pah[2], pah[3], wh2, wh3);
                MMA16816(oc[s][1][0], oc[s][1][1], oc[s][1][2], oc[s][1][3],
                         pah[0], pah[1], pah[2], pah[3], wl2, wl3);
            }
        }
        // stage chunk kc+2
        if (kc + 2 < 32) {
            uint32_t d = sb_base + ((kc + 2) % 3) * BUFB;
            cp16(d + tid * 16,        gk  + (kc + 2) * 64 * DD + tid * 8);
            cp16(d + 2048 + tid * 16, gwh + (kc + 2) * 64 * DD + tid * 8);
            cp16(d + 4096 + tid * 16, gwl + (kc + 2) * 64 * DD + tid * 8);
            CP_COMMIT();
        }
    }

    // epilogue: write fp16 hi/lo fragments to g_Oh / g_Ol (both sets)
    {
        int r = lane >> 2, c2 = lane & 3;
        #pragma unroll
        for (int s = 0; s < 2; s++) {
            int q0 = qbase + warp * 32 + s * 16 + r;
            int b0i = (n * TT + q0) * EE + h * DD;
            int b8i = (n * TT + q0 + 8) * EE + h * DD;
            int idxs[4] = { b0i + 2 * c2, b8i + 2 * c2, b0i + 8 + 2 * c2, b8i + 8 + 2 * c2 };
            float vals[4][2] = { {oc[s][0][0], oc[s][0][1]}, {oc[s][0][2], oc[s][0][3]},
                                 {oc[s][1][0], oc[s][1][1]}, {oc[s][1][2], oc[s][1][3]} };
            #pragma unroll
            for (int i = 0; i < 4; i++) {
                __half2 hi = __float22half2_rn(make_float2(vals[i][0], vals[i][1]));
                float2 bb = __half22float2(hi);
                __half2 lo = __float22half2_rn(make_float2(vals[i][0] - bb.x, vals[i][1] - bb.y));
                *reinterpret_cast<__half2*>(&g_Oh[idxs[i]]) = hi;
                *reinterpret_cast<__half2*>(&g_Ol[idxs[i]]) = lo;
            }
        }
    }
}

// ---------------------------------------------------------------------------
// K5a: split Wfc into fp16 hi/lo (one-time, tiny).
__global__ void k_wsplit(const float* __restrict__ Wfc)
{
    int i = blockIdx.x * blockDim.x + threadIdx.x;   // 0..4095
    float w = Wfc[i];
    __half hi = __float2half_rn(w);
    g_Wfh[i] = hi;
    g_Wfl[i] = __float2half_rn(w - __half2float(hi));
}

// ---------------------------------------------------------------------------
// K5b: final FC via fp16-split HMMA: y = O @ Wfc + bfc.
// grid = 256 blocks x 128 rows; block = 256 (8 warps, warp owns 16 rows).
__global__ void __launch_bounds__(256) k_fc_mma(const float* __restrict__ bfc,
                                               float* __restrict__ out)
{
    __shared__ __align__(16) __half sXh[128 * 64], sXl[128 * 64];
    __shared__ __align__(16) __half sWh[64 * 64],  sWl[64 * 64];
    __shared__ float sb[64];

    int tid = threadIdx.x, lane = tid & 31, warp = tid >> 5;
    int rowbase = blockIdx.x * 128;

    {
        const uint4* srch = reinterpret_cast<const uint4*>(g_Oh + rowbase * EE);
        const uint4* srcl = reinterpret_cast<const uint4*>(g_Ol + rowbase * EE);
        uint4* dh = reinterpret_cast<uint4*>(sXh);
        uint4* dl = reinterpret_cast<uint4*>(sXl);
        #pragma unroll
        for (int j = 0; j < 4; j++) {
            dh[tid + j * 256] = srch[tid + j * 256];
            dl[tid + j * 256] = srcl[tid + j * 256];
        }
    }
    {
        const uint4* srch = reinterpret_cast<const uint4*>(g_Wfh);
        const uint4* srcl = reinterpret_cast<const uint4*>(g_Wfl);
        uint4* dh = reinterpret_cast<uint4*>(sWh);
        uint4* dl = reinterpret_cast<uint4*>(sWl);
        dh[tid] = srch[tid]; dh[tid + 256] = srch[tid + 256];
        dl[tid] = srcl[tid]; dl[tid + 256] = srcl[tid + 256];
    }
    if (tid < 64) sb[tid] = bfc[tid];
    __syncthreads();

    int g = lane >> 3;
    uint32_t axh[4][4], axl[4][4];
    #pragma unroll
    for (int kt = 0; kt < 4; kt++) {
        int row = warp * 16 + (g & 1) * 8 + (lane & 7);
        int col = kt * 16 + (g >> 1) * 8;
        LDSM_X4(axh[kt][0], axh[kt][1], axh[kt][2], axh[kt][3], smem_u32(&sXh[row * 64 + col]));
        LDSM_X4(axl[kt][0], axl[kt][1], axl[kt][2], axl[kt][3], smem_u32(&sXl[row * 64 + col]));
    }

    float c[8][4];
    #pragma unroll
    for (int i = 0; i < 8; i++)
        #pragma unroll
        for (int j = 0; j < 4; j++) c[i][j] = 0.f;

    #pragma unroll
    for (int nt2 = 0; nt2 < 4; nt2++) {
        #pragma unroll
        for (int kt = 0; kt < 4; kt++) {
            int brow = kt * 16 + (g & 1) * 8 + (lane & 7);
            int bcol = nt2 * 16 + (g >> 1) * 8;
            uint32_t bh0, bh1, bh2, bh3, bl0, bl1, bl2, bl3;
            LDSM_X4T(bh0, bh1, bh2, bh3, smem_u32(&sWh[brow * 64 + bcol]));
            LDSM_X4T(bl0, bl1, bl2, bl3, smem_u32(&sWl[brow * 64 + bcol]));
            MMA16816(c[nt2*2][0], c[nt2*2][1], c[nt2*2][2], c[nt2*2][3],
                     axh[kt][0], axh[kt][1], axh[kt][2], axh[kt][3], bh0, bh1);
            MMA16816(c[nt2*2][0], c[nt2*2][1], c[nt2*2][2], c[nt2*2][3],
                     axh[kt][0], axh[kt][1], axh[kt][2], axh[kt][3], bl0, bl1);
            MMA16816(c[nt2*2][0], c[nt2*2][1], c[nt2*2][2], c[nt2*2][3],
                     axl[kt][0], axl[kt][1], axl[kt][2], axl[kt][3], bh0, bh1);
            MMA16816(c[nt2*2+1][0], c[nt2*2+1][1], c[nt2*2+1][2], c[nt2*2+1][3],
                     axh[kt][0], axh[kt][1], axh[kt][2], axh[kt][3], bh2, bh3);
            MMA16816(c[nt2*2+1][0], c[nt2*2+1][1], c[nt2*2+1][2], c[nt2*2+1][3],
                     axh[kt][0], axh[kt][1], axh[kt][2], axh[kt][3], bl2, bl3);
            MMA16816(c[nt2*2+1][0], c[nt2*2+1][1], c[nt2*2+1][2], c[nt2*2+1][3],
                     axl[kt][0], axl[kt][1], axl[kt][2], axl[kt][3], bh2, bh3);
        }
    }

    int r = lane >> 2, j = lane & 3;
    int row0 = rowbase + warp * 16 + r;
    #pragma unroll
    for (int nt = 0; nt < 8; nt++) {
        int ncol = nt * 8 + 2 * j;
        float b0 = sb[ncol], b1 = sb[ncol + 1];
        *reinterpret_cast<float2*>(&out[row0 * 64 + ncol]) =
            make_float2(c[nt][0] + b0, c[nt][1] + b1);
        *reinterpret_cast<float2*>(&out[(row0 + 8) * 64 + ncol]) =
            make_float2(c[nt][2] + b0, c[nt][3] + b1);
    }
}

// ---------------------------------------------------------------------------
// Input order: 0:value 1:key 2:query 3:Wq 4:bq 5:Wk 6:bk 7:Wv 8:bv 9:Wfc 10:bfc
extern "C" void kernel_launch(void* const* d_in, const int* in_sizes, int n_in,
                              void* d_out, int out_size)
{
    const float* value = (const float*)d_in[0];
    const float* key_  = (const float*)d_in[1];
    const float* query = (const float*)d_in[2];
    const float* Wq    = (const float*)d_in[3];
    const float* bq    = (const float*)d_in[4];
    const float* Wk    = (const float*)d_in[5];
    const float* bk    = (const float*)d_in[6];
    const float* Wv    = (const float*)d_in[7];
    const float* bv    = (const float*)d_in[8];
    const float* Wfc   = (const float*)d_in[9];
    const float* bfc   = (const float*)d_in[10];
    float* out = (float*)d_out;

    k_wsplit<<<16, 256>>>(Wfc);
    k_proj<<<(NP * TT) / 256, 256>>>(value, key_, query, Wq, bq, Wk, bk, Wv, bv);
    k_zsum<<<dim3(TT / 128, NP), 128>>>();
    k_out<<<dim3(TT / 128, NP), 128>>>();
    k_fc_mma<<<(NN * TT) / 128, 256>>>(bfc, out);
}

// round 13
// speedup vs baseline: 6.9802x; 1.1397x over previous
#include <cuda_runtime.h>
#include <cuda_fp16.h>
#include <cstdint>

// Problem constants: B=1, N=16, T=2048, E=64, H=4, D=16
#define NN   16
#define TT   2048
#define EE   64
#define HH   4
#define DD   16
#define NP   (NN*HH)          // 64 (n,h) pairs
// Q pre-scaled by log2(e)/8 so scores are in log2 domain -> ex2.approx (1 MUFU)
#define QSCALE2 0.180336880740290f

// ---------------------------------------------------------------------------
// Scratch (static device arrays; allocation-free per harness rules)
__device__ __align__(16) __half g_Qh[NP * TT * DD];  // q*log2e/8 (fp16)
__device__ __align__(16) __half g_Kh[NP * TT * DD];  // k (fp16)
__device__ __align__(16) float  g_V [NP * TT * DD];  // projected v (fp32)
__device__ __align__(16) __half g_Wh[NP * TT * DD];  // (v/Z) fp16
__device__ __align__(16) __half g_Oh[NN * TT * EE];  // attention out fp16
__device__ __align__(16) __half g_Wfh[EE * EE];      // Wfc hi
__device__ __align__(16) __half g_Wfl[EE * EE];      // Wfc lo

// ---------------------------------------------------------------------------
__device__ __forceinline__ uint32_t smem_u32(const void* p) {
    return (uint32_t)__cvta_generic_to_shared(p);
}
__device__ __forceinline__ void cp16(uint32_t dst, const void* src) {
    asm volatile("cp.async.cg.shared.global [%0], [%1], 16;" :: "r"(dst), "l"(src));
}
#define CP_COMMIT() asm volatile("cp.async.commit_group;")
#define CP_WAIT(n)  asm volatile("cp.async.wait_group %0;" :: "n"(n))

#define LDSM_X4(r0,r1,r2,r3,addr) \
    asm volatile("ldmatrix.sync.aligned.m8n8.x4.shared.b16 {%0,%1,%2,%3}, [%4];" \
        : "=r"(r0),"=r"(r1),"=r"(r2),"=r"(r3) : "r"(addr))
#define LDSM_X4T(r0,r1,r2,r3,addr) \
    asm volatile("ldmatrix.sync.aligned.m8n8.x4.trans.shared.b16 {%0,%1,%2,%3}, [%4];" \
        : "=r"(r0),"=r"(r1),"=r"(r2),"=r"(r3) : "r"(addr))
#define MMA16816(c0,c1,c2,c3,a0,a1,a2,a3,b0,b1) \
    asm volatile("mma.sync.aligned.m16n8k16.row.col.f32.f16.f16.f32 " \
        "{%0,%1,%2,%3},{%4,%5,%6,%7},{%8,%9},{%0,%1,%2,%3};" \
        : "+f"(c0),"+f"(c1),"+f"(c2),"+f"(c3) \
        : "r"(a0),"r"(a1),"r"(a2),"r"(a3),"r"(b0),"r"(b1))

__device__ __forceinline__ uint32_t h2u(__half2 h) {
    return reinterpret_cast<uint32_t&>(h);
}
__device__ __forceinline__ __half2 u2h(uint32_t u) {
    return reinterpret_cast<__half2&>(u);
}
// packed fp16x2 exp2 (1 MUFU op for 2 exps)
__device__ __forceinline__ uint32_t EX2H2(float a, float b) {
    uint32_t hin = h2u(__float22half2_rn(make_float2(a, b)));
    uint32_t r;
    asm("ex2.approx.f16x2 %0, %1;" : "=r"(r) : "r"(hin));
    return r;
}

// ---------------------------------------------------------------------------
// K1: head projections -> fp16 Q (log2e-scaled), fp16 K, fp32 V.
__global__ void k_proj(const float* __restrict__ value,
                       const float* __restrict__ key,
                       const float* __restrict__ query,
                       const float* __restrict__ Wq, const float* __restrict__ bq,
                       const float* __restrict__ Wk, const float* __restrict__ bk,
                       const float* __restrict__ Wv, const float* __restrict__ bv)
{
    __shared__ float sWq[256], sWk[256], sWv[256];
    __shared__ float sbq[16], sbk[16], sbv[16];
    int tid = threadIdx.x;
    if (tid < 256) { sWq[tid] = Wq[tid]; sWk[tid] = Wk[tid]; sWv[tid] = Wv[tid]; }
    if (tid < 16)  { sbq[tid] = bq[tid]; sbk[tid] = bk[tid]; sbv[tid] = bv[tid]; }
    __syncthreads();

    int id = blockIdx.x * blockDim.x + tid;
    int t  = id & (TT - 1);
    int p  = id >> 11;
    int n  = p >> 2;
    int h  = p & 3;
    int in_base  = (n * TT + t) * EE + h * DD;
    int out_base = (p * TT + t) * DD;

    float x[16];
    // ---- q (scaled by log2e/8) ----
    #pragma unroll
    for (int i = 0; i < 16; i++) x[i] = query[in_base + i];
    {
        float a[16];
        #pragma unroll
        for (int j = 0; j < 16; j++) {
            float acc = sbq[j];
            #pragma unroll
            for (int i = 0; i < 16; i++) acc = fmaf(x[i], sWq[i * 16 + j], acc);
            a[j] = acc * QSCALE2;
        }
        __half2* dh = reinterpret_cast<__half2*>(&g_Qh[out_base]);
        #pragma unroll
        for (int j = 0; j < 8; j++)
            dh[j] = __float22half2_rn(make_float2(a[2 * j], a[2 * j + 1]));
    }
    // ---- k ----
    #pragma unroll
    for (int i = 0; i < 16; i++) x[i] = key[in_base + i];
    {
        float a[16];
        #pragma unroll
        for (int j = 0; j < 16; j++) {
            float acc = sbk[j];
            #pragma unroll
            for (int i = 0; i < 16; i++) acc = fmaf(x[i], sWk[i * 16 + j], acc);
            a[j] = acc;
        }
        __half2* dh = reinterpret_cast<__half2*>(&g_Kh[out_base]);
        #pragma unroll
        for (int j = 0; j < 8; j++)
            dh[j] = __float22half2_rn(make_float2(a[2 * j], a[2 * j + 1]));
    }
    // ---- v (fp32) ----
    #pragma unroll
    for (int i = 0; i < 16; i++) x[i] = value[in_base + i];
    #pragma unroll
    for (int j = 0; j < 16; j++) {
        float acc = sbv[j];
        #pragma unroll
        for (int i = 0; i < 16; i++) acc = fmaf(x[i], sWv[i * 16 + j], acc);
        g_V[out_base + j] = acc;
    }
}

// ---------------------------------------------------------------------------
// K2 (pass A): Z[k] = sum_q exp2(qh.kh), then fold 1/Z into V in-place.
// S hi-only (1 MMA per n8 tile); exp via ex2.approx.f16x2 — the SAME fp16
// rounding + ex2 path k_out uses, so the softmax is exactly consistent.
// grid = (TT/128, NP), block = 128.
__global__ void __launch_bounds__(128) k_zsum()
{
    __shared__ __align__(16) __half sK[128 * 16];
    __shared__ __align__(16) __half sQ[3][128 * 16];
    __shared__ float sZ[128];

    int tid = threadIdx.x, lane = tid & 31, warp = tid >> 5;
    int p = blockIdx.y, kbase = blockIdx.x * 128;

    // stage this block's 128 K rows: 256 uint4, 2 per thread
    {
        const uint4* src = reinterpret_cast<const uint4*>(g_Kh + (p * TT + kbase) * DD);
        uint4* dst = reinterpret_cast<uint4*>(sK);
        dst[tid * 2] = src[tid * 2];
        dst[tid * 2 + 1] = src[tid * 2 + 1];
    }

    const __half* gq = g_Qh + p * TT * DD;
    // prologue: stage Q tiles 0, 1 (256 uint4 each, 2 per thread)
    #pragma unroll
    for (int qt0 = 0; qt0 < 2; qt0++) {
        uint32_t d = smem_u32(&sQ[qt0][0]);
        cp16(d + (tid * 2) * 16,     gq + qt0 * 128 * DD + (tid * 2) * 8);
        cp16(d + (tid * 2 + 1) * 16, gq + qt0 * 128 * DD + (tid * 2 + 1) * 8);
        CP_COMMIT();
    }

    __syncthreads();   // K tile visible

    // A frags: 2 sets of 16 K rows
    int g = lane >> 3;
    uint32_t akh[2][4];
    #pragma unroll
    for (int s = 0; s < 2; s++) {
        int row = warp * 32 + s * 16 + (g & 1) * 8 + (lane & 7);
        int col = (g >> 1) * 8;
        LDSM_X4(akh[s][0], akh[s][1], akh[s][2], akh[s][3], smem_u32(&sK[row * 16 + col]));
    }

    float z[2][2] = {{0.f, 0.f}, {0.f, 0.f}};
    int browq = (g >> 1) * 8 + (lane & 7);
    int bcol  = (g & 1) * 8;

    for (int qt = 0; qt < 16; qt++) {
        if (qt < 15) { CP_WAIT(1); } else { CP_WAIT(0); }
        __syncthreads();
        int buf = qt % 3;
        uint32_t qb = smem_u32(&sQ[buf][browq * 16 + bcol]);
        #pragma unroll
        for (int sub = 0; sub < 8; sub++) {
            uint32_t bh0, bh1, bh2, bh3;
            LDSM_X4(bh0, bh1, bh2, bh3, qb + sub * 512);
            #pragma unroll
            for (int s = 0; s < 2; s++) {
                #pragma unroll
                for (int nh = 0; nh < 2; nh++) {
                    float c0 = 0.f, c1 = 0.f, c2 = 0.f, c3 = 0.f;
                    if (nh == 0) {
                        MMA16816(c0, c1, c2, c3, akh[s][0], akh[s][1], akh[s][2], akh[s][3], bh0, bh1);
                    } else {
                        MMA16816(c0, c1, c2, c3, akh[s][0], akh[s][1], akh[s][2], akh[s][3], bh2, bh3);
                    }
                    uint32_t e01 = EX2H2(c0, c1);
                    uint32_t e23 = EX2H2(c2, c3);
                    float2 f01 = __half22float2(u2h(e01));
                    float2 f23 = __half22float2(u2h(e23));
                    z[s][0] += f01.x + f01.y;
                    z[s][1] += f23.x + f23.y;
                }
            }
        }
        // stage tile qt+2
        if (qt + 2 < 16) {
            uint32_t d = smem_u32(&sQ[(qt + 2) % 3][0]);
            cp16(d + (tid * 2) * 16,     gq + (qt + 2) * 128 * DD + (tid * 2) * 8);
            cp16(d + (tid * 2 + 1) * 16, gq + (qt + 2) * 128 * DD + (tid * 2 + 1) * 8);
            CP_COMMIT();
        }
    }

    // quad reduce across the 4 threads sharing each row -> sZ
    #pragma unroll
    for (int s = 0; s < 2; s++)
        #pragma unroll
        for (int j = 0; j < 2; j++) {
            z[s][j] += __shfl_xor_sync(0xffffffffu, z[s][j], 1);
            z[s][j] += __shfl_xor_sync(0xffffffffu, z[s][j], 2);
        }
    if ((lane & 3) == 0) {
        int r = lane >> 2;
        #pragma unroll
        for (int s = 0; s < 2; s++) {
            sZ[warp * 32 + s * 16 + r]     = z[s][0];
            sZ[warp * 32 + s * 16 + r + 8] = z[s][1];
        }
    }
    __syncthreads();

    // fused fold: thread owns one k row; W[k,:] = V[k,:]/Z[k] (fp16, hi only)
    {
        int id = p * TT + kbase + tid;
        float inv = 1.0f / sZ[tid];
        const float4* v4 = reinterpret_cast<const float4*>(&g_V[id * DD]);
        __half2* dh = reinterpret_cast<__half2*>(&g_Wh[id * DD]);
        #pragma unroll
        for (int i = 0; i < 4; i++) {
            float4 x = v4[i];
            dh[2 * i]     = __float22half2_rn(make_float2(x.x * inv, x.y * inv));
            dh[2 * i + 1] = __float22half2_rn(make_float2(x.z * inv, x.w * inv));
        }
    }
}

// ---------------------------------------------------------------------------
// K4 (pass B): out[q,:] = sum_k exp2(qh.kh) * W[k,:]  (W pre-folded, fp16).
// S hi-only; P via ex2.approx.f16x2 (bit-consistent with k_zsum); W hi-only
// (fp16 rounding random-walks out over 2048 terms, ~2.4e-4).  4 MMAs per
// 16x16 per set.  Warp owns 32 q rows; 64-k chunks, 3-deep cp.async.
// grid = (TT/128, NP), block = 128.
__global__ void __launch_bounds__(128) k_out()
{
    __shared__ __align__(16) __half sQh[128 * 16];
    __shared__ __align__(16) __half sB[3][2][64 * 16];   // [buf][Kh,Wh]

    int tid = threadIdx.x, lane = tid & 31, warp = tid >> 5;
    int p = blockIdx.y, qbase = blockIdx.x * 128;
    int n = p >> 2, h = p & 3;

    // stage this block's 128 Q rows: 256 uint4, 2 per thread
    {
        const uint4* src = reinterpret_cast<const uint4*>(g_Qh + (p * TT + qbase) * DD);
        uint4* dst = reinterpret_cast<uint4*>(sQh);
        dst[tid * 2] = src[tid * 2];
        dst[tid * 2 + 1] = src[tid * 2 + 1];
    }

    const __half* gk = g_Kh + p * TT * DD;
    const __half* gwh = g_Wh + p * TT * DD;
    uint32_t sb_base = smem_u32(&sB[0][0][0]);
    const uint32_t BUFB = 2 * 64 * 16 * 2;   // 4096 bytes per buffer

    // prologue: stage chunks 0, 1 (2 arrays x 128 slots; 2 cp16/thread)
    #pragma unroll
    for (int c0 = 0; c0 < 2; c0++) {
        uint32_t d = sb_base + c0 * BUFB;
        cp16(d + tid * 16,        gk  + c0 * 64 * DD + tid * 8);
        cp16(d + 2048 + tid * 16, gwh + c0 * 64 * DD + tid * 8);
        CP_COMMIT();
    }

    __syncthreads();   // Q tile visible

    // A frags: 2 sets of 16 Q rows
    int g = lane >> 3;
    uint32_t aqh[2][4];
    #pragma unroll
    for (int s = 0; s < 2; s++) {
        int row = warp * 32 + s * 16 + (g & 1) * 8 + (lane & 7);
        int col = (g >> 1) * 8;
        LDSM_X4(aqh[s][0], aqh[s][1], aqh[s][2], aqh[s][3], smem_u32(&sQh[row * 16 + col]));
    }

    float oc[2][2][4];   // [set][d-half][frag]
    #pragma unroll
    for (int s = 0; s < 2; s++)
        #pragma unroll
        for (int dh2 = 0; dh2 < 2; dh2++)
            #pragma unroll
            for (int j = 0; j < 4; j++) oc[s][dh2][j] = 0.f;

    uint32_t koff = ((g >> 1) * 8 + (lane & 7)) * 32 + (g & 1) * 16;
    uint32_t woff = 2048 + ((g & 1) * 8 + (lane & 7)) * 32 + (g >> 1) * 16;

    for (int kc = 0; kc < 32; kc++) {
        if (kc < 31) { CP_WAIT(1); } else { CP_WAIT(0); }
        __syncthreads();
        uint32_t bufb = sb_base + (kc % 3) * BUFB;
        uint32_t kaddr = bufb + koff;
        uint32_t waddr = bufb + woff;
        #pragma unroll
        for (int sub = 0; sub < 4; sub++) {
            uint32_t kh0, kh1, kh2, kh3;
            LDSM_X4(kh0, kh1, kh2, kh3, kaddr + sub * 512);
            uint32_t wh0, wh1, wh2, wh3;
            LDSM_X4T(wh0, wh1, wh2, wh3, waddr + sub * 512);

            #pragma unroll
            for (int s = 0; s < 2; s++) {
                uint32_t pah[4];
                {
                    float c0 = 0.f, c1 = 0.f, c2 = 0.f, c3 = 0.f;
                    MMA16816(c0, c1, c2, c3, aqh[s][0], aqh[s][1], aqh[s][2], aqh[s][3], kh0, kh1);
                    pah[0] = EX2H2(c0, c1);
                    pah[1] = EX2H2(c2, c3);
                }
                {
                    float c0 = 0.f, c1 = 0.f, c2 = 0.f, c3 = 0.f;
                    MMA16816(c0, c1, c2, c3, aqh[s][0], aqh[s][1], aqh[s][2], aqh[s][3], kh2, kh3);
                    pah[2] = EX2H2(c0, c1);
                    pah[3] = EX2H2(c2, c3);
                }

                MMA16816(oc[s][0][0], oc[s][0][1], oc[s][0][2], oc[s][0][3],
                         pah[0], pah[1], pah[2], pah[3], wh0, wh1);
                MMA16816(oc[s][1][0], oc[s][1][1], oc[s][1][2], oc[s][1][3],
                         pah[0], pah[1], pah[2], pah[3], wh2, wh3);
            }
        }
        // stage chunk kc+2
        if (kc + 2 < 32) {
            uint32_t d = sb_base + ((kc + 2) % 3) * BUFB;
            cp16(d + tid * 16,        gk  + (kc + 2) * 64 * DD + tid * 8);
            cp16(d + 2048 + tid * 16, gwh + (kc + 2) * 64 * DD + tid * 8);
            CP_COMMIT();
        }
    }

    // epilogue: write fp16 fragments to g_Oh (both sets)
    {
        int r = lane >> 2, c2 = lane & 3;
        #pragma unroll
        for (int s = 0; s < 2; s++) {
            int q0 = qbase + warp * 32 + s * 16 + r;
            int b0i = (n * TT + q0) * EE + h * DD;
            int b8i = (n * TT + q0 + 8) * EE + h * DD;
            *reinterpret_cast<__half2*>(&g_Oh[b0i + 2 * c2]) =
                __float22half2_rn(make_float2(oc[s][0][0], oc[s][0][1]));
            *reinterpret_cast<__half2*>(&g_Oh[b8i + 2 * c2]) =
                __float22half2_rn(make_float2(oc[s][0][2], oc[s][0][3]));
            *reinterpret_cast<__half2*>(&g_Oh[b0i + 8 + 2 * c2]) =
                __float22half2_rn(make_float2(oc[s][1][0], oc[s][1][1]));
            *reinterpret_cast<__half2*>(&g_Oh[b8i + 8 + 2 * c2]) =
                __float22half2_rn(make_float2(oc[s][1][2], oc[s][1][3]));
        }
    }
}

// ---------------------------------------------------------------------------
// K5a: split Wfc into fp16 hi/lo (one-time, tiny).
__global__ void k_wsplit(const float* __restrict__ Wfc)
{
    int i = blockIdx.x * blockDim.x + threadIdx.x;   // 0..4095
    float w = Wfc[i];
    __half hi = __float2half_rn(w);
    g_Wfh[i] = hi;
    g_Wfl[i] = __float2half_rn(w - __half2float(hi));
}

// ---------------------------------------------------------------------------
// K5b: final FC via HMMA: y = O @ Wfc + bfc.  X fp16 (hi only), Wfc hi/lo.
// grid = 256 blocks x 128 rows; block = 256 (8 warps, warp owns 16 rows).
__global__ void __launch_bounds__(256) k_fc_mma(const float* __restrict__ bfc,
                                               float* __restrict__ out)
{
    __shared__ __align__(16) __half sXh[128 * 64];
    __shared__ __align__(16) __half sWh[64 * 64],  sWl[64 * 64];
    __shared__ float sb[64];

    int tid = threadIdx.x, lane = tid & 31, warp = tid >> 5;
    int rowbase = blockIdx.x * 128;

    {
        const uint4* srch = reinterpret_cast<const uint4*>(g_Oh + rowbase * EE);
        uint4* dh = reinterpret_cast<uint4*>(sXh);
        #pragma unroll
        for (int j = 0; j < 4; j++)
            dh[tid + j * 256] = srch[tid + j * 256];
    }
    {
        const uint4* srch = reinterpret_cast<const uint4*>(g_Wfh);
        const uint4* srcl = reinterpret_cast<const uint4*>(g_Wfl);
        uint4* dh = reinterpret_cast<uint4*>(sWh);
        uint4* dl = reinterpret_cast<uint4*>(sWl);
        dh[tid] = srch[tid]; dh[tid + 256] = srch[tid + 256];
        dl[tid] = srcl[tid]; dl[tid + 256] = srcl[tid + 256];
    }
    if (tid < 64) sb[tid] = bfc[tid];
    __syncthreads();

    int g = lane >> 3;
    uint32_t axh[4][4];
    #pragma unroll
    for (int kt = 0; kt < 4; kt++) {
        int row = warp * 16 + (g & 1) * 8 + (lane & 7);
        int col = kt * 16 + (g >> 1) * 8;
        LDSM_X4(axh[kt][0], axh[kt][1], axh[kt][2], axh[kt][3], smem_u32(&sXh[row * 64 + col]));
    }

    float c[8][4];
    #pragma unroll
    for (int i = 0; i < 8; i++)
        #pragma unroll
        for (int j = 0; j < 4; j++) c[i][j] = 0.f;

    #pragma unroll
    for (int nt2 = 0; nt2 < 4; nt2++) {
        #pragma unroll
        for (int kt = 0; kt < 4; kt++) {
            int brow = kt * 16 + (g & 1) * 8 + (lane & 7);
            int bcol = nt2 * 16 + (g >> 1) * 8;
            uint32_t bh0, bh1, bh2, bh3, bl0, bl1, bl2, bl3;
            LDSM_X4T(bh0, bh1, bh2, bh3, smem_u32(&sWh[brow * 64 + bcol]));
            LDSM_X4T(bl0, bl1, bl2, bl3, smem_u32(&sWl[brow * 64 + bcol]));
            MMA16816(c[nt2*2][0], c[nt2*2][1], c[nt2*2][2], c[nt2*2][3],
                     axh[kt][0], axh[kt][1], axh[kt][2], axh[kt][3], bh0, bh1);
            MMA16816(c[nt2*2][0], c[nt2*2][1], c[nt2*2][2], c[nt2*2][3],
                     axh[kt][0], axh[kt][1], axh[kt][2], axh[kt][3], bl0, bl1);
            MMA16816(c[nt2*2+1][0], c[nt2*2+1][1], c[nt2*2+1][2], c[nt2*2+1][3],
                     axh[kt][0], axh[kt][1], axh[kt][2], axh[kt][3], bh2, bh3);
            MMA16816(c[nt2*2+1][0], c[nt2*2+1][1], c[nt2*2+1][2], c[nt2*2+1][3],
                     axh[kt][0], axh[kt][1], axh[kt][2], axh[kt][3], bl2, bl3);
        }
    }

    int r = lane >> 2, j = lane & 3;
    int row0 = rowbase + warp * 16 + r;
    #pragma unroll
    for (int nt = 0; nt < 8; nt++) {
        int ncol = nt * 8 + 2 * j;
        float b0 = sb[ncol], b1 = sb[ncol + 1];
        *reinterpret_cast<float2*>(&out[row0 * 64 + ncol]) =
            make_float2(c[nt][0] + b0, c[nt][1] + b1);
        *reinterpret_cast<float2*>(&out[(row0 + 8) * 64 + ncol]) =
            make_float2(c[nt][2] + b0, c[nt][3] + b1);
    }
}

// ---------------------------------------------------------------------------
// Input order: 0:value 1:key 2:query 3:Wq 4:bq 5:Wk 6:bk 7:Wv 8:bv 9:Wfc 10:bfc
extern "C" void kernel_launch(void* const* d_in, const int* in_sizes, int n_in,
                              void* d_out, int out_size)
{
    const float* value = (const float*)d_in[0];
    const float* key_  = (const float*)d_in[1];
    const float* query = (const float*)d_in[2];
    const float* Wq    = (const float*)d_in[3];
    const float* bq    = (const float*)d_in[4];
    const float* Wk    = (const float*)d_in[5];
    const float* bk    = (const float*)d_in[6];
    const float* Wv    = (const float*)d_in[7];
    const float* bv    = (const float*)d_in[8];
    const float* Wfc   = (const float*)d_in[9];
    const float* bfc   = (const float*)d_in[10];
    float* out = (float*)d_out;

    k_wsplit<<<16, 256>>>(Wfc);
    k_proj<<<(NP * TT) / 256, 256>>>(value, key_, query, Wq, bq, Wk, bk, Wv, bv);
    k_zsum<<<dim3(TT / 128, NP), 128>>>();
    k_out<<<dim3(TT / 128, NP), 128>>>();
    k_fc_mma<<<(NN * TT) / 128, 256>>>(bfc, out);
}